// round 11
// baseline (speedup 1.0000x reference)
#include <cuda_runtime.h>
#include <cuda_bf16.h>

#define LL 9
#define BB 4
#define CC 512
#define HW 1024

// ---------------- scratch (device globals; no allocation) ----------------
__device__ __align__(16) float g_invq[LL*BB*HW];
__device__ __align__(16) float g_invs[LL*BB*HW];
__device__ __align__(16) float g_corr[(size_t)BB*HW*HW];   // 16 MB, reused as attn
__device__ __align__(16) float g_c1[BB*256*HW];            // conv1 out [b][256][32*32]
__device__ __align__(16) float g_c1pa[BB*256*HW];          // conv1 K-split partials
__device__ __align__(16) float g_c1pb[BB*256*HW];
__device__ __align__(16) float g_attpa[BB*CC*HW];          // att K-split partials
__device__ __align__(16) float g_attpb[BB*CC*HW];
__device__ __align__(16) float g_c2pa[BB*256*900];         // conv2 K-split partials
__device__ __align__(16) float g_c2pb[BB*256*900];
__device__ __align__(16) float g_pool[BB*256*100];         // pooled [b][256][10*10]
__device__ __align__(16) __nv_bfloat16 g_wt1h[9*1024*256]; // w1 hi [tap][ic][oc]
__device__ __align__(16) __nv_bfloat16 g_wt1l[9*1024*256]; // w1 lo [tap][ic][oc]
__device__ __align__(16) __nv_bfloat16 g_wt2h[9*256*256];  // w2 hi [tap][ic][oc]
__device__ __align__(16) __nv_bfloat16 g_wt2l[9*256*256];  // w2 lo [tap][ic][oc]
__device__ __align__(16) float g_nq2[BB*HW];
__device__ __align__(16) float g_na2[BB*HW];

// ---------------- helpers ----------------
__device__ __forceinline__ void ldsm4t(unsigned* r, unsigned addr) {
    asm volatile("ldmatrix.sync.aligned.m8n8.x4.trans.shared.b16 {%0,%1,%2,%3}, [%4];\n"
        : "=r"(r[0]), "=r"(r[1]), "=r"(r[2]), "=r"(r[3]) : "r"(addr));
}
__device__ __forceinline__ void ldsm4(unsigned* r, unsigned addr) {
    asm volatile("ldmatrix.sync.aligned.m8n8.x4.shared.b16 {%0,%1,%2,%3}, [%4];\n"
        : "=r"(r[0]), "=r"(r[1]), "=r"(r[2]), "=r"(r[3]) : "r"(addr));
}
__device__ __forceinline__ void mma_bf16(float* c, const unsigned* a, const unsigned* b) {
    asm volatile(
        "mma.sync.aligned.m16n8k16.row.col.f32.bf16.bf16.f32 "
        "{%0,%1,%2,%3}, {%4,%5,%6,%7}, {%8,%9}, {%0,%1,%2,%3};\n"
        : "+f"(c[0]), "+f"(c[1]), "+f"(c[2]), "+f"(c[3])
        : "r"(a[0]), "r"(a[1]), "r"(a[2]), "r"(a[3]), "r"(b[0]), "r"(b[1]));
}
// split float4 -> hi bf16x2 pair + lo bf16x2 pair (packed as unsigned)
__device__ __forceinline__ void cvt_hl(float4 v, unsigned& h0, unsigned& h1,
                                       unsigned& l0, unsigned& l1) {
    __nv_bfloat162 H0 = __floats2bfloat162_rn(v.x, v.y);
    __nv_bfloat162 H1 = __floats2bfloat162_rn(v.z, v.w);
    __nv_bfloat162 L0 = __floats2bfloat162_rn(v.x - __bfloat162float(H0.x),
                                              v.y - __bfloat162float(H0.y));
    __nv_bfloat162 L1 = __floats2bfloat162_rn(v.z - __bfloat162float(H1.x),
                                              v.w - __bfloat162float(H1.y));
    h0 = *(unsigned*)&H0; h1 = *(unsigned*)&H1;
    l0 = *(unsigned*)&L0; l1 = *(unsigned*)&L1;
}

// ---------------- weight prep ----------------
__global__ void k_twt1(const float* __restrict__ w1) {
    int i = blockIdx.x * 256 + threadIdx.x;          // < 2359296
    float v = w1[i];
    int oc = i / 9216; int r = i % 9216; int ic = r / 9; int tap = r % 9;
    __nv_bfloat16 h = __float2bfloat16(v);
    __nv_bfloat16 lo = __float2bfloat16(v - __bfloat162float(h));
    int o = tap * 262144 + ic * 256 + oc;
    g_wt1h[o] = h; g_wt1l[o] = lo;
}
__global__ void k_twt2(const float* __restrict__ w2) {
    int i = blockIdx.x * 256 + threadIdx.x;          // < 589824
    float v = w2[i];
    int oc = i / 2304; int r = i % 2304; int ic = r / 9; int tap = r % 9;
    __nv_bfloat16 h = __float2bfloat16(v);
    __nv_bfloat16 lo = __float2bfloat16(v - __bfloat162float(h));
    int o = tap * 65536 + ic * 256 + oc;
    g_wt2h[o] = h; g_wt2l[o] = lo;
}

// ---------------- per-level per-pixel inverse channel norms ----------------
__global__ void k_norms(const float* __restrict__ fq, const float* __restrict__ fs) {
    int lb  = blockIdx.y;                             // 0..35 (l*B+b)
    int pix = blockIdx.x * 256 + threadIdx.x;         // 0..1023
    const float* src = (blockIdx.z == 0 ? fq : fs) + (size_t)lb * CC * HW + pix;
    float ss = 0.f;
#pragma unroll 8
    for (int c = 0; c < CC; c++) { float v = src[(size_t)c * HW]; ss = fmaf(v, v, ss); }
    float inv = 1.0f / fmaxf(sqrtf(ss), 1e-12f);
    (blockIdx.z == 0 ? g_invq : g_invs)[lb * HW + pix] = inv;
}

// ---------------- corr: bf16-split tensor-core, cross-level pipelined ----------------
__global__ void __launch_bounds__(256, 2) k_corr(const float* __restrict__ fq,
                                                 const float* __restrict__ fs) {
    __shared__ __align__(16) unsigned smq[2][4][16][68];  // 68 u32 = 136 halves
    int b  = blockIdx.z;
    int m0 = blockIdx.y * 128, n0 = blockIdx.x * 128;
    int tid = threadIdx.x, lane = tid & 31, wid = tid >> 5;
    int wm = (wid >> 2) * 64, wn = (wid & 3) * 32;
    int kr = tid >> 4, mc = (tid & 15) * 8;           // loader: 16 k-rows x 8 floats

    int kA = (lane & 7) + ((lane >> 4) << 3);
    int cA = ((lane >> 3) & 1) << 3;
    int kB = (lane & 7) + (((lane >> 3) & 1) << 3);
    int cB = (lane >> 4) << 3;
    unsigned smbase = (unsigned)__cvta_generic_to_shared(&smq[0][0][0][0]);
    unsigned offA = (unsigned)(kA * 272 + (cA + wm) * 2);
    unsigned offB = (unsigned)(kB * 272 + (cB + wn) * 2);

    float* outp = g_corr + (size_t)b * HW * HW + (size_t)m0 * HW + n0;

    float c[4][4][4];
#pragma unroll
    for (int f = 0; f < 4; f++)
#pragma unroll
        for (int g = 0; g < 4; g++) { c[f][g][0]=0.f; c[f][g][1]=0.f; c[f][g][2]=0.f; c[f][g][3]=0.f; }

    {   // global prologue: (l=0, kt=0) -> buf 0
        const float* Ag = fq + (size_t)b * CC * HW + m0;
        const float* Bg = fs + (size_t)b * CC * HW + n0;
        float4 a0g = *(const float4*)(Ag + (size_t)kr * HW + mc);
        float4 a1g = *(const float4*)(Ag + (size_t)kr * HW + mc + 4);
        float4 b0g = *(const float4*)(Bg + (size_t)kr * HW + mc);
        float4 b1g = *(const float4*)(Bg + (size_t)kr * HW + mc + 4);
        unsigned h0,h1,l0,l1;
        unsigned* pAh = &smq[0][0][kr][mc >> 1];
        unsigned* pAl = &smq[0][1][kr][mc >> 1];
        unsigned* pBh = &smq[0][2][kr][mc >> 1];
        unsigned* pBl = &smq[0][3][kr][mc >> 1];
        cvt_hl(a0g,h0,h1,l0,l1); pAh[0]=h0; pAh[1]=h1; pAl[0]=l0; pAl[1]=l1;
        cvt_hl(a1g,h0,h1,l0,l1); pAh[2]=h0; pAh[3]=h1; pAl[2]=l0; pAl[3]=l1;
        cvt_hl(b0g,h0,h1,l0,l1); pBh[0]=h0; pBh[1]=h1; pBl[0]=l0; pBl[1]=l1;
        cvt_hl(b1g,h0,h1,l0,l1); pBh[2]=h0; pBh[3]=h1; pBl[2]=l0; pBl[3]=l1;
    }
    __syncthreads();

    int buf = 0;
    for (int lkt = 0; lkt < 288; lkt++) {
        int l = lkt >> 5;
        // prefetch lkt+1
        float4 a0g, a1g, b0g, b1g;
        if (lkt < 287) {
            int nk = lkt + 1;
            int l2 = nk >> 5, k2 = (nk & 31) * 16;
            const float* Ag = fq + (size_t)(l2 * BB + b) * CC * HW + m0;
            const float* Bg = fs + (size_t)(l2 * BB + b) * CC * HW + n0;
            a0g = *(const float4*)(Ag + (size_t)(k2 + kr) * HW + mc);
            a1g = *(const float4*)(Ag + (size_t)(k2 + kr) * HW + mc + 4);
            b0g = *(const float4*)(Bg + (size_t)(k2 + kr) * HW + mc);
            b1g = *(const float4*)(Bg + (size_t)(k2 + kr) * HW + mc + 4);
        }
        unsigned base = smbase + (unsigned)buf * 17408u;
        unsigned a[16], bh[8], bl[8];
#pragma unroll
        for (int f = 0; f < 4; f++) ldsm4t(a + 4 * f, base + offA + f * 32);
#pragma unroll
        for (int g2 = 0; g2 < 2; g2++) ldsm4t(bh + 4 * g2, base + 2u * 4352u + offB + g2 * 32);
#pragma unroll
        for (int g2 = 0; g2 < 2; g2++) ldsm4t(bl + 4 * g2, base + 3u * 4352u + offB + g2 * 32);
#pragma unroll
        for (int f = 0; f < 4; f++)
#pragma unroll
            for (int g = 0; g < 4; g++) {
                mma_bf16(c[f][g], a + 4 * f, bh + 2 * g);
                mma_bf16(c[f][g], a + 4 * f, bl + 2 * g);
            }
#pragma unroll
        for (int f = 0; f < 4; f++) ldsm4t(a + 4 * f, base + 4352u + offA + f * 32);
#pragma unroll
        for (int f = 0; f < 4; f++)
#pragma unroll
            for (int g = 0; g < 4; g++)
                mma_bf16(c[f][g], a + 4 * f, bh + 2 * g);

        if (lkt < 287) {   // STS to other buffer (before epilogue; sync after)
            int nb = buf ^ 1;
            unsigned h0,h1,l0,l1;
            unsigned* pAh = &smq[nb][0][kr][mc >> 1];
            unsigned* pAl = &smq[nb][1][kr][mc >> 1];
            unsigned* pBh = &smq[nb][2][kr][mc >> 1];
            unsigned* pBl = &smq[nb][3][kr][mc >> 1];
            cvt_hl(a0g,h0,h1,l0,l1); pAh[0]=h0; pAh[1]=h1; pAl[0]=l0; pAl[1]=l1;
            cvt_hl(a1g,h0,h1,l0,l1); pAh[2]=h0; pAh[3]=h1; pAl[2]=l0; pAl[3]=l1;
            cvt_hl(b0g,h0,h1,l0,l1); pBh[0]=h0; pBh[1]=h1; pBl[0]=l0; pBl[1]=l1;
            cvt_hl(b1g,h0,h1,l0,l1); pBh[2]=h0; pBh[3]=h1; pBl[2]=l0; pBl[3]=l1;
        }

        if ((lkt & 31) == 31) {   // level epilogue: scale, relu, L2-resident RMW; reset c
            const float* iq = g_invq + (l * BB + b) * HW + m0;
            const float* is = g_invs + (l * BB + b) * HW + n0;
#pragma unroll
            for (int f = 0; f < 4; f++) {
                int r0 = wm + f * 16 + (lane >> 2), r1 = r0 + 8;
                float q0 = iq[r0], q1 = iq[r1];
#pragma unroll
                for (int g = 0; g < 4; g++) {
                    int cb = wn + g * 8 + (lane & 3) * 2;
                    float s0 = is[cb], s1 = is[cb + 1];
                    float v00 = fmaxf(c[f][g][0] * q0 * s0, 0.f);
                    float v01 = fmaxf(c[f][g][1] * q0 * s1, 0.f);
                    float v10 = fmaxf(c[f][g][2] * q1 * s0, 0.f);
                    float v11 = fmaxf(c[f][g][3] * q1 * s1, 0.f);
                    float2* p0 = (float2*)(outp + (size_t)r0 * HW + cb);
                    float2* p1 = (float2*)(outp + (size_t)r1 * HW + cb);
                    if (l == 0) {
                        *p0 = make_float2(v00, v01);
                        *p1 = make_float2(v10, v11);
                    } else {
                        float2 o0 = *p0, o1 = *p1;
                        o0.x += v00; o0.y += v01; o1.x += v10; o1.y += v11;
                        *p0 = o0; *p1 = o1;
                    }
                    c[f][g][0]=0.f; c[f][g][1]=0.f; c[f][g][2]=0.f; c[f][g][3]=0.f;
                }
            }
        }

        if (lkt < 287) {
            __syncthreads();
            buf ^= 1;
        }
    }
}

// ---------------- row softmax (scale = TEMP/L folds the mean) ----------------
__global__ void k_softmax() {
    float* r = g_corr + (size_t)blockIdx.x * HW;      // blockIdx.x = b*1024 + q
    int tid = threadIdx.x, wid = tid >> 5, lane = tid & 31;
    const float sc = 20.0f / 9.0f;
    float4 v = ((const float4*)r)[tid];
    v.x *= sc; v.y *= sc; v.z *= sc; v.w *= sc;
    float mx = fmaxf(fmaxf(v.x, v.y), fmaxf(v.z, v.w));
#pragma unroll
    for (int o = 16; o; o >>= 1) mx = fmaxf(mx, __shfl_xor_sync(0xffffffffu, mx, o));
    __shared__ float sh[8];
    if (lane == 0) sh[wid] = mx;
    __syncthreads();
    float m = sh[0];
#pragma unroll
    for (int k = 1; k < 8; k++) m = fmaxf(m, sh[k]);
    v.x = __expf(v.x - m); v.y = __expf(v.y - m);
    v.z = __expf(v.z - m); v.w = __expf(v.w - m);
    float s = v.x + v.y + v.z + v.w;
#pragma unroll
    for (int o = 16; o; o >>= 1) s += __shfl_xor_sync(0xffffffffu, s, o);
    __syncthreads();
    if (lane == 0) sh[wid] = s;
    __syncthreads();
    float tot = 0.f;
#pragma unroll
    for (int k = 0; k < 8; k++) tot += sh[k];
    float inv = 1.0f / tot;
    v.x *= inv; v.y *= inv; v.z *= inv; v.w *= inv;
    ((float4*)r)[tid] = v;
}

// ---------------- k_att: bf16-split MMA, K-split by 2 (half = z&1) ----------------
__global__ void __launch_bounds__(256, 2) k_att(const float* __restrict__ fs_in) {
    __shared__ __align__(16) uint4 smA[2][2][2][128];   // [buf][hl][kb][row]
    __shared__ __align__(16) uint4 smB[2][2][2][128];
    int b = blockIdx.z >> 1, half = blockIdx.z & 1;
    int m0 = blockIdx.y * 128, n0 = blockIdx.x * 128;
    int tid = threadIdx.x, lane = tid & 31, wid = tid >> 5;
    int wm = (wid >> 2) * 64, wn = (wid & 3) * 32;
    int lrow = tid >> 1, lkb = tid & 1;

    const float* Ag = fs_in + (size_t)b * CC * HW + (size_t)m0 * HW + half * 512;
    const float* Bg = g_corr + (size_t)b * HW * HW + (size_t)n0 * HW + half * 512;

    int rsel = ((lane >> 3) & 1) * 8 + (lane & 7);
    int kbsel = lane >> 4;
    unsigned baseA = (unsigned)__cvta_generic_to_shared(&smA[0][0][0][0]);
    unsigned baseB = (unsigned)__cvta_generic_to_shared(&smB[0][0][0][0]);
    unsigned offA = (unsigned)(kbsel * 2048 + (wm + rsel) * 16);     // + f*256
    unsigned offB = (unsigned)(kbsel * 2048 + (wn + rsel) * 16);     // + gg*256

    float c[4][4][4];
#pragma unroll
    for (int f = 0; f < 4; f++)
#pragma unroll
        for (int g = 0; g < 4; g++) { c[f][g][0]=0.f; c[f][g][1]=0.f; c[f][g][2]=0.f; c[f][g][3]=0.f; }

    {   // prologue: k-tile 0
        float4 a0g = *(const float4*)(Ag + (size_t)lrow * HW + lkb * 8);
        float4 a1g = *(const float4*)(Ag + (size_t)lrow * HW + lkb * 8 + 4);
        float4 b0g = *(const float4*)(Bg + (size_t)lrow * HW + lkb * 8);
        float4 b1g = *(const float4*)(Bg + (size_t)lrow * HW + lkb * 8 + 4);
        unsigned h0,h1,l0,l1,h2,h3,l2,l3;
        cvt_hl(a0g,h0,h1,l0,l1); cvt_hl(a1g,h2,h3,l2,l3);
        smA[0][0][lkb][lrow] = make_uint4(h0,h1,h2,h3);
        smA[0][1][lkb][lrow] = make_uint4(l0,l1,l2,l3);
        cvt_hl(b0g,h0,h1,l0,l1); cvt_hl(b1g,h2,h3,l2,l3);
        smB[0][0][lkb][lrow] = make_uint4(h0,h1,h2,h3);
        smB[0][1][lkb][lrow] = make_uint4(l0,l1,l2,l3);
    }
    __syncthreads();

    int buf = 0;
    for (int kt = 0; kt < 32; kt++) {
        float4 a0g, a1g, b0g, b1g;
        if (kt < 31) {
            int k0 = (kt + 1) * 16 + lkb * 8;
            a0g = *(const float4*)(Ag + (size_t)lrow * HW + k0);
            a1g = *(const float4*)(Ag + (size_t)lrow * HW + k0 + 4);
            b0g = *(const float4*)(Bg + (size_t)lrow * HW + k0);
            b1g = *(const float4*)(Bg + (size_t)lrow * HW + k0 + 4);
        }
        unsigned bA = baseA + (unsigned)buf * 8192u;
        unsigned bB = baseB + (unsigned)buf * 8192u;
        unsigned a[16], bh[8], bl[8], t[4];
#pragma unroll
        for (int f = 0; f < 4; f++) ldsm4(a + 4 * f, bA + offA + f * 256);
#pragma unroll
        for (int gg = 0; gg < 2; gg++) {
            ldsm4(t, bB + offB + gg * 256);
            bh[gg*4+0]=t[0]; bh[gg*4+1]=t[2]; bh[gg*4+2]=t[1]; bh[gg*4+3]=t[3];
        }
#pragma unroll
        for (int gg = 0; gg < 2; gg++) {
            ldsm4(t, bB + 4096u + offB + gg * 256);
            bl[gg*4+0]=t[0]; bl[gg*4+1]=t[2]; bl[gg*4+2]=t[1]; bl[gg*4+3]=t[3];
        }
#pragma unroll
        for (int f = 0; f < 4; f++)
#pragma unroll
            for (int g = 0; g < 4; g++) {
                mma_bf16(c[f][g], a + 4 * f, bh + 2 * g);
                mma_bf16(c[f][g], a + 4 * f, bl + 2 * g);
            }
#pragma unroll
        for (int f = 0; f < 4; f++) ldsm4(a + 4 * f, bA + 4096u + offA + f * 256);
#pragma unroll
        for (int f = 0; f < 4; f++)
#pragma unroll
            for (int g = 0; g < 4; g++)
                mma_bf16(c[f][g], a + 4 * f, bh + 2 * g);

        if (kt < 31) {
            int nb = buf ^ 1;
            unsigned h0,h1,l0,l1,h2,h3,l2,l3;
            cvt_hl(a0g,h0,h1,l0,l1); cvt_hl(a1g,h2,h3,l2,l3);
            smA[nb][0][lkb][lrow] = make_uint4(h0,h1,h2,h3);
            smA[nb][1][lkb][lrow] = make_uint4(l0,l1,l2,l3);
            cvt_hl(b0g,h0,h1,l0,l1); cvt_hl(b1g,h2,h3,l2,l3);
            smB[nb][0][lkb][lrow] = make_uint4(h0,h1,h2,h3);
            smB[nb][1][lkb][lrow] = make_uint4(l0,l1,l2,l3);
            __syncthreads();
            buf = nb;
        }
    }

    float* outp = (half ? g_attpb : g_attpa) + (size_t)b * CC * HW + (size_t)m0 * HW + n0;
#pragma unroll
    for (int f = 0; f < 4; f++) {
        int r0 = wm + f * 16 + (lane >> 2), r1 = r0 + 8;
#pragma unroll
        for (int g = 0; g < 4; g++) {
            int cb = wn + g * 8 + (lane & 3) * 2;
            *(float2*)(outp + (size_t)r0 * HW + cb) = make_float2(c[f][g][0], c[f][g][1]);
            *(float2*)(outp + (size_t)r1 * HW + cb) = make_float2(c[f][g][2], c[f][g][3]);
        }
    }
}

// ---------------- norms of f_q / att (att branch also combines partials) ----------------
__global__ void k_norm2(const float* __restrict__ f_q, float* __restrict__ att) {
    int b   = blockIdx.y;
    int pix = blockIdx.x * 256 + threadIdx.x;
    size_t base = (size_t)b * CC * HW + pix;
    float ss = 0.f;
    if (blockIdx.z == 0) {
        const float* src = f_q + base;
#pragma unroll 8
        for (int c = 0; c < CC; c++) { float v = src[(size_t)c * HW]; ss = fmaf(v, v, ss); }
    } else {
        const float* pa = g_attpa + base;
        const float* pb = g_attpb + base;
        float* ao = att + base;
#pragma unroll 4
        for (int c = 0; c < CC; c++) {
            float v = pa[(size_t)c * HW] + pb[(size_t)c * HW];
            ao[(size_t)c * HW] = v;
            ss = fmaf(v, v, ss);
        }
    }
    float inv = 1.0f / fmaxf(sqrtf(ss), 1e-12f);
    (blockIdx.z == 0 ? g_nq2 : g_na2)[b * HW + pix] = inv;
}

// ---------------- fq = l2n(f_q) + 0.5*l2n(att_fq) ----------------
__global__ void k_fqout(const float* __restrict__ f_q, const float* __restrict__ att,
                        float* __restrict__ fqo) {
    int i4 = blockIdx.x * 256 + threadIdx.x;          // < 524288
    int base = i4 * 4;
    int b = base >> 19;
    int pix = base & 1023;
    float4 q = ((const float4*)f_q)[i4];
    float4 a = ((const float4*)att)[i4];
    int ni = (b * HW + pix) >> 2;
    float4 nq = ((const float4*)g_nq2)[ni];
    float4 na = ((const float4*)g_na2)[ni];
    float4 o;
    o.x = q.x * nq.x + a.x * na.x * 0.5f;
    o.y = q.y * nq.y + a.y * na.y * 0.5f;
    o.z = q.z * nq.z + a.z * na.z * 0.5f;
    o.w = q.w * nq.w + a.w * na.w * 0.5f;
    ((float4*)fqo)[i4] = o;
}

// ---------------- conv1: bf16-split tensor implicit GEMM, K-split by 2 ----------------
__global__ void __launch_bounds__(256, 2) k_conv1(const float* __restrict__ f_q,
                                                  const float* __restrict__ f_s) {
    __shared__ __align__(16) unsigned smW[2][2][16][36];  // [buf][hi/lo][k][oc72h]
    __shared__ __align__(16) unsigned smI[2][2][16][68];  // [buf][hi/lo][k][pix136h]
    int b = blockIdx.z >> 1, half = blockIdx.z & 1;
    int oc0 = blockIdx.y * 64, pix0 = blockIdx.x * 128;
    int tid = threadIdx.x, lane = tid & 31, wid = tid >> 5;
    int wm = (wid >> 2) * 32, wn = (wid & 3) * 32;
    int kr = tid >> 4, mc = (tid & 15) * 8;

    int kA = (lane & 7) + ((lane >> 4) << 3);
    int cA = ((lane >> 3) & 1) << 3;
    int kB = (lane & 7) + (((lane >> 3) & 1) << 3);
    int cB = (lane >> 4) << 3;
    unsigned baseW = (unsigned)__cvta_generic_to_shared(&smW[0][0][0][0]);
    unsigned baseI = (unsigned)__cvta_generic_to_shared(&smI[0][0][0][0]);
    unsigned offA = (unsigned)(kA * 144 + (cA + wm) * 2);
    unsigned offB = (unsigned)(kB * 272 + (cB + wn) * 2);

    const float* fqp = f_q + (size_t)b * CC * HW;
    const float* fsp = f_s + (size_t)b * CC * HW;

    int pp0 = pix0 + mc;
    int py = pp0 >> 5, px0v = pp0 & 31;
    int wtt = (tid & 127);
    int wrow = wtt >> 3, wcol8 = (wtt & 7) * 8;
    bool whalf = (tid < 128);
    int kbase = half * 288;                           // global k-tile base

    float c[2][4][4];
#pragma unroll
    for (int f = 0; f < 2; f++)
#pragma unroll
        for (int g = 0; g < 4; g++) { c[f][g][0]=0.f; c[f][g][1]=0.f; c[f][g][2]=0.f; c[f][g][3]=0.f; }

    {   // prologue: global k-tile kbase
        int tap = kbase >> 6, ict = kbase & 63;
        int dy = 2 * (tap / 3) - 2, dx = 2 * (tap % 3) - 2;
        uint4 wv;
        const __nv_bfloat16* wsrc = whalf ? g_wt1h : g_wt1l;
        wv = *(const uint4*)(wsrc + (size_t)(tap * 1024 + ict * 16 + wrow) * 256 + oc0 + wcol8);
        float v[8];
        int ic = ict * 16 + kr;
        const float* src = (ic < 512 ? fqp + (size_t)ic * HW
                                     : fsp + (size_t)(ic - 512) * HW);
        int iy = py + dy;
        bool yok = ((unsigned)iy < 32u);
        const float* rowp = src + iy * 32;
#pragma unroll
        for (int j = 0; j < 8; j++) {
            int ix = px0v + j + dx;
            v[j] = (yok && ((unsigned)ix < 32u)) ? rowp[ix] : 0.f;
        }
        *(uint4*)&smW[0][whalf ? 0 : 1][wrow][wcol8 >> 1] = wv;
        unsigned h0,h1,l0,l1;
        unsigned* pIh = &smI[0][0][kr][mc >> 1];
        unsigned* pIl = &smI[0][1][kr][mc >> 1];
        float4 fa = make_float4(v[0], v[1], v[2], v[3]);
        float4 fb = make_float4(v[4], v[5], v[6], v[7]);
        cvt_hl(fa,h0,h1,l0,l1); pIh[0]=h0; pIh[1]=h1; pIl[0]=l0; pIl[1]=l1;
        cvt_hl(fb,h0,h1,l0,l1); pIh[2]=h0; pIh[3]=h1; pIl[2]=l0; pIl[3]=l1;
    }
    __syncthreads();

    int buf = 0;
    for (int kt = 0; kt < 288; kt++) {
        uint4 wv; float v[8];
        if (kt < 287) {
            int kn = kbase + kt + 1;
            int tap = kn >> 6, ict = kn & 63;
            int dy = 2 * (tap / 3) - 2, dx = 2 * (tap % 3) - 2;
            const __nv_bfloat16* wsrc = whalf ? g_wt1h : g_wt1l;
            wv = *(const uint4*)(wsrc + (size_t)(tap * 1024 + ict * 16 + wrow) * 256 + oc0 + wcol8);
            int ic = ict * 16 + kr;
            const float* src = (ic < 512 ? fqp + (size_t)ic * HW
                                         : fsp + (size_t)(ic - 512) * HW);
            int iy = py + dy;
            bool yok = ((unsigned)iy < 32u);
            const float* rowp = src + iy * 32;
#pragma unroll
            for (int j = 0; j < 8; j++) {
                int ix = px0v + j + dx;
                v[j] = (yok && ((unsigned)ix < 32u)) ? rowp[ix] : 0.f;
            }
        }
        unsigned bW = baseW + (unsigned)buf * 4608u;
        unsigned bI = baseI + (unsigned)buf * 8704u;
        unsigned a[8], al[8], bh[8], bl[8];
#pragma unroll
        for (int f = 0; f < 2; f++) ldsm4t(a  + 4 * f, bW + offA + f * 32);
#pragma unroll
        for (int f = 0; f < 2; f++) ldsm4t(al + 4 * f, bW + 2304u + offA + f * 32);
#pragma unroll
        for (int g2 = 0; g2 < 2; g2++) ldsm4t(bh + 4 * g2, bI + offB + g2 * 32);
#pragma unroll
        for (int g2 = 0; g2 < 2; g2++) ldsm4t(bl + 4 * g2, bI + 4352u + offB + g2 * 32);
#pragma unroll
        for (int f = 0; f < 2; f++)
#pragma unroll
            for (int g = 0; g < 4; g++) {
                mma_bf16(c[f][g], a  + 4 * f, bh + 2 * g);
                mma_bf16(c[f][g], a  + 4 * f, bl + 2 * g);
                mma_bf16(c[f][g], al + 4 * f, bh + 2 * g);
            }
        if (kt < 287) {
            int nb = buf ^ 1;
            *(uint4*)&smW[nb][whalf ? 0 : 1][wrow][wcol8 >> 1] = wv;
            unsigned h0,h1,l0,l1;
            unsigned* pIh = &smI[nb][0][kr][mc >> 1];
            unsigned* pIl = &smI[nb][1][kr][mc >> 1];
            float4 fa = make_float4(v[0], v[1], v[2], v[3]);
            float4 fb = make_float4(v[4], v[5], v[6], v[7]);
            cvt_hl(fa,h0,h1,l0,l1); pIh[0]=h0; pIh[1]=h1; pIl[0]=l0; pIl[1]=l1;
            cvt_hl(fb,h0,h1,l0,l1); pIh[2]=h0; pIh[3]=h1; pIl[2]=l0; pIl[3]=l1;
            __syncthreads();
            buf = nb;
        }
    }

    float* outp = (half ? g_c1pb : g_c1pa) + (size_t)b * 262144;
#pragma unroll
    for (int f = 0; f < 2; f++) {
        int r0 = wm + f * 16 + (lane >> 2), r1 = r0 + 8;
#pragma unroll
        for (int g = 0; g < 4; g++) {
            int cb = wn + g * 8 + (lane & 3) * 2;
            *(float2*)(outp + (size_t)(oc0 + r0) * HW + pix0 + cb) =
                make_float2(c[f][g][0], c[f][g][1]);
            *(float2*)(outp + (size_t)(oc0 + r1) * HW + pix0 + cb) =
                make_float2(c[f][g][2], c[f][g][3]);
        }
    }
}

// c1 = relu(pa + pb + bias)
__global__ void k_c1comb(const float* __restrict__ b1) {
    int i4 = blockIdx.x * 256 + threadIdx.x;          // < 262144
    float4 a = ((const float4*)g_c1pa)[i4];
    float4 bb = ((const float4*)g_c1pb)[i4];
    int oc = (i4 & 65535) >> 8;                       // per-b block: 65536 f4, 256 f4 per oc
    float bias = b1[oc];
    float4 o;
    o.x = fmaxf(a.x + bb.x + bias, 0.f);
    o.y = fmaxf(a.y + bb.y + bias, 0.f);
    o.z = fmaxf(a.z + bb.z + bias, 0.f);
    o.w = fmaxf(a.w + bb.w + bias, 0.f);
    ((float4*)g_c1)[i4] = o;
}

// ---------------- conv2: bf16-split tensor implicit GEMM, K-split by 2 ----------------
__global__ void __launch_bounds__(256, 2) k_conv2() {
    __shared__ __align__(16) unsigned smW[2][2][16][36];
    __shared__ __align__(16) unsigned smI[2][2][16][68];
    int b = blockIdx.z >> 1, half = blockIdx.z & 1;
    int oc0 = blockIdx.y * 64, pix0 = blockIdx.x * 128;
    int tid = threadIdx.x, lane = tid & 31, wid = tid >> 5;
    int wm = (wid >> 2) * 32, wn = (wid & 3) * 32;
    int kr = tid >> 4, mc = (tid & 15) * 8;

    int kA = (lane & 7) + ((lane >> 4) << 3);
    int cA = ((lane >> 3) & 1) << 3;
    int kB = (lane & 7) + (((lane >> 3) & 1) << 3);
    int cB = (lane >> 4) << 3;
    unsigned baseW = (unsigned)__cvta_generic_to_shared(&smW[0][0][0][0]);
    unsigned baseI = (unsigned)__cvta_generic_to_shared(&smI[0][0][0][0]);
    unsigned offA = (unsigned)(kA * 144 + (cA + wm) * 2);
    unsigned offB = (unsigned)(kB * 272 + (cB + wn) * 2);

    const float* c1p = g_c1 + (size_t)b * 262144;

    int offp[8];
#pragma unroll
    for (int j = 0; j < 8; j++) {
        int p = pix0 + mc + j; if (p > 899) p = 899;
        offp[j] = (p / 30) * 32 + (p % 30);
    }
    int wtt = (tid & 127);
    int wrow = wtt >> 3, wcol8 = (wtt & 7) * 8;
    bool whalf = (tid < 128);
    int kbase = half * 72;                            // 144 k-tiles total

    float c[2][4][4];
#pragma unroll
    for (int f = 0; f < 2; f++)
#pragma unroll
        for (int g = 0; g < 4; g++) { c[f][g][0]=0.f; c[f][g][1]=0.f; c[f][g][2]=0.f; c[f][g][3]=0.f; }

    {   // prologue: k-tile kbase
        int tap = kbase >> 4, ict = kbase & 15;
        int doff = (tap / 3) * 32 + (tap % 3);
        uint4 wv;
        const __nv_bfloat16* wsrc = whalf ? g_wt2h : g_wt2l;
        wv = *(const uint4*)(wsrc + (size_t)(tap * 256 + ict * 16 + wrow) * 256 + oc0 + wcol8);
        float v[8];
        const float* src = c1p + (size_t)(ict * 16 + kr) * HW;
#pragma unroll
        for (int j = 0; j < 8; j++) v[j] = src[offp[j] + doff];
        *(uint4*)&smW[0][whalf ? 0 : 1][wrow][wcol8 >> 1] = wv;
        unsigned h0,h1,l0,l1;
        unsigned* pIh = &smI[0][0][kr][mc >> 1];
        unsigned* pIl = &smI[0][1][kr][mc >> 1];
        float4 fa = make_float4(v[0], v[1], v[2], v[3]);
        float4 fb = make_float4(v[4], v[5], v[6], v[7]);
        cvt_hl(fa,h0,h1,l0,l1); pIh[0]=h0; pIh[1]=h1; pIl[0]=l0; pIl[1]=l1;
        cvt_hl(fb,h0,h1,l0,l1); pIh[2]=h0; pIh[3]=h1; pIl[2]=l0; pIl[3]=l1;
    }
    __syncthreads();

    int buf = 0;
    for (int kt = 0; kt < 72; kt++) {
        uint4 wv; float v[8];
        if (kt < 71) {
            int kn = kbase + kt + 1;
            int tap = kn >> 4, ict = kn & 15;
            int doff = (tap / 3) * 32 + (tap % 3);
            const __nv_bfloat16* wsrc = whalf ? g_wt2h : g_wt2l;
            wv = *(const uint4*)(wsrc + (size_t)(tap * 256 + ict * 16 + wrow) * 256 + oc0 + wcol8);
            const float* src = c1p + (size_t)(ict * 16 + kr) * HW;
#pragma unroll
            for (int j = 0; j < 8; j++) v[j] = src[offp[j] + doff];
        }
        unsigned bW = baseW + (unsigned)buf * 4608u;
        unsigned bI = baseI + (unsigned)buf * 8704u;
        unsigned a[8], al[8], bh[8], bl[8];
#pragma unroll
        for (int f = 0; f < 2; f++) ldsm4t(a  + 4 * f, bW + offA + f * 32);
#pragma unroll
        for (int f = 0; f < 2; f++) ldsm4t(al + 4 * f, bW + 2304u + offA + f * 32);
#pragma unroll
        for (int g2 = 0; g2 < 2; g2++) ldsm4t(bh + 4 * g2, bI + offB + g2 * 32);
#pragma unroll
        for (int g2 = 0; g2 < 2; g2++) ldsm4t(bl + 4 * g2, bI + 4352u + offB + g2 * 32);
#pragma unroll
        for (int f = 0; f < 2; f++)
#pragma unroll
            for (int g = 0; g < 4; g++) {
                mma_bf16(c[f][g], a  + 4 * f, bh + 2 * g);
                mma_bf16(c[f][g], a  + 4 * f, bl + 2 * g);
                mma_bf16(c[f][g], al + 4 * f, bh + 2 * g);
            }
        if (kt < 71) {
            int nb = buf ^ 1;
            *(uint4*)&smW[nb][whalf ? 0 : 1][wrow][wcol8 >> 1] = wv;
            unsigned h0,h1,l0,l1;
            unsigned* pIh = &smI[nb][0][kr][mc >> 1];
            unsigned* pIl = &smI[nb][1][kr][mc >> 1];
            float4 fa = make_float4(v[0], v[1], v[2], v[3]);
            float4 fb = make_float4(v[4], v[5], v[6], v[7]);
            cvt_hl(fa,h0,h1,l0,l1); pIh[0]=h0; pIh[1]=h1; pIl[0]=l0; pIl[1]=l1;
            cvt_hl(fb,h0,h1,l0,l1); pIh[2]=h0; pIh[3]=h1; pIl[2]=l0; pIl[3]=l1;
            __syncthreads();
            buf = nb;
        }
    }

    float* outp = (half ? g_c2pb : g_c2pa) + (size_t)b * 230400;
#pragma unroll
    for (int f = 0; f < 2; f++) {
        int r0 = wm + f * 16 + (lane >> 2), r1 = r0 + 8;
#pragma unroll
        for (int g = 0; g < 4; g++) {
            int cb = wn + g * 8 + (lane & 3) * 2;
            int p0 = pix0 + cb;                // even; p0<900 => p0+1<=899
            if (p0 < 900) {
                *(float2*)(outp + (size_t)(oc0 + r0) * 900 + p0) =
                    make_float2(c[f][g][0], c[f][g][1]);
                *(float2*)(outp + (size_t)(oc0 + r1) * 900 + p0) =
                    make_float2(c[f][g][2], c[f][g][3]);
            }
        }
    }
}

// ---------------- maxpool 3x3 s3 (combines conv2 partials + bias) ----------------
__global__ void k_pool(const float* __restrict__ b2) {
    int oc = blockIdx.x, b = blockIdx.y;
    int t = threadIdx.x;
    if (t >= 100) return;
    int y = t / 10, x = t % 10;
    size_t base = ((size_t)b * 256 + oc) * 900;
    const float* pa = g_c2pa + base;
    const float* pb = g_c2pb + base;
    float m = -3.4e38f;
#pragma unroll
    for (int dy = 0; dy < 3; dy++)
#pragma unroll
        for (int dx = 0; dx < 3; dx++) {
            int idx = (3 * y + dy) * 30 + 3 * x + dx;
            m = fmaxf(m, pa[idx] + pb[idx]);
        }
    g_pool[((size_t)b * 256 + oc) * 100 + t] = m + b2[oc];
}

// ---------------- conv3 (3x3 VALID, 10x10 -> 8x8) + mean -> weight[b] ----------------
__global__ void k_conv3(const float* __restrict__ w3, const float* __restrict__ b3,
                        float* __restrict__ wout) {
    int b = blockIdx.x;
    int tid = threadIdx.x;
    int o = tid >> 2, part = tid & 3;
    int oy = o >> 3, ox = o & 7;
    float s = 0.f;
    for (int ic = part * 64; ic < part * 64 + 64; ic++) {
        const float* pp = g_pool + ((size_t)b * 256 + ic) * 100 + oy * 10 + ox;
        const float* wp = w3 + ic * 9;
#pragma unroll
        for (int ky = 0; ky < 3; ky++)
#pragma unroll
            for (int kx = 0; kx < 3; kx++)
                s = fmaf(pp[ky * 10 + kx], wp[ky * 3 + kx], s);
    }
    s += __shfl_down_sync(0xffffffffu, s, 1);
    s += __shfl_down_sync(0xffffffffu, s, 2);
    __shared__ float sh[64];
    if (part == 0) sh[o] = s;
    __syncthreads();
    if (tid < 32) {
        float v = sh[tid] + sh[tid + 32];
#pragma unroll
        for (int off = 16; off; off >>= 1) v += __shfl_xor_sync(0xffffffffu, v, off);
        if (tid == 0) wout[b] = v * (1.0f / 64.0f) + b3[0];
    }
}

// ---------------- launch ----------------
extern "C" void kernel_launch(void* const* d_in, const int* in_sizes, int n_in,
                              void* d_out, int out_size) {
    const float* fq_feats = (const float*)d_in[0];
    const float* fs_feats = (const float*)d_in[1];
    const float* f_q = (const float*)d_in[2];
    const float* f_s = (const float*)d_in[3];
    const float* w1 = (const float*)d_in[4];
    const float* b1 = (const float*)d_in[5];
    const float* w2 = (const float*)d_in[6];
    const float* b2 = (const float*)d_in[7];
    const float* w3 = (const float*)d_in[8];
    const float* b3 = (const float*)d_in[9];

    float* out     = (float*)d_out;
    float* fq_out  = out;                       // [4,512,32,32]
    float* att_out = out + 2097152;             // [4,512,32,32]
    float* w_out   = out + 4194304;             // [1,4]

    k_twt1<<<9216, 256>>>(w1);
    k_twt2<<<2304, 256>>>(w2);
    k_norms<<<dim3(4, 36, 2), 256>>>(fq_feats, fs_feats);
    k_corr<<<dim3(8, 8, 4), 256>>>(fq_feats, fs_feats);
    k_softmax<<<4096, 256>>>();
    k_att<<<dim3(8, 4, 8), 256>>>(f_s);
    k_norm2<<<dim3(4, 4, 2), 256>>>(f_q, att_out);
    k_fqout<<<2048, 256>>>(f_q, att_out, fq_out);
    k_conv1<<<dim3(8, 4, 8), 256>>>(f_q, f_s);
    k_c1comb<<<1024, 256>>>(b1);
    k_conv2<<<dim3(8, 4, 8), 256>>>();
    k_pool<<<dim3(256, 4), 128>>>(b2);
    k_conv3<<<4, 256>>>(w3, b3, w_out);
}

// round 12
// speedup vs baseline: 1.0531x; 1.0531x over previous
#include <cuda_runtime.h>
#include <cuda_bf16.h>

#define LL 9
#define BB 4
#define CC 512
#define HW 1024

// ---------------- scratch (device globals; no allocation) ----------------
__device__ __align__(16) float g_invq[LL*BB*HW];
__device__ __align__(16) float g_invs[LL*BB*HW];
__device__ __align__(16) float g_corr[(size_t)BB*HW*HW];   // 16 MB, reused as attn
__device__ __align__(16) float g_c1[BB*256*HW];            // conv1 out [b][256][32*32]
__device__ __align__(16) float g_c1pa[BB*256*HW];          // conv1 K-split partials
__device__ __align__(16) float g_c1pb[BB*256*HW];
__device__ __align__(16) float g_attpa[BB*CC*HW];          // att K-split partials
__device__ __align__(16) float g_attpb[BB*CC*HW];
__device__ __align__(16) float g_c2[BB*256*900];           // conv2 out [b][256][30*30]
__device__ __align__(16) float g_pool[BB*256*100];         // pooled [b][256][10*10]
__device__ __align__(16) __nv_bfloat16 g_wt1h[9*1024*256]; // w1 hi [tap][ic][oc]
__device__ __align__(16) __nv_bfloat16 g_wt1l[9*1024*256]; // w1 lo [tap][ic][oc]
__device__ __align__(16) __nv_bfloat16 g_wt2h[9*256*256];  // w2 hi [tap][ic][oc]
__device__ __align__(16) __nv_bfloat16 g_wt2l[9*256*256];  // w2 lo [tap][ic][oc]
__device__ __align__(16) float g_nq2[BB*HW];
__device__ __align__(16) float g_na2[BB*HW];

// ---------------- helpers ----------------
__device__ __forceinline__ void ldsm4t(unsigned* r, unsigned addr) {
    asm volatile("ldmatrix.sync.aligned.m8n8.x4.trans.shared.b16 {%0,%1,%2,%3}, [%4];\n"
        : "=r"(r[0]), "=r"(r[1]), "=r"(r[2]), "=r"(r[3]) : "r"(addr));
}
__device__ __forceinline__ void ldsm4(unsigned* r, unsigned addr) {
    asm volatile("ldmatrix.sync.aligned.m8n8.x4.shared.b16 {%0,%1,%2,%3}, [%4];\n"
        : "=r"(r[0]), "=r"(r[1]), "=r"(r[2]), "=r"(r[3]) : "r"(addr));
}
__device__ __forceinline__ void mma_bf16(float* c, const unsigned* a, const unsigned* b) {
    asm volatile(
        "mma.sync.aligned.m16n8k16.row.col.f32.bf16.bf16.f32 "
        "{%0,%1,%2,%3}, {%4,%5,%6,%7}, {%8,%9}, {%0,%1,%2,%3};\n"
        : "+f"(c[0]), "+f"(c[1]), "+f"(c[2]), "+f"(c[3])
        : "r"(a[0]), "r"(a[1]), "r"(a[2]), "r"(a[3]), "r"(b[0]), "r"(b[1]));
}
// split float4 -> hi bf16x2 pair + lo bf16x2 pair (packed as unsigned)
__device__ __forceinline__ void cvt_hl(float4 v, unsigned& h0, unsigned& h1,
                                       unsigned& l0, unsigned& l1) {
    __nv_bfloat162 H0 = __floats2bfloat162_rn(v.x, v.y);
    __nv_bfloat162 H1 = __floats2bfloat162_rn(v.z, v.w);
    __nv_bfloat162 L0 = __floats2bfloat162_rn(v.x - __bfloat162float(H0.x),
                                              v.y - __bfloat162float(H0.y));
    __nv_bfloat162 L1 = __floats2bfloat162_rn(v.z - __bfloat162float(H1.x),
                                              v.w - __bfloat162float(H1.y));
    h0 = *(unsigned*)&H0; h1 = *(unsigned*)&H1;
    l0 = *(unsigned*)&L0; l1 = *(unsigned*)&L1;
}

// ---------------- weight prep ----------------
__global__ void k_twt1(const float* __restrict__ w1) {
    int i = blockIdx.x * 256 + threadIdx.x;          // < 2359296
    float v = w1[i];
    int oc = i / 9216; int r = i % 9216; int ic = r / 9; int tap = r % 9;
    __nv_bfloat16 h = __float2bfloat16(v);
    __nv_bfloat16 lo = __float2bfloat16(v - __bfloat162float(h));
    int o = tap * 262144 + ic * 256 + oc;
    g_wt1h[o] = h; g_wt1l[o] = lo;
}
__global__ void k_twt2(const float* __restrict__ w2) {
    int i = blockIdx.x * 256 + threadIdx.x;          // < 589824
    float v = w2[i];
    int oc = i / 2304; int r = i % 2304; int ic = r / 9; int tap = r % 9;
    __nv_bfloat16 h = __float2bfloat16(v);
    __nv_bfloat16 lo = __float2bfloat16(v - __bfloat162float(h));
    int o = tap * 65536 + ic * 256 + oc;
    g_wt2h[o] = h; g_wt2l[o] = lo;
}

// ---------------- per-level per-pixel inverse channel norms ----------------
__global__ void k_norms(const float* __restrict__ fq, const float* __restrict__ fs) {
    int lb  = blockIdx.y;                             // 0..35 (l*B+b)
    int pix = blockIdx.x * 256 + threadIdx.x;         // 0..1023
    const float* src = (blockIdx.z == 0 ? fq : fs) + (size_t)lb * CC * HW + pix;
    float ss = 0.f;
#pragma unroll 8
    for (int c = 0; c < CC; c++) { float v = src[(size_t)c * HW]; ss = fmaf(v, v, ss); }
    float inv = 1.0f / fmaxf(sqrtf(ss), 1e-12f);
    (blockIdx.z == 0 ? g_invq : g_invs)[lb * HW + pix] = inv;
}

// ---------------- corr: bf16-split tensor-core, cross-level pipelined ----------------
__global__ void __launch_bounds__(256, 2) k_corr(const float* __restrict__ fq,
                                                 const float* __restrict__ fs) {
    __shared__ __align__(16) unsigned smq[2][4][16][68];  // 68 u32 = 136 halves
    int b  = blockIdx.z;
    int m0 = blockIdx.y * 128, n0 = blockIdx.x * 128;
    int tid = threadIdx.x, lane = tid & 31, wid = tid >> 5;
    int wm = (wid >> 2) * 64, wn = (wid & 3) * 32;
    int kr = tid >> 4, mc = (tid & 15) * 8;           // loader: 16 k-rows x 8 floats

    int kA = (lane & 7) + ((lane >> 4) << 3);
    int cA = ((lane >> 3) & 1) << 3;
    int kB = (lane & 7) + (((lane >> 3) & 1) << 3);
    int cB = (lane >> 4) << 3;
    unsigned smbase = (unsigned)__cvta_generic_to_shared(&smq[0][0][0][0]);
    unsigned offA = (unsigned)(kA * 272 + (cA + wm) * 2);
    unsigned offB = (unsigned)(kB * 272 + (cB + wn) * 2);

    float* outp = g_corr + (size_t)b * HW * HW + (size_t)m0 * HW + n0;

    float c[4][4][4];
#pragma unroll
    for (int f = 0; f < 4; f++)
#pragma unroll
        for (int g = 0; g < 4; g++) { c[f][g][0]=0.f; c[f][g][1]=0.f; c[f][g][2]=0.f; c[f][g][3]=0.f; }

    {   // global prologue: (l=0, kt=0) -> buf 0
        const float* Ag = fq + (size_t)b * CC * HW + m0;
        const float* Bg = fs + (size_t)b * CC * HW + n0;
        float4 a0g = *(const float4*)(Ag + (size_t)kr * HW + mc);
        float4 a1g = *(const float4*)(Ag + (size_t)kr * HW + mc + 4);
        float4 b0g = *(const float4*)(Bg + (size_t)kr * HW + mc);
        float4 b1g = *(const float4*)(Bg + (size_t)kr * HW + mc + 4);
        unsigned h0,h1,l0,l1;
        unsigned* pAh = &smq[0][0][kr][mc >> 1];
        unsigned* pAl = &smq[0][1][kr][mc >> 1];
        unsigned* pBh = &smq[0][2][kr][mc >> 1];
        unsigned* pBl = &smq[0][3][kr][mc >> 1];
        cvt_hl(a0g,h0,h1,l0,l1); pAh[0]=h0; pAh[1]=h1; pAl[0]=l0; pAl[1]=l1;
        cvt_hl(a1g,h0,h1,l0,l1); pAh[2]=h0; pAh[3]=h1; pAl[2]=l0; pAl[3]=l1;
        cvt_hl(b0g,h0,h1,l0,l1); pBh[0]=h0; pBh[1]=h1; pBl[0]=l0; pBl[1]=l1;
        cvt_hl(b1g,h0,h1,l0,l1); pBh[2]=h0; pBh[3]=h1; pBl[2]=l0; pBl[3]=l1;
    }
    __syncthreads();

    int buf = 0;
    for (int lkt = 0; lkt < 288; lkt++) {
        int l = lkt >> 5;
        // prefetch lkt+1
        float4 a0g, a1g, b0g, b1g;
        if (lkt < 287) {
            int nk = lkt + 1;
            int l2 = nk >> 5, k2 = (nk & 31) * 16;
            const float* Ag = fq + (size_t)(l2 * BB + b) * CC * HW + m0;
            const float* Bg = fs + (size_t)(l2 * BB + b) * CC * HW + n0;
            a0g = *(const float4*)(Ag + (size_t)(k2 + kr) * HW + mc);
            a1g = *(const float4*)(Ag + (size_t)(k2 + kr) * HW + mc + 4);
            b0g = *(const float4*)(Bg + (size_t)(k2 + kr) * HW + mc);
            b1g = *(const float4*)(Bg + (size_t)(k2 + kr) * HW + mc + 4);
        }
        unsigned base = smbase + (unsigned)buf * 17408u;
        unsigned a[16], bh[8], bl[8];
#pragma unroll
        for (int f = 0; f < 4; f++) ldsm4t(a + 4 * f, base + offA + f * 32);
#pragma unroll
        for (int g2 = 0; g2 < 2; g2++) ldsm4t(bh + 4 * g2, base + 2u * 4352u + offB + g2 * 32);
#pragma unroll
        for (int g2 = 0; g2 < 2; g2++) ldsm4t(bl + 4 * g2, base + 3u * 4352u + offB + g2 * 32);
#pragma unroll
        for (int f = 0; f < 4; f++)
#pragma unroll
            for (int g = 0; g < 4; g++) {
                mma_bf16(c[f][g], a + 4 * f, bh + 2 * g);
                mma_bf16(c[f][g], a + 4 * f, bl + 2 * g);
            }
#pragma unroll
        for (int f = 0; f < 4; f++) ldsm4t(a + 4 * f, base + 4352u + offA + f * 32);
#pragma unroll
        for (int f = 0; f < 4; f++)
#pragma unroll
            for (int g = 0; g < 4; g++)
                mma_bf16(c[f][g], a + 4 * f, bh + 2 * g);

        if (lkt < 287) {   // STS to other buffer (before epilogue; sync after)
            int nb = buf ^ 1;
            unsigned h0,h1,l0,l1;
            unsigned* pAh = &smq[nb][0][kr][mc >> 1];
            unsigned* pAl = &smq[nb][1][kr][mc >> 1];
            unsigned* pBh = &smq[nb][2][kr][mc >> 1];
            unsigned* pBl = &smq[nb][3][kr][mc >> 1];
            cvt_hl(a0g,h0,h1,l0,l1); pAh[0]=h0; pAh[1]=h1; pAl[0]=l0; pAl[1]=l1;
            cvt_hl(a1g,h0,h1,l0,l1); pAh[2]=h0; pAh[3]=h1; pAl[2]=l0; pAl[3]=l1;
            cvt_hl(b0g,h0,h1,l0,l1); pBh[0]=h0; pBh[1]=h1; pBl[0]=l0; pBl[1]=l1;
            cvt_hl(b1g,h0,h1,l0,l1); pBh[2]=h0; pBh[3]=h1; pBl[2]=l0; pBl[3]=l1;
        }

        if ((lkt & 31) == 31) {   // level epilogue: scale, relu, L2-resident RMW; reset c
            const float* iq = g_invq + (l * BB + b) * HW + m0;
            const float* is = g_invs + (l * BB + b) * HW + n0;
#pragma unroll
            for (int f = 0; f < 4; f++) {
                int r0 = wm + f * 16 + (lane >> 2), r1 = r0 + 8;
                float q0 = iq[r0], q1 = iq[r1];
#pragma unroll
                for (int g = 0; g < 4; g++) {
                    int cb = wn + g * 8 + (lane & 3) * 2;
                    float s0 = is[cb], s1 = is[cb + 1];
                    float v00 = fmaxf(c[f][g][0] * q0 * s0, 0.f);
                    float v01 = fmaxf(c[f][g][1] * q0 * s1, 0.f);
                    float v10 = fmaxf(c[f][g][2] * q1 * s0, 0.f);
                    float v11 = fmaxf(c[f][g][3] * q1 * s1, 0.f);
                    float2* p0 = (float2*)(outp + (size_t)r0 * HW + cb);
                    float2* p1 = (float2*)(outp + (size_t)r1 * HW + cb);
                    if (l == 0) {
                        *p0 = make_float2(v00, v01);
                        *p1 = make_float2(v10, v11);
                    } else {
                        float2 o0 = *p0, o1 = *p1;
                        o0.x += v00; o0.y += v01; o1.x += v10; o1.y += v11;
                        *p0 = o0; *p1 = o1;
                    }
                    c[f][g][0]=0.f; c[f][g][1]=0.f; c[f][g][2]=0.f; c[f][g][3]=0.f;
                }
            }
        }

        if (lkt < 287) {
            __syncthreads();
            buf ^= 1;
        }
    }
}

// ---------------- row softmax (scale = TEMP/L folds the mean) ----------------
__global__ void k_softmax() {
    float* r = g_corr + (size_t)blockIdx.x * HW;      // blockIdx.x = b*1024 + q
    int tid = threadIdx.x, wid = tid >> 5, lane = tid & 31;
    const float sc = 20.0f / 9.0f;
    float4 v = ((const float4*)r)[tid];
    v.x *= sc; v.y *= sc; v.z *= sc; v.w *= sc;
    float mx = fmaxf(fmaxf(v.x, v.y), fmaxf(v.z, v.w));
#pragma unroll
    for (int o = 16; o; o >>= 1) mx = fmaxf(mx, __shfl_xor_sync(0xffffffffu, mx, o));
    __shared__ float sh[8];
    if (lane == 0) sh[wid] = mx;
    __syncthreads();
    float m = sh[0];
#pragma unroll
    for (int k = 1; k < 8; k++) m = fmaxf(m, sh[k]);
    v.x = __expf(v.x - m); v.y = __expf(v.y - m);
    v.z = __expf(v.z - m); v.w = __expf(v.w - m);
    float s = v.x + v.y + v.z + v.w;
#pragma unroll
    for (int o = 16; o; o >>= 1) s += __shfl_xor_sync(0xffffffffu, s, o);
    __syncthreads();
    if (lane == 0) sh[wid] = s;
    __syncthreads();
    float tot = 0.f;
#pragma unroll
    for (int k = 0; k < 8; k++) tot += sh[k];
    float inv = 1.0f / tot;
    v.x *= inv; v.y *= inv; v.z *= inv; v.w *= inv;
    ((float4*)r)[tid] = v;
}

// ---------------- k_att: bf16-split MMA, K-split by 2 (half = z&1) ----------------
__global__ void __launch_bounds__(256, 2) k_att(const float* __restrict__ fs_in) {
    __shared__ __align__(16) uint4 smA[2][2][2][128];   // [buf][hl][kb][row]
    __shared__ __align__(16) uint4 smB[2][2][2][128];
    int b = blockIdx.z >> 1, half = blockIdx.z & 1;
    int m0 = blockIdx.y * 128, n0 = blockIdx.x * 128;
    int tid = threadIdx.x, lane = tid & 31, wid = tid >> 5;
    int wm = (wid >> 2) * 64, wn = (wid & 3) * 32;
    int lrow = tid >> 1, lkb = tid & 1;

    const float* Ag = fs_in + (size_t)b * CC * HW + (size_t)m0 * HW + half * 512;
    const float* Bg = g_corr + (size_t)b * HW * HW + (size_t)n0 * HW + half * 512;

    int rsel = ((lane >> 3) & 1) * 8 + (lane & 7);
    int kbsel = lane >> 4;
    unsigned baseA = (unsigned)__cvta_generic_to_shared(&smA[0][0][0][0]);
    unsigned baseB = (unsigned)__cvta_generic_to_shared(&smB[0][0][0][0]);
    unsigned offA = (unsigned)(kbsel * 2048 + (wm + rsel) * 16);     // + f*256
    unsigned offB = (unsigned)(kbsel * 2048 + (wn + rsel) * 16);     // + gg*256

    float c[4][4][4];
#pragma unroll
    for (int f = 0; f < 4; f++)
#pragma unroll
        for (int g = 0; g < 4; g++) { c[f][g][0]=0.f; c[f][g][1]=0.f; c[f][g][2]=0.f; c[f][g][3]=0.f; }

    {   // prologue: k-tile 0
        float4 a0g = *(const float4*)(Ag + (size_t)lrow * HW + lkb * 8);
        float4 a1g = *(const float4*)(Ag + (size_t)lrow * HW + lkb * 8 + 4);
        float4 b0g = *(const float4*)(Bg + (size_t)lrow * HW + lkb * 8);
        float4 b1g = *(const float4*)(Bg + (size_t)lrow * HW + lkb * 8 + 4);
        unsigned h0,h1,l0,l1,h2,h3,l2,l3;
        cvt_hl(a0g,h0,h1,l0,l1); cvt_hl(a1g,h2,h3,l2,l3);
        smA[0][0][lkb][lrow] = make_uint4(h0,h1,h2,h3);
        smA[0][1][lkb][lrow] = make_uint4(l0,l1,l2,l3);
        cvt_hl(b0g,h0,h1,l0,l1); cvt_hl(b1g,h2,h3,l2,l3);
        smB[0][0][lkb][lrow] = make_uint4(h0,h1,h2,h3);
        smB[0][1][lkb][lrow] = make_uint4(l0,l1,l2,l3);
    }
    __syncthreads();

    int buf = 0;
    for (int kt = 0; kt < 32; kt++) {
        float4 a0g, a1g, b0g, b1g;
        if (kt < 31) {
            int k0 = (kt + 1) * 16 + lkb * 8;
            a0g = *(const float4*)(Ag + (size_t)lrow * HW + k0);
            a1g = *(const float4*)(Ag + (size_t)lrow * HW + k0 + 4);
            b0g = *(const float4*)(Bg + (size_t)lrow * HW + k0);
            b1g = *(const float4*)(Bg + (size_t)lrow * HW + k0 + 4);
        }
        unsigned bA = baseA + (unsigned)buf * 8192u;
        unsigned bB = baseB + (unsigned)buf * 8192u;
        unsigned a[16], bh[8], bl[8], t[4];
#pragma unroll
        for (int f = 0; f < 4; f++) ldsm4(a + 4 * f, bA + offA + f * 256);
#pragma unroll
        for (int gg = 0; gg < 2; gg++) {
            ldsm4(t, bB + offB + gg * 256);
            bh[gg*4+0]=t[0]; bh[gg*4+1]=t[2]; bh[gg*4+2]=t[1]; bh[gg*4+3]=t[3];
        }
#pragma unroll
        for (int gg = 0; gg < 2; gg++) {
            ldsm4(t, bB + 4096u + offB + gg * 256);
            bl[gg*4+0]=t[0]; bl[gg*4+1]=t[2]; bl[gg*4+2]=t[1]; bl[gg*4+3]=t[3];
        }
#pragma unroll
        for (int f = 0; f < 4; f++)
#pragma unroll
            for (int g = 0; g < 4; g++) {
                mma_bf16(c[f][g], a + 4 * f, bh + 2 * g);
                mma_bf16(c[f][g], a + 4 * f, bl + 2 * g);
            }
#pragma unroll
        for (int f = 0; f < 4; f++) ldsm4(a + 4 * f, bA + 4096u + offA + f * 256);
#pragma unroll
        for (int f = 0; f < 4; f++)
#pragma unroll
            for (int g = 0; g < 4; g++)
                mma_bf16(c[f][g], a + 4 * f, bh + 2 * g);

        if (kt < 31) {
            int nb = buf ^ 1;
            unsigned h0,h1,l0,l1,h2,h3,l2,l3;
            cvt_hl(a0g,h0,h1,l0,l1); cvt_hl(a1g,h2,h3,l2,l3);
            smA[nb][0][lkb][lrow] = make_uint4(h0,h1,h2,h3);
            smA[nb][1][lkb][lrow] = make_uint4(l0,l1,l2,l3);
            cvt_hl(b0g,h0,h1,l0,l1); cvt_hl(b1g,h2,h3,l2,l3);
            smB[nb][0][lkb][lrow] = make_uint4(h0,h1,h2,h3);
            smB[nb][1][lkb][lrow] = make_uint4(l0,l1,l2,l3);
            __syncthreads();
            buf = nb;
        }
    }

    float* outp = (half ? g_attpb : g_attpa) + (size_t)b * CC * HW + (size_t)m0 * HW + n0;
#pragma unroll
    for (int f = 0; f < 4; f++) {
        int r0 = wm + f * 16 + (lane >> 2), r1 = r0 + 8;
#pragma unroll
        for (int g = 0; g < 4; g++) {
            int cb = wn + g * 8 + (lane & 3) * 2;
            *(float2*)(outp + (size_t)r0 * HW + cb) = make_float2(c[f][g][0], c[f][g][1]);
            *(float2*)(outp + (size_t)r1 * HW + cb) = make_float2(c[f][g][2], c[f][g][3]);
        }
    }
}

// att_out = pa + pb
__global__ void k_attcomb(float* __restrict__ attout) {
    int i4 = blockIdx.x * 256 + threadIdx.x;          // < 524288
    float4 a = ((const float4*)g_attpa)[i4];
    float4 bb = ((const float4*)g_attpb)[i4];
    ((float4*)attout)[i4] = make_float4(a.x + bb.x, a.y + bb.y, a.z + bb.z, a.w + bb.w);
}

// ---------------- inverse channel norms of f_q and att_fq ----------------
__global__ void k_norm2(const float* __restrict__ f_q, const float* __restrict__ att) {
    int b   = blockIdx.y;
    int pix = blockIdx.x * 256 + threadIdx.x;
    const float* src = (blockIdx.z == 0 ? f_q : att) + (size_t)b * CC * HW + pix;
    float ss = 0.f;
#pragma unroll 8
    for (int c = 0; c < CC; c++) { float v = src[(size_t)c * HW]; ss = fmaf(v, v, ss); }
    float inv = 1.0f / fmaxf(sqrtf(ss), 1e-12f);
    (blockIdx.z == 0 ? g_nq2 : g_na2)[b * HW + pix] = inv;
}

// ---------------- fq = l2n(f_q) + 0.5*l2n(att_fq) ----------------
__global__ void k_fqout(const float* __restrict__ f_q, const float* __restrict__ att,
                        float* __restrict__ fqo) {
    int i4 = blockIdx.x * 256 + threadIdx.x;          // < 524288
    int base = i4 * 4;
    int b = base >> 19;
    int pix = base & 1023;
    float4 q = ((const float4*)f_q)[i4];
    float4 a = ((const float4*)att)[i4];
    int ni = (b * HW + pix) >> 2;
    float4 nq = ((const float4*)g_nq2)[ni];
    float4 na = ((const float4*)g_na2)[ni];
    float4 o;
    o.x = q.x * nq.x + a.x * na.x * 0.5f;
    o.y = q.y * nq.y + a.y * na.y * 0.5f;
    o.z = q.z * nq.z + a.z * na.z * 0.5f;
    o.w = q.w * nq.w + a.w * na.w * 0.5f;
    ((float4*)fqo)[i4] = o;
}

// ---------------- conv1: bf16-split tensor implicit GEMM, K-split by 2 ----------------
__global__ void __launch_bounds__(256, 2) k_conv1(const float* __restrict__ f_q,
                                                  const float* __restrict__ f_s) {
    __shared__ __align__(16) unsigned smW[2][2][16][36];  // [buf][hi/lo][k][oc72h]
    __shared__ __align__(16) unsigned smI[2][2][16][68];  // [buf][hi/lo][k][pix136h]
    int b = blockIdx.z >> 1, half = blockIdx.z & 1;
    int oc0 = blockIdx.y * 64, pix0 = blockIdx.x * 128;
    int tid = threadIdx.x, lane = tid & 31, wid = tid >> 5;
    int wm = (wid >> 2) * 32, wn = (wid & 3) * 32;
    int kr = tid >> 4, mc = (tid & 15) * 8;

    int kA = (lane & 7) + ((lane >> 4) << 3);
    int cA = ((lane >> 3) & 1) << 3;
    int kB = (lane & 7) + (((lane >> 3) & 1) << 3);
    int cB = (lane >> 4) << 3;
    unsigned baseW = (unsigned)__cvta_generic_to_shared(&smW[0][0][0][0]);
    unsigned baseI = (unsigned)__cvta_generic_to_shared(&smI[0][0][0][0]);
    unsigned offA = (unsigned)(kA * 144 + (cA + wm) * 2);
    unsigned offB = (unsigned)(kB * 272 + (cB + wn) * 2);

    const float* fqp = f_q + (size_t)b * CC * HW;
    const float* fsp = f_s + (size_t)b * CC * HW;

    int pp0 = pix0 + mc;
    int py = pp0 >> 5, px0v = pp0 & 31;
    int wtt = (tid & 127);
    int wrow = wtt >> 3, wcol8 = (wtt & 7) * 8;
    bool whalf = (tid < 128);
    int kbase = half * 288;                           // global k-tile base

    float c[2][4][4];
#pragma unroll
    for (int f = 0; f < 2; f++)
#pragma unroll
        for (int g = 0; g < 4; g++) { c[f][g][0]=0.f; c[f][g][1]=0.f; c[f][g][2]=0.f; c[f][g][3]=0.f; }

    {   // prologue: global k-tile kbase
        int tap = kbase >> 6, ict = kbase & 63;
        int dy = 2 * (tap / 3) - 2, dx = 2 * (tap % 3) - 2;
        uint4 wv;
        const __nv_bfloat16* wsrc = whalf ? g_wt1h : g_wt1l;
        wv = *(const uint4*)(wsrc + (size_t)(tap * 1024 + ict * 16 + wrow) * 256 + oc0 + wcol8);
        float v[8];
        int ic = ict * 16 + kr;
        const float* src = (ic < 512 ? fqp + (size_t)ic * HW
                                     : fsp + (size_t)(ic - 512) * HW);
        int iy = py + dy;
        bool yok = ((unsigned)iy < 32u);
        const float* rowp = src + iy * 32;
#pragma unroll
        for (int j = 0; j < 8; j++) {
            int ix = px0v + j + dx;
            v[j] = (yok && ((unsigned)ix < 32u)) ? rowp[ix] : 0.f;
        }
        *(uint4*)&smW[0][whalf ? 0 : 1][wrow][wcol8 >> 1] = wv;
        unsigned h0,h1,l0,l1;
        unsigned* pIh = &smI[0][0][kr][mc >> 1];
        unsigned* pIl = &smI[0][1][kr][mc >> 1];
        float4 fa = make_float4(v[0], v[1], v[2], v[3]);
        float4 fb = make_float4(v[4], v[5], v[6], v[7]);
        cvt_hl(fa,h0,h1,l0,l1); pIh[0]=h0; pIh[1]=h1; pIl[0]=l0; pIl[1]=l1;
        cvt_hl(fb,h0,h1,l0,l1); pIh[2]=h0; pIh[3]=h1; pIl[2]=l0; pIl[3]=l1;
    }
    __syncthreads();

    int buf = 0;
    for (int kt = 0; kt < 288; kt++) {
        uint4 wv; float v[8];
        if (kt < 287) {
            int kn = kbase + kt + 1;
            int tap = kn >> 6, ict = kn & 63;
            int dy = 2 * (tap / 3) - 2, dx = 2 * (tap % 3) - 2;
            const __nv_bfloat16* wsrc = whalf ? g_wt1h : g_wt1l;
            wv = *(const uint4*)(wsrc + (size_t)(tap * 1024 + ict * 16 + wrow) * 256 + oc0 + wcol8);
            int ic = ict * 16 + kr;
            const float* src = (ic < 512 ? fqp + (size_t)ic * HW
                                         : fsp + (size_t)(ic - 512) * HW);
            int iy = py + dy;
            bool yok = ((unsigned)iy < 32u);
            const float* rowp = src + iy * 32;
#pragma unroll
            for (int j = 0; j < 8; j++) {
                int ix = px0v + j + dx;
                v[j] = (yok && ((unsigned)ix < 32u)) ? rowp[ix] : 0.f;
            }
        }
        unsigned bW = baseW + (unsigned)buf * 4608u;
        unsigned bI = baseI + (unsigned)buf * 8704u;
        unsigned a[8], al[8], bh[8], bl[8];
#pragma unroll
        for (int f = 0; f < 2; f++) ldsm4t(a  + 4 * f, bW + offA + f * 32);
#pragma unroll
        for (int f = 0; f < 2; f++) ldsm4t(al + 4 * f, bW + 2304u + offA + f * 32);
#pragma unroll
        for (int g2 = 0; g2 < 2; g2++) ldsm4t(bh + 4 * g2, bI + offB + g2 * 32);
#pragma unroll
        for (int g2 = 0; g2 < 2; g2++) ldsm4t(bl + 4 * g2, bI + 4352u + offB + g2 * 32);
#pragma unroll
        for (int f = 0; f < 2; f++)
#pragma unroll
            for (int g = 0; g < 4; g++) {
                mma_bf16(c[f][g], a  + 4 * f, bh + 2 * g);
                mma_bf16(c[f][g], a  + 4 * f, bl + 2 * g);
                mma_bf16(c[f][g], al + 4 * f, bh + 2 * g);
            }
        if (kt < 287) {
            int nb = buf ^ 1;
            *(uint4*)&smW[nb][whalf ? 0 : 1][wrow][wcol8 >> 1] = wv;
            unsigned h0,h1,l0,l1;
            unsigned* pIh = &smI[nb][0][kr][mc >> 1];
            unsigned* pIl = &smI[nb][1][kr][mc >> 1];
            float4 fa = make_float4(v[0], v[1], v[2], v[3]);
            float4 fb = make_float4(v[4], v[5], v[6], v[7]);
            cvt_hl(fa,h0,h1,l0,l1); pIh[0]=h0; pIh[1]=h1; pIl[0]=l0; pIl[1]=l1;
            cvt_hl(fb,h0,h1,l0,l1); pIh[2]=h0; pIh[3]=h1; pIl[2]=l0; pIl[3]=l1;
            __syncthreads();
            buf = nb;
        }
    }

    float* outp = (half ? g_c1pb : g_c1pa) + (size_t)b * 262144;
#pragma unroll
    for (int f = 0; f < 2; f++) {
        int r0 = wm + f * 16 + (lane >> 2), r1 = r0 + 8;
#pragma unroll
        for (int g = 0; g < 4; g++) {
            int cb = wn + g * 8 + (lane & 3) * 2;
            *(float2*)(outp + (size_t)(oc0 + r0) * HW + pix0 + cb) =
                make_float2(c[f][g][0], c[f][g][1]);
            *(float2*)(outp + (size_t)(oc0 + r1) * HW + pix0 + cb) =
                make_float2(c[f][g][2], c[f][g][3]);
        }
    }
}

// c1 = relu(pa + pb + bias)
__global__ void k_c1comb(const float* __restrict__ b1) {
    int i4 = blockIdx.x * 256 + threadIdx.x;          // < 262144
    float4 a = ((const float4*)g_c1pa)[i4];
    float4 bb = ((const float4*)g_c1pb)[i4];
    int oc = (i4 & 65535) >> 8;                       // per-b block: 65536 f4, 256 f4 per oc
    float bias = b1[oc];
    float4 o;
    o.x = fmaxf(a.x + bb.x + bias, 0.f);
    o.y = fmaxf(a.y + bb.y + bias, 0.f);
    o.z = fmaxf(a.z + bb.z + bias, 0.f);
    o.w = fmaxf(a.w + bb.w + bias, 0.f);
    ((float4*)g_c1)[i4] = o;
}

// ---------------- conv2: bf16-split tensor implicit GEMM (unsplit, bias epilogue) ----------------
__global__ void __launch_bounds__(256, 2) k_conv2(const float* __restrict__ b2) {
    __shared__ __align__(16) unsigned smW[2][2][16][36];
    __shared__ __align__(16) unsigned smI[2][2][16][68];
    int b = blockIdx.z, oc0 = blockIdx.y * 64, pix0 = blockIdx.x * 128;
    int tid = threadIdx.x, lane = tid & 31, wid = tid >> 5;
    int wm = (wid >> 2) * 32, wn = (wid & 3) * 32;
    int kr = tid >> 4, mc = (tid & 15) * 8;

    int kA = (lane & 7) + ((lane >> 4) << 3);
    int cA = ((lane >> 3) & 1) << 3;
    int kB = (lane & 7) + (((lane >> 3) & 1) << 3);
    int cB = (lane >> 4) << 3;
    unsigned baseW = (unsigned)__cvta_generic_to_shared(&smW[0][0][0][0]);
    unsigned baseI = (unsigned)__cvta_generic_to_shared(&smI[0][0][0][0]);
    unsigned offA = (unsigned)(kA * 144 + (cA + wm) * 2);
    unsigned offB = (unsigned)(kB * 272 + (cB + wn) * 2);

    const float* c1p = g_c1 + (size_t)b * 262144;

    int offp[8];
#pragma unroll
    for (int j = 0; j < 8; j++) {
        int p = pix0 + mc + j; if (p > 899) p = 899;
        offp[j] = (p / 30) * 32 + (p % 30);
    }
    int wtt = (tid & 127);
    int wrow = wtt >> 3, wcol8 = (wtt & 7) * 8;
    bool whalf = (tid < 128);

    float c[2][4][4];
#pragma unroll
    for (int f = 0; f < 2; f++)
#pragma unroll
        for (int g = 0; g < 4; g++) { c[f][g][0]=0.f; c[f][g][1]=0.f; c[f][g][2]=0.f; c[f][g][3]=0.f; }

    {   // prologue kt=0: tap 0 (dy=0,dx=0), ict 0
        uint4 wv;
        const __nv_bfloat16* wsrc = whalf ? g_wt2h : g_wt2l;
        wv = *(const uint4*)(wsrc + (size_t)wrow * 256 + oc0 + wcol8);
        float v[8];
        const float* src = c1p + (size_t)kr * HW;
#pragma unroll
        for (int j = 0; j < 8; j++) v[j] = src[offp[j]];
        *(uint4*)&smW[0][whalf ? 0 : 1][wrow][wcol8 >> 1] = wv;
        unsigned h0,h1,l0,l1;
        unsigned* pIh = &smI[0][0][kr][mc >> 1];
        unsigned* pIl = &smI[0][1][kr][mc >> 1];
        float4 fa = make_float4(v[0], v[1], v[2], v[3]);
        float4 fb = make_float4(v[4], v[5], v[6], v[7]);
        cvt_hl(fa,h0,h1,l0,l1); pIh[0]=h0; pIh[1]=h1; pIl[0]=l0; pIl[1]=l1;
        cvt_hl(fb,h0,h1,l0,l1); pIh[2]=h0; pIh[3]=h1; pIl[2]=l0; pIl[3]=l1;
    }
    __syncthreads();

    int buf = 0;
    for (int kt = 0; kt < 144; kt++) {
        uint4 wv; float v[8];
        if (kt < 143) {
            int kn = kt + 1;
            int tap = kn >> 4, ict = kn & 15;
            int doff = (tap / 3) * 32 + (tap % 3);
            const __nv_bfloat16* wsrc = whalf ? g_wt2h : g_wt2l;
            wv = *(const uint4*)(wsrc + (size_t)(tap * 256 + ict * 16 + wrow) * 256 + oc0 + wcol8);
            const float* src = c1p + (size_t)(ict * 16 + kr) * HW;
#pragma unroll
            for (int j = 0; j < 8; j++) v[j] = src[offp[j] + doff];
        }
        unsigned bW = baseW + (unsigned)buf * 4608u;
        unsigned bI = baseI + (unsigned)buf * 8704u;
        unsigned a[8], al[8], bh[8], bl[8];
#pragma unroll
        for (int f = 0; f < 2; f++) ldsm4t(a  + 4 * f, bW + offA + f * 32);
#pragma unroll
        for (int f = 0; f < 2; f++) ldsm4t(al + 4 * f, bW + 2304u + offA + f * 32);
#pragma unroll
        for (int g2 = 0; g2 < 2; g2++) ldsm4t(bh + 4 * g2, bI + offB + g2 * 32);
#pragma unroll
        for (int g2 = 0; g2 < 2; g2++) ldsm4t(bl + 4 * g2, bI + 4352u + offB + g2 * 32);
#pragma unroll
        for (int f = 0; f < 2; f++)
#pragma unroll
            for (int g = 0; g < 4; g++) {
                mma_bf16(c[f][g], a  + 4 * f, bh + 2 * g);
                mma_bf16(c[f][g], a  + 4 * f, bl + 2 * g);
                mma_bf16(c[f][g], al + 4 * f, bh + 2 * g);
            }
        if (kt < 143) {
            int nb = buf ^ 1;
            *(uint4*)&smW[nb][whalf ? 0 : 1][wrow][wcol8 >> 1] = wv;
            unsigned h0,h1,l0,l1;
            unsigned* pIh = &smI[nb][0][kr][mc >> 1];
            unsigned* pIl = &smI[nb][1][kr][mc >> 1];
            float4 fa = make_float4(v[0], v[1], v[2], v[3]);
            float4 fb = make_float4(v[4], v[5], v[6], v[7]);
            cvt_hl(fa,h0,h1,l0,l1); pIh[0]=h0; pIh[1]=h1; pIl[0]=l0; pIl[1]=l1;
            cvt_hl(fb,h0,h1,l0,l1); pIh[2]=h0; pIh[3]=h1; pIl[2]=l0; pIl[3]=l1;
            __syncthreads();
            buf = nb;
        }
    }

    float* outp = g_c2 + (size_t)b * 230400;
#pragma unroll
    for (int f = 0; f < 2; f++) {
        int r0 = wm + f * 16 + (lane >> 2), r1 = r0 + 8;
        float bias0 = b2[oc0 + r0], bias1 = b2[oc0 + r1];
#pragma unroll
        for (int g = 0; g < 4; g++) {
            int cb = wn + g * 8 + (lane & 3) * 2;
            int p0 = pix0 + cb;                // even; p0<900 => p0+1<=899
            if (p0 < 900) {
                *(float2*)(outp + (size_t)(oc0 + r0) * 900 + p0) =
                    make_float2(c[f][g][0] + bias0, c[f][g][1] + bias0);
                *(float2*)(outp + (size_t)(oc0 + r1) * 900 + p0) =
                    make_float2(c[f][g][2] + bias1, c[f][g][3] + bias1);
            }
        }
    }
}

// ---------------- 3x3 stride-3 maxpool: 30x30 -> 10x10 ----------------
__global__ void k_pool() {
    int oc = blockIdx.x, b = blockIdx.y;
    int t = threadIdx.x;
    if (t >= 100) return;
    int y = t / 10, x = t % 10;
    const float* in = g_c2 + ((size_t)b * 256 + oc) * 900;
    float m = -3.4e38f;
#pragma unroll
    for (int dy = 0; dy < 3; dy++)
#pragma unroll
        for (int dx = 0; dx < 3; dx++)
            m = fmaxf(m, in[(3 * y + dy) * 30 + 3 * x + dx]);
    g_pool[((size_t)b * 256 + oc) * 100 + t] = m;
}

// ---------------- conv3 (3x3 VALID, 10x10 -> 8x8) + mean -> weight[b] ----------------
__global__ void k_conv3(const float* __restrict__ w3, const float* __restrict__ b3,
                        float* __restrict__ wout) {
    int b = blockIdx.x;
    int tid = threadIdx.x;
    int o = tid >> 2, part = tid & 3;
    int oy = o >> 3, ox = o & 7;
    float s = 0.f;
    for (int ic = part * 64; ic < part * 64 + 64; ic++) {
        const float* pp = g_pool + ((size_t)b * 256 + ic) * 100 + oy * 10 + ox;
        const float* wp = w3 + ic * 9;
#pragma unroll
        for (int ky = 0; ky < 3; ky++)
#pragma unroll
            for (int kx = 0; kx < 3; kx++)
                s = fmaf(pp[ky * 10 + kx], wp[ky * 3 + kx], s);
    }
    s += __shfl_down_sync(0xffffffffu, s, 1);
    s += __shfl_down_sync(0xffffffffu, s, 2);
    __shared__ float sh[64];
    if (part == 0) sh[o] = s;
    __syncthreads();
    if (tid < 32) {
        float v = sh[tid] + sh[tid + 32];
#pragma unroll
        for (int off = 16; off; off >>= 1) v += __shfl_xor_sync(0xffffffffu, v, off);
        if (tid == 0) wout[b] = v * (1.0f / 64.0f) + b3[0];
    }
}

// ---------------- launch ----------------
extern "C" void kernel_launch(void* const* d_in, const int* in_sizes, int n_in,
                              void* d_out, int out_size) {
    const float* fq_feats = (const float*)d_in[0];
    const float* fs_feats = (const float*)d_in[1];
    const float* f_q = (const float*)d_in[2];
    const float* f_s = (const float*)d_in[3];
    const float* w1 = (const float*)d_in[4];
    const float* b1 = (const float*)d_in[5];
    const float* w2 = (const float*)d_in[6];
    const float* b2 = (const float*)d_in[7];
    const float* w3 = (const float*)d_in[8];
    const float* b3 = (const float*)d_in[9];

    float* out     = (float*)d_out;
    float* fq_out  = out;                       // [4,512,32,32]
    float* att_out = out + 2097152;             // [4,512,32,32]
    float* w_out   = out + 4194304;             // [1,4]

    k_twt1<<<9216, 256>>>(w1);
    k_twt2<<<2304, 256>>>(w2);
    k_norms<<<dim3(4, 36, 2), 256>>>(fq_feats, fs_feats);
    k_corr<<<dim3(8, 8, 4), 256>>>(fq_feats, fs_feats);
    k_softmax<<<4096, 256>>>();
    k_att<<<dim3(8, 4, 8), 256>>>(f_s);
    k_attcomb<<<2048, 256>>>(att_out);
    k_norm2<<<dim3(4, 4, 2), 256>>>(f_q, att_out);
    k_fqout<<<2048, 256>>>(f_q, att_out, fq_out);
    k_conv1<<<dim3(8, 4, 8), 256>>>(f_q, f_s);
    k_c1comb<<<1024, 256>>>(b1);
    k_conv2<<<dim3(8, 4, 4), 256>>>(b2);
    k_pool<<<dim3(256, 4), 128>>>();
    k_conv3<<<4, 256>>>(w3, b3, w_out);
}

// round 14
// speedup vs baseline: 1.0585x; 1.0051x over previous
#include <cuda_runtime.h>
#include <cuda_bf16.h>

#define LL 9
#define BB 4
#define CC 512
#define HW 1024

// ---------------- scratch (device globals; no allocation) ----------------
__device__ __align__(16) float g_invq[LL*BB*HW];
__device__ __align__(16) float g_invs[LL*BB*HW];
__device__ __align__(16) float g_corr[(size_t)BB*HW*HW];   // 16 MB, reused as attn
__device__ __align__(16) float g_c1[BB*256*HW];            // conv1 out [b][256][32*32]
__device__ __align__(16) float g_c1pa[BB*256*HW];          // conv1 K-split partials
__device__ __align__(16) float g_c1pb[BB*256*HW];
__device__ __align__(16) float g_attpa[BB*CC*HW];          // att K-split partials
__device__ __align__(16) float g_attpb[BB*CC*HW];
__device__ __align__(16) float g_c2[BB*256*900];           // conv2 out [b][256][30*30]
__device__ __align__(16) float g_pool[BB*256*100];         // pooled [b][256][10*10]
__device__ __align__(16) __nv_bfloat16 g_wt1h[9*1024*256]; // w1 hi [tap][ic][oc]
__device__ __align__(16) __nv_bfloat16 g_wt1l[9*1024*256]; // w1 lo [tap][ic][oc]
__device__ __align__(16) __nv_bfloat16 g_wt2h[9*256*256];  // w2 hi [tap][ic][oc]
__device__ __align__(16) __nv_bfloat16 g_wt2l[9*256*256];  // w2 lo [tap][ic][oc]
__device__ __align__(16) float g_nq2[BB*HW];
__device__ __align__(16) float g_na2[BB*HW];

// ---------------- helpers ----------------
__device__ __forceinline__ void ldsm4t(unsigned* r, unsigned addr) {
    asm volatile("ldmatrix.sync.aligned.m8n8.x4.trans.shared.b16 {%0,%1,%2,%3}, [%4];\n"
        : "=r"(r[0]), "=r"(r[1]), "=r"(r[2]), "=r"(r[3]) : "r"(addr));
}
__device__ __forceinline__ void ldsm4(unsigned* r, unsigned addr) {
    asm volatile("ldmatrix.sync.aligned.m8n8.x4.shared.b16 {%0,%1,%2,%3}, [%4];\n"
        : "=r"(r[0]), "=r"(r[1]), "=r"(r[2]), "=r"(r[3]) : "r"(addr));
}
__device__ __forceinline__ void mma_bf16(float* c, const unsigned* a, const unsigned* b) {
    asm volatile(
        "mma.sync.aligned.m16n8k16.row.col.f32.bf16.bf16.f32 "
        "{%0,%1,%2,%3}, {%4,%5,%6,%7}, {%8,%9}, {%0,%1,%2,%3};\n"
        : "+f"(c[0]), "+f"(c[1]), "+f"(c[2]), "+f"(c[3])
        : "r"(a[0]), "r"(a[1]), "r"(a[2]), "r"(a[3]), "r"(b[0]), "r"(b[1]));
}
// split float4 -> hi bf16x2 pair + lo bf16x2 pair (packed as unsigned)
__device__ __forceinline__ void cvt_hl(float4 v, unsigned& h0, unsigned& h1,
                                       unsigned& l0, unsigned& l1) {
    __nv_bfloat162 H0 = __floats2bfloat162_rn(v.x, v.y);
    __nv_bfloat162 H1 = __floats2bfloat162_rn(v.z, v.w);
    __nv_bfloat162 L0 = __floats2bfloat162_rn(v.x - __bfloat162float(H0.x),
                                              v.y - __bfloat162float(H0.y));
    __nv_bfloat162 L1 = __floats2bfloat162_rn(v.z - __bfloat162float(H1.x),
                                              v.w - __bfloat162float(H1.y));
    h0 = *(unsigned*)&H0; h1 = *(unsigned*)&H1;
    l0 = *(unsigned*)&L0; l1 = *(unsigned*)&L1;
}

// ---------------- weight prep ----------------
__global__ void k_twt1(const float* __restrict__ w1) {
    int i = blockIdx.x * 256 + threadIdx.x;          // < 2359296
    float v = w1[i];
    int oc = i / 9216; int r = i % 9216; int ic = r / 9; int tap = r % 9;
    __nv_bfloat16 h = __float2bfloat16(v);
    __nv_bfloat16 lo = __float2bfloat16(v - __bfloat162float(h));
    int o = tap * 262144 + ic * 256 + oc;
    g_wt1h[o] = h; g_wt1l[o] = lo;
}
__global__ void k_twt2(const float* __restrict__ w2) {
    int i = blockIdx.x * 256 + threadIdx.x;          // < 589824
    float v = w2[i];
    int oc = i / 2304; int r = i % 2304; int ic = r / 9; int tap = r % 9;
    __nv_bfloat16 h = __float2bfloat16(v);
    __nv_bfloat16 lo = __float2bfloat16(v - __bfloat162float(h));
    int o = tap * 65536 + ic * 256 + oc;
    g_wt2h[o] = h; g_wt2l[o] = lo;
}

// ---------------- per-level per-pixel inverse channel norms ----------------
__global__ void k_norms(const float* __restrict__ fq, const float* __restrict__ fs) {
    int lb  = blockIdx.y;                             // 0..35 (l*B+b)
    int pix = blockIdx.x * 256 + threadIdx.x;         // 0..1023
    const float* src = (blockIdx.z == 0 ? fq : fs) + (size_t)lb * CC * HW + pix;
    float ss = 0.f;
#pragma unroll 8
    for (int c = 0; c < CC; c++) { float v = src[(size_t)c * HW]; ss = fmaf(v, v, ss); }
    float inv = 1.0f / fmaxf(sqrtf(ss), 1e-12f);
    (blockIdx.z == 0 ? g_invq : g_invs)[lb * HW + pix] = inv;
}

// ---------------- corr: bf16-split tensor-core, cross-level pipelined ----------------
__global__ void __launch_bounds__(256, 2) k_corr(const float* __restrict__ fq,
                                                 const float* __restrict__ fs) {
    __shared__ __align__(16) unsigned smq[2][4][16][68];  // 68 u32 = 136 halves
    int b  = blockIdx.z;
    int m0 = blockIdx.y * 128, n0 = blockIdx.x * 128;
    int tid = threadIdx.x, lane = tid & 31, wid = tid >> 5;
    int wm = (wid >> 2) * 64, wn = (wid & 3) * 32;
    int kr = tid >> 4, mc = (tid & 15) * 8;           // loader: 16 k-rows x 8 floats

    int kA = (lane & 7) + ((lane >> 4) << 3);
    int cA = ((lane >> 3) & 1) << 3;
    int kB = (lane & 7) + (((lane >> 3) & 1) << 3);
    int cB = (lane >> 4) << 3;
    unsigned smbase = (unsigned)__cvta_generic_to_shared(&smq[0][0][0][0]);
    unsigned offA = (unsigned)(kA * 272 + (cA + wm) * 2);
    unsigned offB = (unsigned)(kB * 272 + (cB + wn) * 2);

    float* outp = g_corr + (size_t)b * HW * HW + (size_t)m0 * HW + n0;

    float c[4][4][4];
#pragma unroll
    for (int f = 0; f < 4; f++)
#pragma unroll
        for (int g = 0; g < 4; g++) { c[f][g][0]=0.f; c[f][g][1]=0.f; c[f][g][2]=0.f; c[f][g][3]=0.f; }

    {   // global prologue: (l=0, kt=0) -> buf 0
        const float* Ag = fq + (size_t)b * CC * HW + m0;
        const float* Bg = fs + (size_t)b * CC * HW + n0;
        float4 a0g = *(const float4*)(Ag + (size_t)kr * HW + mc);
        float4 a1g = *(const float4*)(Ag + (size_t)kr * HW + mc + 4);
        float4 b0g = *(const float4*)(Bg + (size_t)kr * HW + mc);
        float4 b1g = *(const float4*)(Bg + (size_t)kr * HW + mc + 4);
        unsigned h0,h1,l0,l1;
        unsigned* pAh = &smq[0][0][kr][mc >> 1];
        unsigned* pAl = &smq[0][1][kr][mc >> 1];
        unsigned* pBh = &smq[0][2][kr][mc >> 1];
        unsigned* pBl = &smq[0][3][kr][mc >> 1];
        cvt_hl(a0g,h0,h1,l0,l1); pAh[0]=h0; pAh[1]=h1; pAl[0]=l0; pAl[1]=l1;
        cvt_hl(a1g,h0,h1,l0,l1); pAh[2]=h0; pAh[3]=h1; pAl[2]=l0; pAl[3]=l1;
        cvt_hl(b0g,h0,h1,l0,l1); pBh[0]=h0; pBh[1]=h1; pBl[0]=l0; pBl[1]=l1;
        cvt_hl(b1g,h0,h1,l0,l1); pBh[2]=h0; pBh[3]=h1; pBl[2]=l0; pBl[3]=l1;
    }
    __syncthreads();

    int buf = 0;
    for (int lkt = 0; lkt < 288; lkt++) {
        int l = lkt >> 5;
        // prefetch lkt+1
        float4 a0g, a1g, b0g, b1g;
        if (lkt < 287) {
            int nk = lkt + 1;
            int l2 = nk >> 5, k2 = (nk & 31) * 16;
            const float* Ag = fq + (size_t)(l2 * BB + b) * CC * HW + m0;
            const float* Bg = fs + (size_t)(l2 * BB + b) * CC * HW + n0;
            a0g = *(const float4*)(Ag + (size_t)(k2 + kr) * HW + mc);
            a1g = *(const float4*)(Ag + (size_t)(k2 + kr) * HW + mc + 4);
            b0g = *(const float4*)(Bg + (size_t)(k2 + kr) * HW + mc);
            b1g = *(const float4*)(Bg + (size_t)(k2 + kr) * HW + mc + 4);
        }
        unsigned base = smbase + (unsigned)buf * 17408u;
        unsigned a[16], bh[8], bl[8];
#pragma unroll
        for (int f = 0; f < 4; f++) ldsm4t(a + 4 * f, base + offA + f * 32);
#pragma unroll
        for (int g2 = 0; g2 < 2; g2++) ldsm4t(bh + 4 * g2, base + 2u * 4352u + offB + g2 * 32);
#pragma unroll
        for (int g2 = 0; g2 < 2; g2++) ldsm4t(bl + 4 * g2, base + 3u * 4352u + offB + g2 * 32);
#pragma unroll
        for (int f = 0; f < 4; f++)
#pragma unroll
            for (int g = 0; g < 4; g++) {
                mma_bf16(c[f][g], a + 4 * f, bh + 2 * g);
                mma_bf16(c[f][g], a + 4 * f, bl + 2 * g);
            }
#pragma unroll
        for (int f = 0; f < 4; f++) ldsm4t(a + 4 * f, base + 4352u + offA + f * 32);
#pragma unroll
        for (int f = 0; f < 4; f++)
#pragma unroll
            for (int g = 0; g < 4; g++)
                mma_bf16(c[f][g], a + 4 * f, bh + 2 * g);

        if (lkt < 287) {   // STS to other buffer (before epilogue; sync after)
            int nb = buf ^ 1;
            unsigned h0,h1,l0,l1;
            unsigned* pAh = &smq[nb][0][kr][mc >> 1];
            unsigned* pAl = &smq[nb][1][kr][mc >> 1];
            unsigned* pBh = &smq[nb][2][kr][mc >> 1];
            unsigned* pBl = &smq[nb][3][kr][mc >> 1];
            cvt_hl(a0g,h0,h1,l0,l1); pAh[0]=h0; pAh[1]=h1; pAl[0]=l0; pAl[1]=l1;
            cvt_hl(a1g,h0,h1,l0,l1); pAh[2]=h0; pAh[3]=h1; pAl[2]=l0; pAl[3]=l1;
            cvt_hl(b0g,h0,h1,l0,l1); pBh[0]=h0; pBh[1]=h1; pBl[0]=l0; pBl[1]=l1;
            cvt_hl(b1g,h0,h1,l0,l1); pBh[2]=h0; pBh[3]=h1; pBl[2]=l0; pBl[3]=l1;
        }

        if ((lkt & 31) == 31) {   // level epilogue: scale, relu, L2-resident RMW; reset c
            const float* iq = g_invq + (l * BB + b) * HW + m0;
            const float* is = g_invs + (l * BB + b) * HW + n0;
#pragma unroll
            for (int f = 0; f < 4; f++) {
                int r0 = wm + f * 16 + (lane >> 2), r1 = r0 + 8;
                float q0 = iq[r0], q1 = iq[r1];
#pragma unroll
                for (int g = 0; g < 4; g++) {
                    int cb = wn + g * 8 + (lane & 3) * 2;
                    float s0 = is[cb], s1 = is[cb + 1];
                    float v00 = fmaxf(c[f][g][0] * q0 * s0, 0.f);
                    float v01 = fmaxf(c[f][g][1] * q0 * s1, 0.f);
                    float v10 = fmaxf(c[f][g][2] * q1 * s0, 0.f);
                    float v11 = fmaxf(c[f][g][3] * q1 * s1, 0.f);
                    float2* p0 = (float2*)(outp + (size_t)r0 * HW + cb);
                    float2* p1 = (float2*)(outp + (size_t)r1 * HW + cb);
                    if (l == 0) {
                        *p0 = make_float2(v00, v01);
                        *p1 = make_float2(v10, v11);
                    } else {
                        float2 o0 = *p0, o1 = *p1;
                        o0.x += v00; o0.y += v01; o1.x += v10; o1.y += v11;
                        *p0 = o0; *p1 = o1;
                    }
                    c[f][g][0]=0.f; c[f][g][1]=0.f; c[f][g][2]=0.f; c[f][g][3]=0.f;
                }
            }
        }

        if (lkt < 287) {
            __syncthreads();
            buf ^= 1;
        }
    }
}

// ---------------- row softmax (scale = TEMP/L folds the mean) ----------------
__global__ void k_softmax() {
    float* r = g_corr + (size_t)blockIdx.x * HW;      // blockIdx.x = b*1024 + q
    int tid = threadIdx.x, wid = tid >> 5, lane = tid & 31;
    const float sc = 20.0f / 9.0f;
    float4 v = ((const float4*)r)[tid];
    v.x *= sc; v.y *= sc; v.z *= sc; v.w *= sc;
    float mx = fmaxf(fmaxf(v.x, v.y), fmaxf(v.z, v.w));
#pragma unroll
    for (int o = 16; o; o >>= 1) mx = fmaxf(mx, __shfl_xor_sync(0xffffffffu, mx, o));
    __shared__ float sh[8];
    if (lane == 0) sh[wid] = mx;
    __syncthreads();
    float m = sh[0];
#pragma unroll
    for (int k = 1; k < 8; k++) m = fmaxf(m, sh[k]);
    v.x = __expf(v.x - m); v.y = __expf(v.y - m);
    v.z = __expf(v.z - m); v.w = __expf(v.w - m);
    float s = v.x + v.y + v.z + v.w;
#pragma unroll
    for (int o = 16; o; o >>= 1) s += __shfl_xor_sync(0xffffffffu, s, o);
    __syncthreads();
    if (lane == 0) sh[wid] = s;
    __syncthreads();
    float tot = 0.f;
#pragma unroll
    for (int k = 0; k < 8; k++) tot += sh[k];
    float inv = 1.0f / tot;
    v.x *= inv; v.y *= inv; v.z *= inv; v.w *= inv;
    ((float4*)r)[tid] = v;
}

// ---------------- k_att: bf16-split MMA, K-split by 2 (half = z&1) ----------------
__global__ void __launch_bounds__(256, 2) k_att(const float* __restrict__ fs_in) {
    __shared__ __align__(16) uint4 smA[2][2][2][128];   // [buf][hl][kb][row]
    __shared__ __align__(16) uint4 smB[2][2][2][128];
    int b = blockIdx.z >> 1, half = blockIdx.z & 1;
    int m0 = blockIdx.y * 128, n0 = blockIdx.x * 128;
    int tid = threadIdx.x, lane = tid & 31, wid = tid >> 5;
    int wm = (wid >> 2) * 64, wn = (wid & 3) * 32;
    int lrow = tid >> 1, lkb = tid & 1;

    const float* Ag = fs_in + (size_t)b * CC * HW + (size_t)m0 * HW + half * 512;
    const float* Bg = g_corr + (size_t)b * HW * HW + (size_t)n0 * HW + half * 512;

    int rsel = ((lane >> 3) & 1) * 8 + (lane & 7);
    int kbsel = lane >> 4;
    unsigned baseA = (unsigned)__cvta_generic_to_shared(&smA[0][0][0][0]);
    unsigned baseB = (unsigned)__cvta_generic_to_shared(&smB[0][0][0][0]);
    unsigned offA = (unsigned)(kbsel * 2048 + (wm + rsel) * 16);     // + f*256
    unsigned offB = (unsigned)(kbsel * 2048 + (wn + rsel) * 16);     // + gg*256

    float c[4][4][4];
#pragma unroll
    for (int f = 0; f < 4; f++)
#pragma unroll
        for (int g = 0; g < 4; g++) { c[f][g][0]=0.f; c[f][g][1]=0.f; c[f][g][2]=0.f; c[f][g][3]=0.f; }

    {   // prologue: k-tile 0
        float4 a0g = *(const float4*)(Ag + (size_t)lrow * HW + lkb * 8);
        float4 a1g = *(const float4*)(Ag + (size_t)lrow * HW + lkb * 8 + 4);
        float4 b0g = *(const float4*)(Bg + (size_t)lrow * HW + lkb * 8);
        float4 b1g = *(const float4*)(Bg + (size_t)lrow * HW + lkb * 8 + 4);
        unsigned h0,h1,l0,l1,h2,h3,l2,l3;
        cvt_hl(a0g,h0,h1,l0,l1); cvt_hl(a1g,h2,h3,l2,l3);
        smA[0][0][lkb][lrow] = make_uint4(h0,h1,h2,h3);
        smA[0][1][lkb][lrow] = make_uint4(l0,l1,l2,l3);
        cvt_hl(b0g,h0,h1,l0,l1); cvt_hl(b1g,h2,h3,l2,l3);
        smB[0][0][lkb][lrow] = make_uint4(h0,h1,h2,h3);
        smB[0][1][lkb][lrow] = make_uint4(l0,l1,l2,l3);
    }
    __syncthreads();

    int buf = 0;
    for (int kt = 0; kt < 32; kt++) {
        float4 a0g, a1g, b0g, b1g;
        if (kt < 31) {
            int k0 = (kt + 1) * 16 + lkb * 8;
            a0g = *(const float4*)(Ag + (size_t)lrow * HW + k0);
            a1g = *(const float4*)(Ag + (size_t)lrow * HW + k0 + 4);
            b0g = *(const float4*)(Bg + (size_t)lrow * HW + k0);
            b1g = *(const float4*)(Bg + (size_t)lrow * HW + k0 + 4);
        }
        unsigned bA = baseA + (unsigned)buf * 8192u;
        unsigned bB = baseB + (unsigned)buf * 8192u;
        unsigned a[16], bh[8], bl[8], t[4];
#pragma unroll
        for (int f = 0; f < 4; f++) ldsm4(a + 4 * f, bA + offA + f * 256);
#pragma unroll
        for (int gg = 0; gg < 2; gg++) {
            ldsm4(t, bB + offB + gg * 256);
            bh[gg*4+0]=t[0]; bh[gg*4+1]=t[2]; bh[gg*4+2]=t[1]; bh[gg*4+3]=t[3];
        }
#pragma unroll
        for (int gg = 0; gg < 2; gg++) {
            ldsm4(t, bB + 4096u + offB + gg * 256);
            bl[gg*4+0]=t[0]; bl[gg*4+1]=t[2]; bl[gg*4+2]=t[1]; bl[gg*4+3]=t[3];
        }
#pragma unroll
        for (int f = 0; f < 4; f++)
#pragma unroll
            for (int g = 0; g < 4; g++) {
                mma_bf16(c[f][g], a + 4 * f, bh + 2 * g);
                mma_bf16(c[f][g], a + 4 * f, bl + 2 * g);
            }
#pragma unroll
        for (int f = 0; f < 4; f++) ldsm4(a + 4 * f, bA + 4096u + offA + f * 256);
#pragma unroll
        for (int f = 0; f < 4; f++)
#pragma unroll
            for (int g = 0; g < 4; g++)
                mma_bf16(c[f][g], a + 4 * f, bh + 2 * g);

        if (kt < 31) {
            int nb = buf ^ 1;
            unsigned h0,h1,l0,l1,h2,h3,l2,l3;
            cvt_hl(a0g,h0,h1,l0,l1); cvt_hl(a1g,h2,h3,l2,l3);
            smA[nb][0][lkb][lrow] = make_uint4(h0,h1,h2,h3);
            smA[nb][1][lkb][lrow] = make_uint4(l0,l1,l2,l3);
            cvt_hl(b0g,h0,h1,l0,l1); cvt_hl(b1g,h2,h3,l2,l3);
            smB[nb][0][lkb][lrow] = make_uint4(h0,h1,h2,h3);
            smB[nb][1][lkb][lrow] = make_uint4(l0,l1,l2,l3);
            __syncthreads();
            buf = nb;
        }
    }

    float* outp = (half ? g_attpb : g_attpa) + (size_t)b * CC * HW + (size_t)m0 * HW + n0;
#pragma unroll
    for (int f = 0; f < 4; f++) {
        int r0 = wm + f * 16 + (lane >> 2), r1 = r0 + 8;
#pragma unroll
        for (int g = 0; g < 4; g++) {
            int cb = wn + g * 8 + (lane & 3) * 2;
            *(float2*)(outp + (size_t)r0 * HW + cb) = make_float2(c[f][g][0], c[f][g][1]);
            *(float2*)(outp + (size_t)r1 * HW + cb) = make_float2(c[f][g][2], c[f][g][3]);
        }
    }
}

// att_out = pa + pb
__global__ void k_attcomb(float* __restrict__ attout) {
    int i4 = blockIdx.x * 256 + threadIdx.x;          // < 524288
    float4 a = ((const float4*)g_attpa)[i4];
    float4 bb = ((const float4*)g_attpb)[i4];
    ((float4*)attout)[i4] = make_float4(a.x + bb.x, a.y + bb.y, a.z + bb.z, a.w + bb.w);
}

// ---------------- inverse channel norms of f_q and att_fq ----------------
__global__ void k_norm2(const float* __restrict__ f_q, const float* __restrict__ att) {
    int b   = blockIdx.y;
    int pix = blockIdx.x * 256 + threadIdx.x;
    const float* src = (blockIdx.z == 0 ? f_q : att) + (size_t)b * CC * HW + pix;
    float ss = 0.f;
#pragma unroll 8
    for (int c = 0; c < CC; c++) { float v = src[(size_t)c * HW]; ss = fmaf(v, v, ss); }
    float inv = 1.0f / fmaxf(sqrtf(ss), 1e-12f);
    (blockIdx.z == 0 ? g_nq2 : g_na2)[b * HW + pix] = inv;
}

// ---------------- fq = l2n(f_q) + 0.5*l2n(att_fq) ----------------
__global__ void k_fqout(const float* __restrict__ f_q, const float* __restrict__ att,
                        float* __restrict__ fqo) {
    int i4 = blockIdx.x * 256 + threadIdx.x;          // < 524288
    int base = i4 * 4;
    int b = base >> 19;
    int pix = base & 1023;
    float4 q = ((const float4*)f_q)[i4];
    float4 a = ((const float4*)att)[i4];
    int ni = (b * HW + pix) >> 2;
    float4 nq = ((const float4*)g_nq2)[ni];
    float4 na = ((const float4*)g_na2)[ni];
    float4 o;
    o.x = q.x * nq.x + a.x * na.x * 0.5f;
    o.y = q.y * nq.y + a.y * na.y * 0.5f;
    o.z = q.z * nq.z + a.z * na.z * 0.5f;
    o.w = q.w * nq.w + a.w * na.w * 0.5f;
    ((float4*)fqo)[i4] = o;
}

// ---------------- conv1: bf16-split tensor implicit GEMM, K-split by 2 ----------------
__global__ void __launch_bounds__(256, 2) k_conv1(const float* __restrict__ f_q,
                                                  const float* __restrict__ f_s) {
    __shared__ __align__(16) unsigned smW[2][2][16][36];  // [buf][hi/lo][k][oc72h]
    __shared__ __align__(16) unsigned smI[2][2][16][68];  // [buf][hi/lo][k][pix136h]
    int b = blockIdx.z >> 1, half = blockIdx.z & 1;
    int oc0 = blockIdx.y * 64, pix0 = blockIdx.x * 128;
    int tid = threadIdx.x, lane = tid & 31, wid = tid >> 5;
    int wm = (wid >> 2) * 32, wn = (wid & 3) * 32;
    int kr = tid >> 4, mc = (tid & 15) * 8;

    int kA = (lane & 7) + ((lane >> 4) << 3);
    int cA = ((lane >> 3) & 1) << 3;
    int kB = (lane & 7) + (((lane >> 3) & 1) << 3);
    int cB = (lane >> 4) << 3;
    unsigned baseW = (unsigned)__cvta_generic_to_shared(&smW[0][0][0][0]);
    unsigned baseI = (unsigned)__cvta_generic_to_shared(&smI[0][0][0][0]);
    unsigned offA = (unsigned)(kA * 144 + (cA + wm) * 2);
    unsigned offB = (unsigned)(kB * 272 + (cB + wn) * 2);

    const float* fqp = f_q + (size_t)b * CC * HW;
    const float* fsp = f_s + (size_t)b * CC * HW;

    int pp0 = pix0 + mc;
    int py = pp0 >> 5, px0v = pp0 & 31;
    int wtt = (tid & 127);
    int wrow = wtt >> 3, wcol8 = (wtt & 7) * 8;
    bool whalf = (tid < 128);
    int kbase = half * 288;                           // global k-tile base

    float c[2][4][4];
#pragma unroll
    for (int f = 0; f < 2; f++)
#pragma unroll
        for (int g = 0; g < 4; g++) { c[f][g][0]=0.f; c[f][g][1]=0.f; c[f][g][2]=0.f; c[f][g][3]=0.f; }

    {   // prologue: global k-tile kbase
        int tap = kbase >> 6, ict = kbase & 63;
        int dy = 2 * (tap / 3) - 2, dx = 2 * (tap % 3) - 2;
        uint4 wv;
        const __nv_bfloat16* wsrc = whalf ? g_wt1h : g_wt1l;
        wv = *(const uint4*)(wsrc + (size_t)(tap * 1024 + ict * 16 + wrow) * 256 + oc0 + wcol8);
        float v[8];
        int ic = ict * 16 + kr;
        const float* src = (ic < 512 ? fqp + (size_t)ic * HW
                                     : fsp + (size_t)(ic - 512) * HW);
        int iy = py + dy;
        bool yok = ((unsigned)iy < 32u);
        const float* rowp = src + iy * 32;
#pragma unroll
        for (int j = 0; j < 8; j++) {
            int ix = px0v + j + dx;
            v[j] = (yok && ((unsigned)ix < 32u)) ? rowp[ix] : 0.f;
        }
        *(uint4*)&smW[0][whalf ? 0 : 1][wrow][wcol8 >> 1] = wv;
        unsigned h0,h1,l0,l1;
        unsigned* pIh = &smI[0][0][kr][mc >> 1];
        unsigned* pIl = &smI[0][1][kr][mc >> 1];
        float4 fa = make_float4(v[0], v[1], v[2], v[3]);
        float4 fb = make_float4(v[4], v[5], v[6], v[7]);
        cvt_hl(fa,h0,h1,l0,l1); pIh[0]=h0; pIh[1]=h1; pIl[0]=l0; pIl[1]=l1;
        cvt_hl(fb,h0,h1,l0,l1); pIh[2]=h0; pIh[3]=h1; pIl[2]=l0; pIl[3]=l1;
    }
    __syncthreads();

    int buf = 0;
    for (int kt = 0; kt < 288; kt++) {
        uint4 wv; float v[8];
        if (kt < 287) {
            int kn = kbase + kt + 1;
            int tap = kn >> 6, ict = kn & 63;
            int dy = 2 * (tap / 3) - 2, dx = 2 * (tap % 3) - 2;
            const __nv_bfloat16* wsrc = whalf ? g_wt1h : g_wt1l;
            wv = *(const uint4*)(wsrc + (size_t)(tap * 1024 + ict * 16 + wrow) * 256 + oc0 + wcol8);
            int ic = ict * 16 + kr;
            const float* src = (ic < 512 ? fqp + (size_t)ic * HW
                                         : fsp + (size_t)(ic - 512) * HW);
            int iy = py + dy;
            bool yok = ((unsigned)iy < 32u);
            const float* rowp = src + iy * 32;
#pragma unroll
            for (int j = 0; j < 8; j++) {
                int ix = px0v + j + dx;
                v[j] = (yok && ((unsigned)ix < 32u)) ? rowp[ix] : 0.f;
            }
        }
        unsigned bW = baseW + (unsigned)buf * 4608u;
        unsigned bI = baseI + (unsigned)buf * 8704u;
        unsigned a[8], al[8], bh[8], bl[8];
#pragma unroll
        for (int f = 0; f < 2; f++) ldsm4t(a  + 4 * f, bW + offA + f * 32);
#pragma unroll
        for (int f = 0; f < 2; f++) ldsm4t(al + 4 * f, bW + 2304u + offA + f * 32);
#pragma unroll
        for (int g2 = 0; g2 < 2; g2++) ldsm4t(bh + 4 * g2, bI + offB + g2 * 32);
#pragma unroll
        for (int g2 = 0; g2 < 2; g2++) ldsm4t(bl + 4 * g2, bI + 4352u + offB + g2 * 32);
#pragma unroll
        for (int f = 0; f < 2; f++)
#pragma unroll
            for (int g = 0; g < 4; g++) {
                mma_bf16(c[f][g], a  + 4 * f, bh + 2 * g);
                mma_bf16(c[f][g], a  + 4 * f, bl + 2 * g);
                mma_bf16(c[f][g], al + 4 * f, bh + 2 * g);
            }
        if (kt < 287) {
            int nb = buf ^ 1;
            *(uint4*)&smW[nb][whalf ? 0 : 1][wrow][wcol8 >> 1] = wv;
            unsigned h0,h1,l0,l1;
            unsigned* pIh = &smI[nb][0][kr][mc >> 1];
            unsigned* pIl = &smI[nb][1][kr][mc >> 1];
            float4 fa = make_float4(v[0], v[1], v[2], v[3]);
            float4 fb = make_float4(v[4], v[5], v[6], v[7]);
            cvt_hl(fa,h0,h1,l0,l1); pIh[0]=h0; pIh[1]=h1; pIl[0]=l0; pIl[1]=l1;
            cvt_hl(fb,h0,h1,l0,l1); pIh[2]=h0; pIh[3]=h1; pIl[2]=l0; pIl[3]=l1;
            __syncthreads();
            buf = nb;
        }
    }

    float* outp = (half ? g_c1pb : g_c1pa) + (size_t)b * 262144;
#pragma unroll
    for (int f = 0; f < 2; f++) {
        int r0 = wm + f * 16 + (lane >> 2), r1 = r0 + 8;
#pragma unroll
        for (int g = 0; g < 4; g++) {
            int cb = wn + g * 8 + (lane & 3) * 2;
            *(float2*)(outp + (size_t)(oc0 + r0) * HW + pix0 + cb) =
                make_float2(c[f][g][0], c[f][g][1]);
            *(float2*)(outp + (size_t)(oc0 + r1) * HW + pix0 + cb) =
                make_float2(c[f][g][2], c[f][g][3]);
        }
    }
}

// c1 = relu(pa + pb + bias)
__global__ void k_c1comb(const float* __restrict__ b1) {
    int i4 = blockIdx.x * 256 + threadIdx.x;          // < 262144
    float4 a = ((const float4*)g_c1pa)[i4];
    float4 bb = ((const float4*)g_c1pb)[i4];
    int oc = (i4 & 65535) >> 8;                       // per-b block: 65536 f4, 256 f4 per oc
    float bias = b1[oc];
    float4 o;
    o.x = fmaxf(a.x + bb.x + bias, 0.f);
    o.y = fmaxf(a.y + bb.y + bias, 0.f);
    o.z = fmaxf(a.z + bb.z + bias, 0.f);
    o.w = fmaxf(a.w + bb.w + bias, 0.f);
    ((float4*)g_c1)[i4] = o;
}

// ---------------- conv2: bf16-split tensor implicit GEMM (unsplit, bias epilogue) ----------------
__global__ void __launch_bounds__(256, 2) k_conv2(const float* __restrict__ b2) {
    __shared__ __align__(16) unsigned smW[2][2][16][36];
    __shared__ __align__(16) unsigned smI[2][2][16][68];
    int b = blockIdx.z, oc0 = blockIdx.y * 64, pix0 = blockIdx.x * 128;
    int tid = threadIdx.x, lane = tid & 31, wid = tid >> 5;
    int wm = (wid >> 2) * 32, wn = (wid & 3) * 32;
    int kr = tid >> 4, mc = (tid & 15) * 8;

    int kA = (lane & 7) + ((lane >> 4) << 3);
    int cA = ((lane >> 3) & 1) << 3;
    int kB = (lane & 7) + (((lane >> 3) & 1) << 3);
    int cB = (lane >> 4) << 3;
    unsigned baseW = (unsigned)__cvta_generic_to_shared(&smW[0][0][0][0]);
    unsigned baseI = (unsigned)__cvta_generic_to_shared(&smI[0][0][0][0]);
    unsigned offA = (unsigned)(kA * 144 + (cA + wm) * 2);
    unsigned offB = (unsigned)(kB * 272 + (cB + wn) * 2);

    const float* c1p = g_c1 + (size_t)b * 262144;

    int offp[8];
#pragma unroll
    for (int j = 0; j < 8; j++) {
        int p = pix0 + mc + j; if (p > 899) p = 899;
        offp[j] = (p / 30) * 32 + (p % 30);
    }
    int wtt = (tid & 127);
    int wrow = wtt >> 3, wcol8 = (wtt & 7) * 8;
    bool whalf = (tid < 128);

    float c[2][4][4];
#pragma unroll
    for (int f = 0; f < 2; f++)
#pragma unroll
        for (int g = 0; g < 4; g++) { c[f][g][0]=0.f; c[f][g][1]=0.f; c[f][g][2]=0.f; c[f][g][3]=0.f; }

    {   // prologue kt=0: tap 0 (dy=0,dx=0), ict 0
        uint4 wv;
        const __nv_bfloat16* wsrc = whalf ? g_wt2h : g_wt2l;
        wv = *(const uint4*)(wsrc + (size_t)wrow * 256 + oc0 + wcol8);
        float v[8];
        const float* src = c1p + (size_t)kr * HW;
#pragma unroll
        for (int j = 0; j < 8; j++) v[j] = src[offp[j]];
        *(uint4*)&smW[0][whalf ? 0 : 1][wrow][wcol8 >> 1] = wv;
        unsigned h0,h1,l0,l1;
        unsigned* pIh = &smI[0][0][kr][mc >> 1];
        unsigned* pIl = &smI[0][1][kr][mc >> 1];
        float4 fa = make_float4(v[0], v[1], v[2], v[3]);
        float4 fb = make_float4(v[4], v[5], v[6], v[7]);
        cvt_hl(fa,h0,h1,l0,l1); pIh[0]=h0; pIh[1]=h1; pIl[0]=l0; pIl[1]=l1;
        cvt_hl(fb,h0,h1,l0,l1); pIh[2]=h0; pIh[3]=h1; pIl[2]=l0; pIl[3]=l1;
    }
    __syncthreads();

    int buf = 0;
    for (int kt = 0; kt < 144; kt++) {
        uint4 wv; float v[8];
        if (kt < 143) {
            int kn = kt + 1;
            int tap = kn >> 4, ict = kn & 15;
            int doff = (tap / 3) * 32 + (tap % 3);
            const __nv_bfloat16* wsrc = whalf ? g_wt2h : g_wt2l;
            wv = *(const uint4*)(wsrc + (size_t)(tap * 256 + ict * 16 + wrow) * 256 + oc0 + wcol8);
            const float* src = c1p + (size_t)(ict * 16 + kr) * HW;
#pragma unroll
            for (int j = 0; j < 8; j++) v[j] = src[offp[j] + doff];
        }
        unsigned bW = baseW + (unsigned)buf * 4608u;
        unsigned bI = baseI + (unsigned)buf * 8704u;
        unsigned a[8], al[8], bh[8], bl[8];
#pragma unroll
        for (int f = 0; f < 2; f++) ldsm4t(a  + 4 * f, bW + offA + f * 32);
#pragma unroll
        for (int f = 0; f < 2; f++) ldsm4t(al + 4 * f, bW + 2304u + offA + f * 32);
#pragma unroll
        for (int g2 = 0; g2 < 2; g2++) ldsm4t(bh + 4 * g2, bI + offB + g2 * 32);
#pragma unroll
        for (int g2 = 0; g2 < 2; g2++) ldsm4t(bl + 4 * g2, bI + 4352u + offB + g2 * 32);
#pragma unroll
        for (int f = 0; f < 2; f++)
#pragma unroll
            for (int g = 0; g < 4; g++) {
                mma_bf16(c[f][g], a  + 4 * f, bh + 2 * g);
                mma_bf16(c[f][g], a  + 4 * f, bl + 2 * g);
                mma_bf16(c[f][g], al + 4 * f, bh + 2 * g);
            }
        if (kt < 143) {
            int nb = buf ^ 1;
            *(uint4*)&smW[nb][whalf ? 0 : 1][wrow][wcol8 >> 1] = wv;
            unsigned h0,h1,l0,l1;
            unsigned* pIh = &smI[nb][0][kr][mc >> 1];
            unsigned* pIl = &smI[nb][1][kr][mc >> 1];
            float4 fa = make_float4(v[0], v[1], v[2], v[3]);
            float4 fb = make_float4(v[4], v[5], v[6], v[7]);
            cvt_hl(fa,h0,h1,l0,l1); pIh[0]=h0; pIh[1]=h1; pIl[0]=l0; pIl[1]=l1;
            cvt_hl(fb,h0,h1,l0,l1); pIh[2]=h0; pIh[3]=h1; pIl[2]=l0; pIl[3]=l1;
            __syncthreads();
            buf = nb;
        }
    }

    float* outp = g_c2 + (size_t)b * 230400;
#pragma unroll
    for (int f = 0; f < 2; f++) {
        int r0 = wm + f * 16 + (lane >> 2), r1 = r0 + 8;
        float bias0 = b2[oc0 + r0], bias1 = b2[oc0 + r1];
#pragma unroll
        for (int g = 0; g < 4; g++) {
            int cb = wn + g * 8 + (lane & 3) * 2;
            int p0 = pix0 + cb;                // even; p0<900 => p0+1<=899
            if (p0 < 900) {
                *(float2*)(outp + (size_t)(oc0 + r0) * 900 + p0) =
                    make_float2(c[f][g][0] + bias0, c[f][g][1] + bias0);
                *(float2*)(outp + (size_t)(oc0 + r1) * 900 + p0) =
                    make_float2(c[f][g][2] + bias1, c[f][g][3] + bias1);
            }
        }
    }
}

// ---------------- 3x3 stride-3 maxpool: 30x30 -> 10x10 ----------------
__global__ void k_pool() {
    int oc = blockIdx.x, b = blockIdx.y;
    int t = threadIdx.x;
    if (t >= 100) return;
    int y = t / 10, x = t % 10;
    const float* in = g_c2 + ((size_t)b * 256 + oc) * 900;
    float m = -3.4e38f;
#pragma unroll
    for (int dy = 0; dy < 3; dy++)
#pragma unroll
        for (int dx = 0; dx < 3; dx++)
            m = fmaxf(m, in[(3 * y + dy) * 30 + 3 * x + dx]);
    g_pool[((size_t)b * 256 + oc) * 100 + t] = m;
}

// ---------------- conv3 (3x3 VALID, 10x10 -> 8x8) + mean -> weight[b] ----------------
__global__ void k_conv3(const float* __restrict__ w3, const float* __restrict__ b3,
                        float* __restrict__ wout) {
    int b = blockIdx.x;
    int tid = threadIdx.x;
    int o = tid >> 2, part = tid & 3;
    int oy = o >> 3, ox = o & 7;
    float s = 0.f;
    for (int ic = part * 64; ic < part * 64 + 64; ic++) {
        const float* pp = g_pool + ((size_t)b * 256 + ic) * 100 + oy * 10 + ox;
        const float* wp = w3 + ic * 9;
#pragma unroll
        for (int ky = 0; ky < 3; ky++)
#pragma unroll
            for (int kx = 0; kx < 3; kx++)
                s = fmaf(pp[ky * 10 + kx], wp[ky * 3 + kx], s);
    }
    s += __shfl_down_sync(0xffffffffu, s, 1);
    s += __shfl_down_sync(0xffffffffu, s, 2);
    __shared__ float sh[64];
    if (part == 0) sh[o] = s;
    __syncthreads();
    if (tid < 32) {
        float v = sh[tid] + sh[tid + 32];
#pragma unroll
        for (int off = 16; off; off >>= 1) v += __shfl_xor_sync(0xffffffffu, v, off);
        if (tid == 0) wout[b] = v * (1.0f / 64.0f) + b3[0];
    }
}

// ---------------- launch ----------------
extern "C" void kernel_launch(void* const* d_in, const int* in_sizes, int n_in,
                              void* d_out, int out_size) {
    const float* fq_feats = (const float*)d_in[0];
    const float* fs_feats = (const float*)d_in[1];
    const float* f_q = (const float*)d_in[2];
    const float* f_s = (const float*)d_in[3];
    const float* w1 = (const float*)d_in[4];
    const float* b1 = (const float*)d_in[5];
    const float* w2 = (const float*)d_in[6];
    const float* b2 = (const float*)d_in[7];
    const float* w3 = (const float*)d_in[8];
    const float* b3 = (const float*)d_in[9];

    float* out     = (float*)d_out;
    float* fq_out  = out;                       // [4,512,32,32]
    float* att_out = out + 2097152;             // [4,512,32,32]
    float* w_out   = out + 4194304;             // [1,4]

    k_twt1<<<9216, 256>>>(w1);
    k_twt2<<<2304, 256>>>(w2);
    k_norms<<<dim3(4, 36, 2), 256>>>(fq_feats, fs_feats);
    k_corr<<<dim3(8, 8, 4), 256>>>(fq_feats, fs_feats);
    k_softmax<<<4096, 256>>>();
    k_att<<<dim3(8, 4, 8), 256>>>(f_s);
    k_attcomb<<<2048, 256>>>(att_out);
    k_norm2<<<dim3(4, 4, 2), 256>>>(f_q, att_out);
    k_fqout<<<2048, 256>>>(f_q, att_out, fq_out);
    k_conv1<<<dim3(8, 4, 8), 256>>>(f_q, f_s);
    k_c1comb<<<1024, 256>>>(b1);
    k_conv2<<<dim3(8, 4, 4), 256>>>(b2);
    k_pool<<<dim3(256, 4), 128>>>();
    k_conv3<<<4, 256>>>(w3, b3, w_out);
}

// round 15
// speedup vs baseline: 1.1099x; 1.0486x over previous
#include <cuda_runtime.h>
#include <cuda_bf16.h>

#define LL 9
#define BB 4
#define CC 512
#define HW 1024

// ---------------- scratch (device globals; no allocation) ----------------
__device__ __align__(16) float g_invq[LL*BB*HW];
__device__ __align__(16) float g_invs[LL*BB*HW];
__device__ __align__(16) float g_corr[(size_t)BB*HW*HW];   // 16 MB, reused as attn
__device__ __align__(16) float g_c1[BB*256*HW];            // conv1 out [b][256][32*32]
__device__ __align__(16) float g_c1pa[BB*256*HW];          // conv1 K-split partials
__device__ __align__(16) float g_c1pb[BB*256*HW];
__device__ __align__(16) float g_attpa[BB*CC*HW];          // att K-split partials
__device__ __align__(16) float g_attpb[BB*CC*HW];
__device__ __align__(16) float g_c2pa[BB*256*900];         // conv2 K-split partials
__device__ __align__(16) float g_c2pb[BB*256*900];
__device__ __align__(16) float g_pool[BB*256*100];         // pooled [b][256][10*10]
__device__ __align__(16) __nv_bfloat16 g_wt1h[9*1024*256]; // w1 hi [tap][ic][oc]
__device__ __align__(16) __nv_bfloat16 g_wt1l[9*1024*256]; // w1 lo [tap][ic][oc]
__device__ __align__(16) __nv_bfloat16 g_wt2h[9*256*256];  // w2 hi [tap][ic][oc]
__device__ __align__(16) __nv_bfloat16 g_wt2l[9*256*256];  // w2 lo [tap][ic][oc]
__device__ __align__(16) float g_nq2[BB*HW];
__device__ __align__(16) float g_na2[BB*HW];

// ---------------- helpers ----------------
__device__ __forceinline__ void ldsm4t(unsigned* r, unsigned addr) {
    asm volatile("ldmatrix.sync.aligned.m8n8.x4.trans.shared.b16 {%0,%1,%2,%3}, [%4];\n"
        : "=r"(r[0]), "=r"(r[1]), "=r"(r[2]), "=r"(r[3]) : "r"(addr));
}
__device__ __forceinline__ void ldsm4(unsigned* r, unsigned addr) {
    asm volatile("ldmatrix.sync.aligned.m8n8.x4.shared.b16 {%0,%1,%2,%3}, [%4];\n"
        : "=r"(r[0]), "=r"(r[1]), "=r"(r[2]), "=r"(r[3]) : "r"(addr));
}
__device__ __forceinline__ void mma_bf16(float* c, const unsigned* a, const unsigned* b) {
    asm volatile(
        "mma.sync.aligned.m16n8k16.row.col.f32.bf16.bf16.f32 "
        "{%0,%1,%2,%3}, {%4,%5,%6,%7}, {%8,%9}, {%0,%1,%2,%3};\n"
        : "+f"(c[0]), "+f"(c[1]), "+f"(c[2]), "+f"(c[3])
        : "r"(a[0]), "r"(a[1]), "r"(a[2]), "r"(a[3]), "r"(b[0]), "r"(b[1]));
}
// split float4 -> hi bf16x2 pair + lo bf16x2 pair (packed as unsigned)
__device__ __forceinline__ void cvt_hl(float4 v, unsigned& h0, unsigned& h1,
                                       unsigned& l0, unsigned& l1) {
    __nv_bfloat162 H0 = __floats2bfloat162_rn(v.x, v.y);
    __nv_bfloat162 H1 = __floats2bfloat162_rn(v.z, v.w);
    __nv_bfloat162 L0 = __floats2bfloat162_rn(v.x - __bfloat162float(H0.x),
                                              v.y - __bfloat162float(H0.y));
    __nv_bfloat162 L1 = __floats2bfloat162_rn(v.z - __bfloat162float(H1.x),
                                              v.w - __bfloat162float(H1.y));
    h0 = *(unsigned*)&H0; h1 = *(unsigned*)&H1;
    l0 = *(unsigned*)&L0; l1 = *(unsigned*)&L1;
}

// ---------------- weight prep ----------------
__global__ void k_twt1(const float* __restrict__ w1) {
    int i = blockIdx.x * 256 + threadIdx.x;          // < 2359296
    float v = w1[i];
    int oc = i / 9216; int r = i % 9216; int ic = r / 9; int tap = r % 9;
    __nv_bfloat16 h = __float2bfloat16(v);
    __nv_bfloat16 lo = __float2bfloat16(v - __bfloat162float(h));
    int o = tap * 262144 + ic * 256 + oc;
    g_wt1h[o] = h; g_wt1l[o] = lo;
}
__global__ void k_twt2(const float* __restrict__ w2) {
    int i = blockIdx.x * 256 + threadIdx.x;          // < 589824
    float v = w2[i];
    int oc = i / 2304; int r = i % 2304; int ic = r / 9; int tap = r % 9;
    __nv_bfloat16 h = __float2bfloat16(v);
    __nv_bfloat16 lo = __float2bfloat16(v - __bfloat162float(h));
    int o = tap * 65536 + ic * 256 + oc;
    g_wt2h[o] = h; g_wt2l[o] = lo;
}

// ---------------- per-level per-pixel inverse channel norms ----------------
__global__ void k_norms(const float* __restrict__ fq, const float* __restrict__ fs) {
    int lb  = blockIdx.y;                             // 0..35 (l*B+b)
    int pix = blockIdx.x * 256 + threadIdx.x;         // 0..1023
    const float* src = (blockIdx.z == 0 ? fq : fs) + (size_t)lb * CC * HW + pix;
    float ss = 0.f;
#pragma unroll 8
    for (int c = 0; c < CC; c++) { float v = src[(size_t)c * HW]; ss = fmaf(v, v, ss); }
    float inv = 1.0f / fmaxf(sqrtf(ss), 1e-12f);
    (blockIdx.z == 0 ? g_invq : g_invs)[lb * HW + pix] = inv;
}

// ---------------- corr: bf16-split tensor-core, cross-level pipelined ----------------
__global__ void __launch_bounds__(256, 2) k_corr(const float* __restrict__ fq,
                                                 const float* __restrict__ fs) {
    __shared__ __align__(16) unsigned smq[2][4][16][68];  // 68 u32 = 136 halves
    int b  = blockIdx.z;
    int m0 = blockIdx.y * 128, n0 = blockIdx.x * 128;
    int tid = threadIdx.x, lane = tid & 31, wid = tid >> 5;
    int wm = (wid >> 2) * 64, wn = (wid & 3) * 32;
    int kr = tid >> 4, mc = (tid & 15) * 8;           // loader: 16 k-rows x 8 floats

    int kA = (lane & 7) + ((lane >> 4) << 3);
    int cA = ((lane >> 3) & 1) << 3;
    int kB = (lane & 7) + (((lane >> 3) & 1) << 3);
    int cB = (lane >> 4) << 3;
    unsigned smbase = (unsigned)__cvta_generic_to_shared(&smq[0][0][0][0]);
    unsigned offA = (unsigned)(kA * 272 + (cA + wm) * 2);
    unsigned offB = (unsigned)(kB * 272 + (cB + wn) * 2);

    float* outp = g_corr + (size_t)b * HW * HW + (size_t)m0 * HW + n0;

    float c[4][4][4];
#pragma unroll
    for (int f = 0; f < 4; f++)
#pragma unroll
        for (int g = 0; g < 4; g++) { c[f][g][0]=0.f; c[f][g][1]=0.f; c[f][g][2]=0.f; c[f][g][3]=0.f; }

    {   // global prologue: (l=0, kt=0) -> buf 0
        const float* Ag = fq + (size_t)b * CC * HW + m0;
        const float* Bg = fs + (size_t)b * CC * HW + n0;
        float4 a0g = *(const float4*)(Ag + (size_t)kr * HW + mc);
        float4 a1g = *(const float4*)(Ag + (size_t)kr * HW + mc + 4);
        float4 b0g = *(const float4*)(Bg + (size_t)kr * HW + mc);
        float4 b1g = *(const float4*)(Bg + (size_t)kr * HW + mc + 4);
        unsigned h0,h1,l0,l1;
        unsigned* pAh = &smq[0][0][kr][mc >> 1];
        unsigned* pAl = &smq[0][1][kr][mc >> 1];
        unsigned* pBh = &smq[0][2][kr][mc >> 1];
        unsigned* pBl = &smq[0][3][kr][mc >> 1];
        cvt_hl(a0g,h0,h1,l0,l1); pAh[0]=h0; pAh[1]=h1; pAl[0]=l0; pAl[1]=l1;
        cvt_hl(a1g,h0,h1,l0,l1); pAh[2]=h0; pAh[3]=h1; pAl[2]=l0; pAl[3]=l1;
        cvt_hl(b0g,h0,h1,l0,l1); pBh[0]=h0; pBh[1]=h1; pBl[0]=l0; pBl[1]=l1;
        cvt_hl(b1g,h0,h1,l0,l1); pBh[2]=h0; pBh[3]=h1; pBl[2]=l0; pBl[3]=l1;
    }
    __syncthreads();

    int buf = 0;
    for (int lkt = 0; lkt < 288; lkt++) {
        int l = lkt >> 5;
        // prefetch lkt+1
        float4 a0g, a1g, b0g, b1g;
        if (lkt < 287) {
            int nk = lkt + 1;
            int l2 = nk >> 5, k2 = (nk & 31) * 16;
            const float* Ag = fq + (size_t)(l2 * BB + b) * CC * HW + m0;
            const float* Bg = fs + (size_t)(l2 * BB + b) * CC * HW + n0;
            a0g = *(const float4*)(Ag + (size_t)(k2 + kr) * HW + mc);
            a1g = *(const float4*)(Ag + (size_t)(k2 + kr) * HW + mc + 4);
            b0g = *(const float4*)(Bg + (size_t)(k2 + kr) * HW + mc);
            b1g = *(const float4*)(Bg + (size_t)(k2 + kr) * HW + mc + 4);
        }
        unsigned base = smbase + (unsigned)buf * 17408u;
        unsigned a[16], bh[8], bl[8];
#pragma unroll
        for (int f = 0; f < 4; f++) ldsm4t(a + 4 * f, base + offA + f * 32);
#pragma unroll
        for (int g2 = 0; g2 < 2; g2++) ldsm4t(bh + 4 * g2, base + 2u * 4352u + offB + g2 * 32);
#pragma unroll
        for (int g2 = 0; g2 < 2; g2++) ldsm4t(bl + 4 * g2, base + 3u * 4352u + offB + g2 * 32);
#pragma unroll
        for (int f = 0; f < 4; f++)
#pragma unroll
            for (int g = 0; g < 4; g++) {
                mma_bf16(c[f][g], a + 4 * f, bh + 2 * g);
                mma_bf16(c[f][g], a + 4 * f, bl + 2 * g);
            }
#pragma unroll
        for (int f = 0; f < 4; f++) ldsm4t(a + 4 * f, base + 4352u + offA + f * 32);
#pragma unroll
        for (int f = 0; f < 4; f++)
#pragma unroll
            for (int g = 0; g < 4; g++)
                mma_bf16(c[f][g], a + 4 * f, bh + 2 * g);

        if (lkt < 287) {   // STS to other buffer (before epilogue; sync after)
            int nb = buf ^ 1;
            unsigned h0,h1,l0,l1;
            unsigned* pAh = &smq[nb][0][kr][mc >> 1];
            unsigned* pAl = &smq[nb][1][kr][mc >> 1];
            unsigned* pBh = &smq[nb][2][kr][mc >> 1];
            unsigned* pBl = &smq[nb][3][kr][mc >> 1];
            cvt_hl(a0g,h0,h1,l0,l1); pAh[0]=h0; pAh[1]=h1; pAl[0]=l0; pAl[1]=l1;
            cvt_hl(a1g,h0,h1,l0,l1); pAh[2]=h0; pAh[3]=h1; pAl[2]=l0; pAl[3]=l1;
            cvt_hl(b0g,h0,h1,l0,l1); pBh[0]=h0; pBh[1]=h1; pBl[0]=l0; pBl[1]=l1;
            cvt_hl(b1g,h0,h1,l0,l1); pBh[2]=h0; pBh[3]=h1; pBl[2]=l0; pBl[3]=l1;
        }

        if ((lkt & 31) == 31) {   // level epilogue: scale, relu, L2-resident RMW; reset c
            const float* iq = g_invq + (l * BB + b) * HW + m0;
            const float* is = g_invs + (l * BB + b) * HW + n0;
#pragma unroll
            for (int f = 0; f < 4; f++) {
                int r0 = wm + f * 16 + (lane >> 2), r1 = r0 + 8;
                float q0 = iq[r0], q1 = iq[r1];
#pragma unroll
                for (int g = 0; g < 4; g++) {
                    int cb = wn + g * 8 + (lane & 3) * 2;
                    float s0 = is[cb], s1 = is[cb + 1];
                    float v00 = fmaxf(c[f][g][0] * q0 * s0, 0.f);
                    float v01 = fmaxf(c[f][g][1] * q0 * s1, 0.f);
                    float v10 = fmaxf(c[f][g][2] * q1 * s0, 0.f);
                    float v11 = fmaxf(c[f][g][3] * q1 * s1, 0.f);
                    float2* p0 = (float2*)(outp + (size_t)r0 * HW + cb);
                    float2* p1 = (float2*)(outp + (size_t)r1 * HW + cb);
                    if (l == 0) {
                        *p0 = make_float2(v00, v01);
                        *p1 = make_float2(v10, v11);
                    } else {
                        float2 o0 = *p0, o1 = *p1;
                        o0.x += v00; o0.y += v01; o1.x += v10; o1.y += v11;
                        *p0 = o0; *p1 = o1;
                    }
                    c[f][g][0]=0.f; c[f][g][1]=0.f; c[f][g][2]=0.f; c[f][g][3]=0.f;
                }
            }
        }

        if (lkt < 287) {
            __syncthreads();
            buf ^= 1;
        }
    }
}

// ---------------- row softmax (scale = TEMP/L folds the mean) ----------------
__global__ void k_softmax() {
    float* r = g_corr + (size_t)blockIdx.x * HW;      // blockIdx.x = b*1024 + q
    int tid = threadIdx.x, wid = tid >> 5, lane = tid & 31;
    const float sc = 20.0f / 9.0f;
    float4 v = ((const float4*)r)[tid];
    v.x *= sc; v.y *= sc; v.z *= sc; v.w *= sc;
    float mx = fmaxf(fmaxf(v.x, v.y), fmaxf(v.z, v.w));
#pragma unroll
    for (int o = 16; o; o >>= 1) mx = fmaxf(mx, __shfl_xor_sync(0xffffffffu, mx, o));
    __shared__ float sh[8];
    if (lane == 0) sh[wid] = mx;
    __syncthreads();
    float m = sh[0];
#pragma unroll
    for (int k = 1; k < 8; k++) m = fmaxf(m, sh[k]);
    v.x = __expf(v.x - m); v.y = __expf(v.y - m);
    v.z = __expf(v.z - m); v.w = __expf(v.w - m);
    float s = v.x + v.y + v.z + v.w;
#pragma unroll
    for (int o = 16; o; o >>= 1) s += __shfl_xor_sync(0xffffffffu, s, o);
    __syncthreads();
    if (lane == 0) sh[wid] = s;
    __syncthreads();
    float tot = 0.f;
#pragma unroll
    for (int k = 0; k < 8; k++) tot += sh[k];
    float inv = 1.0f / tot;
    v.x *= inv; v.y *= inv; v.z *= inv; v.w *= inv;
    ((float4*)r)[tid] = v;
}

// ---------------- k_att: bf16-split MMA, K-split by 2 (half = z&1) ----------------
__global__ void __launch_bounds__(256, 2) k_att(const float* __restrict__ fs_in) {
    __shared__ __align__(16) uint4 smA[2][2][2][128];   // [buf][hl][kb][row]
    __shared__ __align__(16) uint4 smB[2][2][2][128];
    int b = blockIdx.z >> 1, half = blockIdx.z & 1;
    int m0 = blockIdx.y * 128, n0 = blockIdx.x * 128;
    int tid = threadIdx.x, lane = tid & 31, wid = tid >> 5;
    int wm = (wid >> 2) * 64, wn = (wid & 3) * 32;
    int lrow = tid >> 1, lkb = tid & 1;

    const float* Ag = fs_in + (size_t)b * CC * HW + (size_t)m0 * HW + half * 512;
    const float* Bg = g_corr + (size_t)b * HW * HW + (size_t)n0 * HW + half * 512;

    int rsel = ((lane >> 3) & 1) * 8 + (lane & 7);
    int kbsel = lane >> 4;
    unsigned baseA = (unsigned)__cvta_generic_to_shared(&smA[0][0][0][0]);
    unsigned baseB = (unsigned)__cvta_generic_to_shared(&smB[0][0][0][0]);
    unsigned offA = (unsigned)(kbsel * 2048 + (wm + rsel) * 16);     // + f*256
    unsigned offB = (unsigned)(kbsel * 2048 + (wn + rsel) * 16);     // + gg*256

    float c[4][4][4];
#pragma unroll
    for (int f = 0; f < 4; f++)
#pragma unroll
        for (int g = 0; g < 4; g++) { c[f][g][0]=0.f; c[f][g][1]=0.f; c[f][g][2]=0.f; c[f][g][3]=0.f; }

    {   // prologue: k-tile 0
        float4 a0g = *(const float4*)(Ag + (size_t)lrow * HW + lkb * 8);
        float4 a1g = *(const float4*)(Ag + (size_t)lrow * HW + lkb * 8 + 4);
        float4 b0g = *(const float4*)(Bg + (size_t)lrow * HW + lkb * 8);
        float4 b1g = *(const float4*)(Bg + (size_t)lrow * HW + lkb * 8 + 4);
        unsigned h0,h1,l0,l1,h2,h3,l2,l3;
        cvt_hl(a0g,h0,h1,l0,l1); cvt_hl(a1g,h2,h3,l2,l3);
        smA[0][0][lkb][lrow] = make_uint4(h0,h1,h2,h3);
        smA[0][1][lkb][lrow] = make_uint4(l0,l1,l2,l3);
        cvt_hl(b0g,h0,h1,l0,l1); cvt_hl(b1g,h2,h3,l2,l3);
        smB[0][0][lkb][lrow] = make_uint4(h0,h1,h2,h3);
        smB[0][1][lkb][lrow] = make_uint4(l0,l1,l2,l3);
    }
    __syncthreads();

    int buf = 0;
    for (int kt = 0; kt < 32; kt++) {
        float4 a0g, a1g, b0g, b1g;
        if (kt < 31) {
            int k0 = (kt + 1) * 16 + lkb * 8;
            a0g = *(const float4*)(Ag + (size_t)lrow * HW + k0);
            a1g = *(const float4*)(Ag + (size_t)lrow * HW + k0 + 4);
            b0g = *(const float4*)(Bg + (size_t)lrow * HW + k0);
            b1g = *(const float4*)(Bg + (size_t)lrow * HW + k0 + 4);
        }
        unsigned bA = baseA + (unsigned)buf * 8192u;
        unsigned bB = baseB + (unsigned)buf * 8192u;
        unsigned a[16], bh[8], bl[8], t[4];
#pragma unroll
        for (int f = 0; f < 4; f++) ldsm4(a + 4 * f, bA + offA + f * 256);
#pragma unroll
        for (int gg = 0; gg < 2; gg++) {
            ldsm4(t, bB + offB + gg * 256);
            bh[gg*4+0]=t[0]; bh[gg*4+1]=t[2]; bh[gg*4+2]=t[1]; bh[gg*4+3]=t[3];
        }
#pragma unroll
        for (int gg = 0; gg < 2; gg++) {
            ldsm4(t, bB + 4096u + offB + gg * 256);
            bl[gg*4+0]=t[0]; bl[gg*4+1]=t[2]; bl[gg*4+2]=t[1]; bl[gg*4+3]=t[3];
        }
#pragma unroll
        for (int f = 0; f < 4; f++)
#pragma unroll
            for (int g = 0; g < 4; g++) {
                mma_bf16(c[f][g], a + 4 * f, bh + 2 * g);
                mma_bf16(c[f][g], a + 4 * f, bl + 2 * g);
            }
#pragma unroll
        for (int f = 0; f < 4; f++) ldsm4(a + 4 * f, bA + 4096u + offA + f * 256);
#pragma unroll
        for (int f = 0; f < 4; f++)
#pragma unroll
            for (int g = 0; g < 4; g++)
                mma_bf16(c[f][g], a + 4 * f, bh + 2 * g);

        if (kt < 31) {
            int nb = buf ^ 1;
            unsigned h0,h1,l0,l1,h2,h3,l2,l3;
            cvt_hl(a0g,h0,h1,l0,l1); cvt_hl(a1g,h2,h3,l2,l3);
            smA[nb][0][lkb][lrow] = make_uint4(h0,h1,h2,h3);
            smA[nb][1][lkb][lrow] = make_uint4(l0,l1,l2,l3);
            cvt_hl(b0g,h0,h1,l0,l1); cvt_hl(b1g,h2,h3,l2,l3);
            smB[nb][0][lkb][lrow] = make_uint4(h0,h1,h2,h3);
            smB[nb][1][lkb][lrow] = make_uint4(l0,l1,l2,l3);
            __syncthreads();
            buf = nb;
        }
    }

    float* outp = (half ? g_attpb : g_attpa) + (size_t)b * CC * HW + (size_t)m0 * HW + n0;
#pragma unroll
    for (int f = 0; f < 4; f++) {
        int r0 = wm + f * 16 + (lane >> 2), r1 = r0 + 8;
#pragma unroll
        for (int g = 0; g < 4; g++) {
            int cb = wn + g * 8 + (lane & 3) * 2;
            *(float2*)(outp + (size_t)r0 * HW + cb) = make_float2(c[f][g][0], c[f][g][1]);
            *(float2*)(outp + (size_t)r1 * HW + cb) = make_float2(c[f][g][2], c[f][g][3]);
        }
    }
}

// att_out = pa + pb
__global__ void k_attcomb(float* __restrict__ attout) {
    int i4 = blockIdx.x * 256 + threadIdx.x;          // < 524288
    float4 a = ((const float4*)g_attpa)[i4];
    float4 bb = ((const float4*)g_attpb)[i4];
    ((float4*)attout)[i4] = make_float4(a.x + bb.x, a.y + bb.y, a.z + bb.z, a.w + bb.w);
}

// ---------------- inverse channel norms of f_q and att_fq ----------------
__global__ void k_norm2(const float* __restrict__ f_q, const float* __restrict__ att) {
    int b   = blockIdx.y;
    int pix = blockIdx.x * 256 + threadIdx.x;
    const float* src = (blockIdx.z == 0 ? f_q : att) + (size_t)b * CC * HW + pix;
    float ss = 0.f;
#pragma unroll 8
    for (int c = 0; c < CC; c++) { float v = src[(size_t)c * HW]; ss = fmaf(v, v, ss); }
    float inv = 1.0f / fmaxf(sqrtf(ss), 1e-12f);
    (blockIdx.z == 0 ? g_nq2 : g_na2)[b * HW + pix] = inv;
}

// ---------------- fq = l2n(f_q) + 0.5*l2n(att_fq) ----------------
__global__ void k_fqout(const float* __restrict__ f_q, const float* __restrict__ att,
                        float* __restrict__ fqo) {
    int i4 = blockIdx.x * 256 + threadIdx.x;          // < 524288
    int base = i4 * 4;
    int b = base >> 19;
    int pix = base & 1023;
    float4 q = ((const float4*)f_q)[i4];
    float4 a = ((const float4*)att)[i4];
    int ni = (b * HW + pix) >> 2;
    float4 nq = ((const float4*)g_nq2)[ni];
    float4 na = ((const float4*)g_na2)[ni];
    float4 o;
    o.x = q.x * nq.x + a.x * na.x * 0.5f;
    o.y = q.y * nq.y + a.y * na.y * 0.5f;
    o.z = q.z * nq.z + a.z * na.z * 0.5f;
    o.w = q.w * nq.w + a.w * na.w * 0.5f;
    ((float4*)fqo)[i4] = o;
}

// ---------------- conv1: bf16-split tensor implicit GEMM, K-split by 2 ----------------
__global__ void __launch_bounds__(256, 2) k_conv1(const float* __restrict__ f_q,
                                                  const float* __restrict__ f_s) {
    __shared__ __align__(16) unsigned smW[2][2][16][36];  // [buf][hi/lo][k][oc72h]
    __shared__ __align__(16) unsigned smI[2][2][16][68];  // [buf][hi/lo][k][pix136h]
    int b = blockIdx.z >> 1, half = blockIdx.z & 1;
    int oc0 = blockIdx.y * 64, pix0 = blockIdx.x * 128;
    int tid = threadIdx.x, lane = tid & 31, wid = tid >> 5;
    int wm = (wid >> 2) * 32, wn = (wid & 3) * 32;
    int kr = tid >> 4, mc = (tid & 15) * 8;

    int kA = (lane & 7) + ((lane >> 4) << 3);
    int cA = ((lane >> 3) & 1) << 3;
    int kB = (lane & 7) + (((lane >> 3) & 1) << 3);
    int cB = (lane >> 4) << 3;
    unsigned baseW = (unsigned)__cvta_generic_to_shared(&smW[0][0][0][0]);
    unsigned baseI = (unsigned)__cvta_generic_to_shared(&smI[0][0][0][0]);
    unsigned offA = (unsigned)(kA * 144 + (cA + wm) * 2);
    unsigned offB = (unsigned)(kB * 272 + (cB + wn) * 2);

    const float* fqp = f_q + (size_t)b * CC * HW;
    const float* fsp = f_s + (size_t)b * CC * HW;

    int pp0 = pix0 + mc;
    int py = pp0 >> 5, px0v = pp0 & 31;
    int wtt = (tid & 127);
    int wrow = wtt >> 3, wcol8 = (wtt & 7) * 8;
    bool whalf = (tid < 128);
    int kbase = half * 288;                           // global k-tile base

    float c[2][4][4];
#pragma unroll
    for (int f = 0; f < 2; f++)
#pragma unroll
        for (int g = 0; g < 4; g++) { c[f][g][0]=0.f; c[f][g][1]=0.f; c[f][g][2]=0.f; c[f][g][3]=0.f; }

    {   // prologue: global k-tile kbase
        int tap = kbase >> 6, ict = kbase & 63;
        int dy = 2 * (tap / 3) - 2, dx = 2 * (tap % 3) - 2;
        uint4 wv;
        const __nv_bfloat16* wsrc = whalf ? g_wt1h : g_wt1l;
        wv = *(const uint4*)(wsrc + (size_t)(tap * 1024 + ict * 16 + wrow) * 256 + oc0 + wcol8);
        float v[8];
        int ic = ict * 16 + kr;
        const float* src = (ic < 512 ? fqp + (size_t)ic * HW
                                     : fsp + (size_t)(ic - 512) * HW);
        int iy = py + dy;
        bool yok = ((unsigned)iy < 32u);
        const float* rowp = src + iy * 32;
#pragma unroll
        for (int j = 0; j < 8; j++) {
            int ix = px0v + j + dx;
            v[j] = (yok && ((unsigned)ix < 32u)) ? rowp[ix] : 0.f;
        }
        *(uint4*)&smW[0][whalf ? 0 : 1][wrow][wcol8 >> 1] = wv;
        unsigned h0,h1,l0,l1;
        unsigned* pIh = &smI[0][0][kr][mc >> 1];
        unsigned* pIl = &smI[0][1][kr][mc >> 1];
        float4 fa = make_float4(v[0], v[1], v[2], v[3]);
        float4 fb = make_float4(v[4], v[5], v[6], v[7]);
        cvt_hl(fa,h0,h1,l0,l1); pIh[0]=h0; pIh[1]=h1; pIl[0]=l0; pIl[1]=l1;
        cvt_hl(fb,h0,h1,l0,l1); pIh[2]=h0; pIh[3]=h1; pIl[2]=l0; pIl[3]=l1;
    }
    __syncthreads();

    int buf = 0;
    for (int kt = 0; kt < 288; kt++) {
        uint4 wv; float v[8];
        if (kt < 287) {
            int kn = kbase + kt + 1;
            int tap = kn >> 6, ict = kn & 63;
            int dy = 2 * (tap / 3) - 2, dx = 2 * (tap % 3) - 2;
            const __nv_bfloat16* wsrc = whalf ? g_wt1h : g_wt1l;
            wv = *(const uint4*)(wsrc + (size_t)(tap * 1024 + ict * 16 + wrow) * 256 + oc0 + wcol8);
            int ic = ict * 16 + kr;
            const float* src = (ic < 512 ? fqp + (size_t)ic * HW
                                         : fsp + (size_t)(ic - 512) * HW);
            int iy = py + dy;
            bool yok = ((unsigned)iy < 32u);
            const float* rowp = src + iy * 32;
#pragma unroll
            for (int j = 0; j < 8; j++) {
                int ix = px0v + j + dx;
                v[j] = (yok && ((unsigned)ix < 32u)) ? rowp[ix] : 0.f;
            }
        }
        unsigned bW = baseW + (unsigned)buf * 4608u;
        unsigned bI = baseI + (unsigned)buf * 8704u;
        unsigned a[8], al[8], bh[8], bl[8];
#pragma unroll
        for (int f = 0; f < 2; f++) ldsm4t(a  + 4 * f, bW + offA + f * 32);
#pragma unroll
        for (int f = 0; f < 2; f++) ldsm4t(al + 4 * f, bW + 2304u + offA + f * 32);
#pragma unroll
        for (int g2 = 0; g2 < 2; g2++) ldsm4t(bh + 4 * g2, bI + offB + g2 * 32);
#pragma unroll
        for (int g2 = 0; g2 < 2; g2++) ldsm4t(bl + 4 * g2, bI + 4352u + offB + g2 * 32);
#pragma unroll
        for (int f = 0; f < 2; f++)
#pragma unroll
            for (int g = 0; g < 4; g++) {
                mma_bf16(c[f][g], a  + 4 * f, bh + 2 * g);
                mma_bf16(c[f][g], a  + 4 * f, bl + 2 * g);
                mma_bf16(c[f][g], al + 4 * f, bh + 2 * g);
            }
        if (kt < 287) {
            int nb = buf ^ 1;
            *(uint4*)&smW[nb][whalf ? 0 : 1][wrow][wcol8 >> 1] = wv;
            unsigned h0,h1,l0,l1;
            unsigned* pIh = &smI[nb][0][kr][mc >> 1];
            unsigned* pIl = &smI[nb][1][kr][mc >> 1];
            float4 fa = make_float4(v[0], v[1], v[2], v[3]);
            float4 fb = make_float4(v[4], v[5], v[6], v[7]);
            cvt_hl(fa,h0,h1,l0,l1); pIh[0]=h0; pIh[1]=h1; pIl[0]=l0; pIl[1]=l1;
            cvt_hl(fb,h0,h1,l0,l1); pIh[2]=h0; pIh[3]=h1; pIl[2]=l0; pIl[3]=l1;
            __syncthreads();
            buf = nb;
        }
    }

    float* outp = (half ? g_c1pb : g_c1pa) + (size_t)b * 262144;
#pragma unroll
    for (int f = 0; f < 2; f++) {
        int r0 = wm + f * 16 + (lane >> 2), r1 = r0 + 8;
#pragma unroll
        for (int g = 0; g < 4; g++) {
            int cb = wn + g * 8 + (lane & 3) * 2;
            *(float2*)(outp + (size_t)(oc0 + r0) * HW + pix0 + cb) =
                make_float2(c[f][g][0], c[f][g][1]);
            *(float2*)(outp + (size_t)(oc0 + r1) * HW + pix0 + cb) =
                make_float2(c[f][g][2], c[f][g][3]);
        }
    }
}

// c1 = relu(pa + pb + bias)
__global__ void k_c1comb(const float* __restrict__ b1) {
    int i4 = blockIdx.x * 256 + threadIdx.x;          // < 262144
    float4 a = ((const float4*)g_c1pa)[i4];
    float4 bb = ((const float4*)g_c1pb)[i4];
    int oc = (i4 & 65535) >> 8;                       // per-b block: 65536 f4, 256 f4 per oc
    float bias = b1[oc];
    float4 o;
    o.x = fmaxf(a.x + bb.x + bias, 0.f);
    o.y = fmaxf(a.y + bb.y + bias, 0.f);
    o.z = fmaxf(a.z + bb.z + bias, 0.f);
    o.w = fmaxf(a.w + bb.w + bias, 0.f);
    ((float4*)g_c1)[i4] = o;
}

// ---------------- conv2: bf16-split tensor implicit GEMM, K-split by 2 ----------------
__global__ void __launch_bounds__(256, 2) k_conv2() {
    __shared__ __align__(16) unsigned smW[2][2][16][36];
    __shared__ __align__(16) unsigned smI[2][2][16][68];
    int b = blockIdx.z >> 1, half = blockIdx.z & 1;
    int oc0 = blockIdx.y * 64, pix0 = blockIdx.x * 128;
    int tid = threadIdx.x, lane = tid & 31, wid = tid >> 5;
    int wm = (wid >> 2) * 32, wn = (wid & 3) * 32;
    int kr = tid >> 4, mc = (tid & 15) * 8;

    int kA = (lane & 7) + ((lane >> 4) << 3);
    int cA = ((lane >> 3) & 1) << 3;
    int kB = (lane & 7) + (((lane >> 3) & 1) << 3);
    int cB = (lane >> 4) << 3;
    unsigned baseW = (unsigned)__cvta_generic_to_shared(&smW[0][0][0][0]);
    unsigned baseI = (unsigned)__cvta_generic_to_shared(&smI[0][0][0][0]);
    unsigned offA = (unsigned)(kA * 144 + (cA + wm) * 2);
    unsigned offB = (unsigned)(kB * 272 + (cB + wn) * 2);

    const float* c1p = g_c1 + (size_t)b * 262144;

    int offp[8];
#pragma unroll
    for (int j = 0; j < 8; j++) {
        int p = pix0 + mc + j; if (p > 899) p = 899;
        offp[j] = (p / 30) * 32 + (p % 30);
    }
    int wtt = (tid & 127);
    int wrow = wtt >> 3, wcol8 = (wtt & 7) * 8;
    bool whalf = (tid < 128);
    int kbase = half * 72;                            // 144 k-tiles total

    float c[2][4][4];
#pragma unroll
    for (int f = 0; f < 2; f++)
#pragma unroll
        for (int g = 0; g < 4; g++) { c[f][g][0]=0.f; c[f][g][1]=0.f; c[f][g][2]=0.f; c[f][g][3]=0.f; }

    {   // prologue: k-tile kbase
        int tap = kbase >> 4, ict = kbase & 15;
        int doff = (tap / 3) * 32 + (tap % 3);
        uint4 wv;
        const __nv_bfloat16* wsrc = whalf ? g_wt2h : g_wt2l;
        wv = *(const uint4*)(wsrc + (size_t)(tap * 256 + ict * 16 + wrow) * 256 + oc0 + wcol8);
        float v[8];
        const float* src = c1p + (size_t)(ict * 16 + kr) * HW;
#pragma unroll
        for (int j = 0; j < 8; j++) v[j] = src[offp[j] + doff];
        *(uint4*)&smW[0][whalf ? 0 : 1][wrow][wcol8 >> 1] = wv;
        unsigned h0,h1,l0,l1;
        unsigned* pIh = &smI[0][0][kr][mc >> 1];
        unsigned* pIl = &smI[0][1][kr][mc >> 1];
        float4 fa = make_float4(v[0], v[1], v[2], v[3]);
        float4 fb = make_float4(v[4], v[5], v[6], v[7]);
        cvt_hl(fa,h0,h1,l0,l1); pIh[0]=h0; pIh[1]=h1; pIl[0]=l0; pIl[1]=l1;
        cvt_hl(fb,h0,h1,l0,l1); pIh[2]=h0; pIh[3]=h1; pIl[2]=l0; pIl[3]=l1;
    }
    __syncthreads();

    int buf = 0;
    for (int kt = 0; kt < 72; kt++) {
        uint4 wv; float v[8];
        if (kt < 71) {
            int kn = kbase + kt + 1;
            int tap = kn >> 4, ict = kn & 15;
            int doff = (tap / 3) * 32 + (tap % 3);
            const __nv_bfloat16* wsrc = whalf ? g_wt2h : g_wt2l;
            wv = *(const uint4*)(wsrc + (size_t)(tap * 256 + ict * 16 + wrow) * 256 + oc0 + wcol8);
            const float* src = c1p + (size_t)(ict * 16 + kr) * HW;
#pragma unroll
            for (int j = 0; j < 8; j++) v[j] = src[offp[j] + doff];
        }
        unsigned bW = baseW + (unsigned)buf * 4608u;
        unsigned bI = baseI + (unsigned)buf * 8704u;
        unsigned a[8], al[8], bh[8], bl[8];
#pragma unroll
        for (int f = 0; f < 2; f++) ldsm4t(a  + 4 * f, bW + offA + f * 32);
#pragma unroll
        for (int f = 0; f < 2; f++) ldsm4t(al + 4 * f, bW + 2304u + offA + f * 32);
#pragma unroll
        for (int g2 = 0; g2 < 2; g2++) ldsm4t(bh + 4 * g2, bI + offB + g2 * 32);
#pragma unroll
        for (int g2 = 0; g2 < 2; g2++) ldsm4t(bl + 4 * g2, bI + 4352u + offB + g2 * 32);
#pragma unroll
        for (int f = 0; f < 2; f++)
#pragma unroll
            for (int g = 0; g < 4; g++) {
                mma_bf16(c[f][g], a  + 4 * f, bh + 2 * g);
                mma_bf16(c[f][g], a  + 4 * f, bl + 2 * g);
                mma_bf16(c[f][g], al + 4 * f, bh + 2 * g);
            }
        if (kt < 71) {
            int nb = buf ^ 1;
            *(uint4*)&smW[nb][whalf ? 0 : 1][wrow][wcol8 >> 1] = wv;
            unsigned h0,h1,l0,l1;
            unsigned* pIh = &smI[nb][0][kr][mc >> 1];
            unsigned* pIl = &smI[nb][1][kr][mc >> 1];
            float4 fa = make_float4(v[0], v[1], v[2], v[3]);
            float4 fb = make_float4(v[4], v[5], v[6], v[7]);
            cvt_hl(fa,h0,h1,l0,l1); pIh[0]=h0; pIh[1]=h1; pIl[0]=l0; pIl[1]=l1;
            cvt_hl(fb,h0,h1,l0,l1); pIh[2]=h0; pIh[3]=h1; pIl[2]=l0; pIl[3]=l1;
            __syncthreads();
            buf = nb;
        }
    }

    float* outp = (half ? g_c2pb : g_c2pa) + (size_t)b * 230400;
#pragma unroll
    for (int f = 0; f < 2; f++) {
        int r0 = wm + f * 16 + (lane >> 2), r1 = r0 + 8;
#pragma unroll
        for (int g = 0; g < 4; g++) {
            int cb = wn + g * 8 + (lane & 3) * 2;
            int p0 = pix0 + cb;                // even; p0<900 => p0+1<=899
            if (p0 < 900) {
                *(float2*)(outp + (size_t)(oc0 + r0) * 900 + p0) =
                    make_float2(c[f][g][0], c[f][g][1]);
                *(float2*)(outp + (size_t)(oc0 + r1) * 900 + p0) =
                    make_float2(c[f][g][2], c[f][g][3]);
            }
        }
    }
}

// ---------------- maxpool 3x3 s3 (combines conv2 partials + bias) ----------------
__global__ void k_pool(const float* __restrict__ b2) {
    int oc = blockIdx.x, b = blockIdx.y;
    int t = threadIdx.x;
    if (t >= 100) return;
    int y = t / 10, x = t % 10;
    size_t base = ((size_t)b * 256 + oc) * 900;
    const float* pa = g_c2pa + base;
    const float* pb = g_c2pb + base;
    float m = -3.4e38f;
#pragma unroll
    for (int dy = 0; dy < 3; dy++)
#pragma unroll
        for (int dx = 0; dx < 3; dx++) {
            int idx = (3 * y + dy) * 30 + 3 * x + dx;
            m = fmaxf(m, pa[idx] + pb[idx]);
        }
    g_pool[((size_t)b * 256 + oc) * 100 + t] = m + b2[oc];
}

// ---------------- conv3 (3x3 VALID, 10x10 -> 8x8) + mean -> weight[b] ----------------
__global__ void k_conv3(const float* __restrict__ w3, const float* __restrict__ b3,
                        float* __restrict__ wout) {
    int b = blockIdx.x;
    int tid = threadIdx.x;
    int o = tid >> 2, part = tid & 3;
    int oy = o >> 3, ox = o & 7;
    float s = 0.f;
    for (int ic = part * 64; ic < part * 64 + 64; ic++) {
        const float* pp = g_pool + ((size_t)b * 256 + ic) * 100 + oy * 10 + ox;
        const float* wp = w3 + ic * 9;
#pragma unroll
        for (int ky = 0; ky < 3; ky++)
#pragma unroll
            for (int kx = 0; kx < 3; kx++)
                s = fmaf(pp[ky * 10 + kx], wp[ky * 3 + kx], s);
    }
    s += __shfl_down_sync(0xffffffffu, s, 1);
    s += __shfl_down_sync(0xffffffffu, s, 2);
    __shared__ float sh[64];
    if (part == 0) sh[o] = s;
    __syncthreads();
    if (tid < 32) {
        float v = sh[tid] + sh[tid + 32];
#pragma unroll
        for (int off = 16; off; off >>= 1) v += __shfl_xor_sync(0xffffffffu, v, off);
        if (tid == 0) wout[b] = v * (1.0f / 64.0f) + b3[0];
    }
}

// ---------------- launch ----------------
extern "C" void kernel_launch(void* const* d_in, const int* in_sizes, int n_in,
                              void* d_out, int out_size) {
    const float* fq_feats = (const float*)d_in[0];
    const float* fs_feats = (const float*)d_in[1];
    const float* f_q = (const float*)d_in[2];
    const float* f_s = (const float*)d_in[3];
    const float* w1 = (const float*)d_in[4];
    const float* b1 = (const float*)d_in[5];
    const float* w2 = (const float*)d_in[6];
    const float* b2 = (const float*)d_in[7];
    const float* w3 = (const float*)d_in[8];
    const float* b3 = (const float*)d_in[9];

    float* out     = (float*)d_out;
    float* fq_out  = out;                       // [4,512,32,32]
    float* att_out = out + 2097152;             // [4,512,32,32]
    float* w_out   = out + 4194304;             // [1,4]

    k_twt1<<<9216, 256>>>(w1);
    k_twt2<<<2304, 256>>>(w2);
    k_norms<<<dim3(4, 36, 2), 256>>>(fq_feats, fs_feats);
    k_corr<<<dim3(8, 8, 4), 256>>>(fq_feats, fs_feats);
    k_softmax<<<4096, 256>>>();
    k_att<<<dim3(8, 4, 8), 256>>>(f_s);
    k_attcomb<<<2048, 256>>>(att_out);
    k_norm2<<<dim3(4, 4, 2), 256>>>(f_q, att_out);
    k_fqout<<<2048, 256>>>(f_q, att_out, fq_out);
    k_conv1<<<dim3(8, 4, 8), 256>>>(f_q, f_s);
    k_c1comb<<<1024, 256>>>(b1);
    k_conv2<<<dim3(8, 4, 8), 256>>>();
    k_pool<<<dim3(256, 4), 128>>>(b2);
    k_conv3<<<4, 256>>>(w3, b3, w_out);
}

// round 16
// speedup vs baseline: 1.1475x; 1.0338x over previous
#include <cuda_runtime.h>
#include <cuda_bf16.h>

#define LL 9
#define BB 4
#define CC 512
#define HW 1024

// ---------------- scratch (device globals; no allocation) ----------------
__device__ __align__(16) float g_corr[(size_t)BB*HW*HW];   // 16 MB, reused as attn
__device__ __align__(16) float g_c1[BB*256*HW];            // conv1 out [b][256][32*32]
__device__ __align__(16) float g_c1pa[BB*256*HW];          // conv1 K-split partials
__device__ __align__(16) float g_c1pb[BB*256*HW];
__device__ __align__(16) float g_attpa[BB*CC*HW];          // att K-split partials
__device__ __align__(16) float g_attpb[BB*CC*HW];
__device__ __align__(16) float g_c2pa[BB*256*900];         // conv2 K-split partials
__device__ __align__(16) float g_c2pb[BB*256*900];
__device__ __align__(16) float g_pool[BB*256*100];         // pooled [b][256][10*10]
__device__ __align__(16) __nv_bfloat16 g_wt1h[9*1024*256]; // w1 hi [tap][ic][oc]
__device__ __align__(16) __nv_bfloat16 g_wt1l[9*1024*256]; // w1 lo [tap][ic][oc]
__device__ __align__(16) __nv_bfloat16 g_wt2h[9*256*256];  // w2 hi [tap][ic][oc]
__device__ __align__(16) __nv_bfloat16 g_wt2l[9*256*256];  // w2 lo [tap][ic][oc]
__device__ __align__(16) float g_nq2[BB*HW];
__device__ __align__(16) float g_na2[BB*HW];

// ---------------- helpers ----------------
__device__ __forceinline__ void ldsm4t(unsigned* r, unsigned addr) {
    asm volatile("ldmatrix.sync.aligned.m8n8.x4.trans.shared.b16 {%0,%1,%2,%3}, [%4];\n"
        : "=r"(r[0]), "=r"(r[1]), "=r"(r[2]), "=r"(r[3]) : "r"(addr));
}
__device__ __forceinline__ void ldsm4(unsigned* r, unsigned addr) {
    asm volatile("ldmatrix.sync.aligned.m8n8.x4.shared.b16 {%0,%1,%2,%3}, [%4];\n"
        : "=r"(r[0]), "=r"(r[1]), "=r"(r[2]), "=r"(r[3]) : "r"(addr));
}
__device__ __forceinline__ void mma_bf16(float* c, const unsigned* a, const unsigned* b) {
    asm volatile(
        "mma.sync.aligned.m16n8k16.row.col.f32.bf16.bf16.f32 "
        "{%0,%1,%2,%3}, {%4,%5,%6,%7}, {%8,%9}, {%0,%1,%2,%3};\n"
        : "+f"(c[0]), "+f"(c[1]), "+f"(c[2]), "+f"(c[3])
        : "r"(a[0]), "r"(a[1]), "r"(a[2]), "r"(a[3]), "r"(b[0]), "r"(b[1]));
}
// split float4 -> hi bf16x2 pair + lo bf16x2 pair (packed as unsigned)
__device__ __forceinline__ void cvt_hl(float4 v, unsigned& h0, unsigned& h1,
                                       unsigned& l0, unsigned& l1) {
    __nv_bfloat162 H0 = __floats2bfloat162_rn(v.x, v.y);
    __nv_bfloat162 H1 = __floats2bfloat162_rn(v.z, v.w);
    __nv_bfloat162 L0 = __floats2bfloat162_rn(v.x - __bfloat162float(H0.x),
                                              v.y - __bfloat162float(H0.y));
    __nv_bfloat162 L1 = __floats2bfloat162_rn(v.z - __bfloat162float(H1.x),
                                              v.w - __bfloat162float(H1.y));
    h0 = *(unsigned*)&H0; h1 = *(unsigned*)&H1;
    l0 = *(unsigned*)&L0; l1 = *(unsigned*)&L1;
}

// ---------------- weight prep ----------------
__global__ void k_twt1(const float* __restrict__ w1) {
    int i = blockIdx.x * 256 + threadIdx.x;          // < 2359296
    float v = w1[i];
    int oc = i / 9216; int r = i % 9216; int ic = r / 9; int tap = r % 9;
    __nv_bfloat16 h = __float2bfloat16(v);
    __nv_bfloat16 lo = __float2bfloat16(v - __bfloat162float(h));
    int o = tap * 262144 + ic * 256 + oc;
    g_wt1h[o] = h; g_wt1l[o] = lo;
}
__global__ void k_twt2(const float* __restrict__ w2) {
    int i = blockIdx.x * 256 + threadIdx.x;          // < 589824
    float v = w2[i];
    int oc = i / 2304; int r = i % 2304; int ic = r / 9; int tap = r % 9;
    __nv_bfloat16 h = __float2bfloat16(v);
    __nv_bfloat16 lo = __float2bfloat16(v - __bfloat162float(h));
    int o = tap * 65536 + ic * 256 + oc;
    g_wt2h[o] = h; g_wt2l[o] = lo;
}

// ---------------- corr: bf16-split tensor-core, pipelined, fused norms ----------------
// Per-level sum-of-squares of A-cols/B-cols accumulated from the loaded values;
// reduced through the dead smem tile buffer at level end -> s_inv replaces k_norms.
__global__ void __launch_bounds__(256, 2) k_corr(const float* __restrict__ fq,
                                                 const float* __restrict__ fs) {
    __shared__ __align__(16) unsigned smq[2][4][16][68];  // 68 u32 = 136 halves
    __shared__ float s_inv[2][128];
    int b  = blockIdx.z;
    int m0 = blockIdx.y * 128, n0 = blockIdx.x * 128;
    int tid = threadIdx.x, lane = tid & 31, wid = tid >> 5;
    int wm = (wid >> 2) * 64, wn = (wid & 3) * 32;
    int kr = tid >> 4, mc = (tid & 15) * 8;           // loader: 16 k-rows x 8 floats

    int kA = (lane & 7) + ((lane >> 4) << 3);
    int cA = ((lane >> 3) & 1) << 3;
    int kB = (lane & 7) + (((lane >> 3) & 1) << 3);
    int cB = (lane >> 4) << 3;
    unsigned smbase = (unsigned)__cvta_generic_to_shared(&smq[0][0][0][0]);
    unsigned offA = (unsigned)(kA * 272 + (cA + wm) * 2);
    unsigned offB = (unsigned)(kB * 272 + (cB + wn) * 2);

    float* outp = g_corr + (size_t)b * HW * HW + (size_t)m0 * HW + n0;

    float c[4][4][4];
#pragma unroll
    for (int f = 0; f < 4; f++)
#pragma unroll
        for (int g = 0; g < 4; g++) { c[f][g][0]=0.f; c[f][g][1]=0.f; c[f][g][2]=0.f; c[f][g][3]=0.f; }

    float sq[16];                                      // 0..7 A-cols, 8..15 B-cols
#pragma unroll
    for (int j = 0; j < 16; j++) sq[j] = 0.f;

    {   // global prologue: (l=0, kt=0) -> buf 0
        const float* Ag = fq + (size_t)b * CC * HW + m0;
        const float* Bg = fs + (size_t)b * CC * HW + n0;
        float4 a0g = *(const float4*)(Ag + (size_t)kr * HW + mc);
        float4 a1g = *(const float4*)(Ag + (size_t)kr * HW + mc + 4);
        float4 b0g = *(const float4*)(Bg + (size_t)kr * HW + mc);
        float4 b1g = *(const float4*)(Bg + (size_t)kr * HW + mc + 4);
        sq[0]=fmaf(a0g.x,a0g.x,sq[0]); sq[1]=fmaf(a0g.y,a0g.y,sq[1]);
        sq[2]=fmaf(a0g.z,a0g.z,sq[2]); sq[3]=fmaf(a0g.w,a0g.w,sq[3]);
        sq[4]=fmaf(a1g.x,a1g.x,sq[4]); sq[5]=fmaf(a1g.y,a1g.y,sq[5]);
        sq[6]=fmaf(a1g.z,a1g.z,sq[6]); sq[7]=fmaf(a1g.w,a1g.w,sq[7]);
        sq[8]=fmaf(b0g.x,b0g.x,sq[8]);  sq[9]=fmaf(b0g.y,b0g.y,sq[9]);
        sq[10]=fmaf(b0g.z,b0g.z,sq[10]); sq[11]=fmaf(b0g.w,b0g.w,sq[11]);
        sq[12]=fmaf(b1g.x,b1g.x,sq[12]); sq[13]=fmaf(b1g.y,b1g.y,sq[13]);
        sq[14]=fmaf(b1g.z,b1g.z,sq[14]); sq[15]=fmaf(b1g.w,b1g.w,sq[15]);
        unsigned h0,h1,l0,l1;
        unsigned* pAh = &smq[0][0][kr][mc >> 1];
        unsigned* pAl = &smq[0][1][kr][mc >> 1];
        unsigned* pBh = &smq[0][2][kr][mc >> 1];
        unsigned* pBl = &smq[0][3][kr][mc >> 1];
        cvt_hl(a0g,h0,h1,l0,l1); pAh[0]=h0; pAh[1]=h1; pAl[0]=l0; pAl[1]=l1;
        cvt_hl(a1g,h0,h1,l0,l1); pAh[2]=h0; pAh[3]=h1; pAl[2]=l0; pAl[3]=l1;
        cvt_hl(b0g,h0,h1,l0,l1); pBh[0]=h0; pBh[1]=h1; pBl[0]=l0; pBl[1]=l1;
        cvt_hl(b1g,h0,h1,l0,l1); pBh[2]=h0; pBh[3]=h1; pBl[2]=l0; pBl[3]=l1;
    }
    __syncthreads();

    int buf = 0;
    for (int lkt = 0; lkt < 288; lkt++) {
        bool boundary = ((lkt & 31) == 31);
        // prefetch lkt+1
        float4 a0g, a1g, b0g, b1g;
        if (lkt < 287) {
            int nk = lkt + 1;
            int l2 = nk >> 5, k2 = (nk & 31) * 16;
            const float* Ag = fq + (size_t)(l2 * BB + b) * CC * HW + m0;
            const float* Bg = fs + (size_t)(l2 * BB + b) * CC * HW + n0;
            a0g = *(const float4*)(Ag + (size_t)(k2 + kr) * HW + mc);
            a1g = *(const float4*)(Ag + (size_t)(k2 + kr) * HW + mc + 4);
            b0g = *(const float4*)(Bg + (size_t)(k2 + kr) * HW + mc);
            b1g = *(const float4*)(Bg + (size_t)(k2 + kr) * HW + mc + 4);
        }
        unsigned base = smbase + (unsigned)buf * 17408u;
        unsigned a[16], bh[8], bl[8];
#pragma unroll
        for (int f = 0; f < 4; f++) ldsm4t(a + 4 * f, base + offA + f * 32);
#pragma unroll
        for (int g2 = 0; g2 < 2; g2++) ldsm4t(bh + 4 * g2, base + 2u * 4352u + offB + g2 * 32);
#pragma unroll
        for (int g2 = 0; g2 < 2; g2++) ldsm4t(bl + 4 * g2, base + 3u * 4352u + offB + g2 * 32);
#pragma unroll
        for (int f = 0; f < 4; f++)
#pragma unroll
            for (int g = 0; g < 4; g++) {
                mma_bf16(c[f][g], a + 4 * f, bh + 2 * g);
                mma_bf16(c[f][g], a + 4 * f, bl + 2 * g);
            }
#pragma unroll
        for (int f = 0; f < 4; f++) ldsm4t(a + 4 * f, base + 4352u + offA + f * 32);
#pragma unroll
        for (int f = 0; f < 4; f++)
#pragma unroll
            for (int g = 0; g < 4; g++)
                mma_bf16(c[f][g], a + 4 * f, bh + 2 * g);

        if (lkt < 287) {   // STS to other buffer
            int nb = buf ^ 1;
            unsigned h0,h1,l0,l1;
            unsigned* pAh = &smq[nb][0][kr][mc >> 1];
            unsigned* pAl = &smq[nb][1][kr][mc >> 1];
            unsigned* pBh = &smq[nb][2][kr][mc >> 1];
            unsigned* pBl = &smq[nb][3][kr][mc >> 1];
            cvt_hl(a0g,h0,h1,l0,l1); pAh[0]=h0; pAh[1]=h1; pAl[0]=l0; pAl[1]=l1;
            cvt_hl(a1g,h0,h1,l0,l1); pAh[2]=h0; pAh[3]=h1; pAl[2]=l0; pAl[3]=l1;
            cvt_hl(b0g,h0,h1,l0,l1); pBh[0]=h0; pBh[1]=h1; pBl[0]=l0; pBl[1]=l1;
            cvt_hl(b1g,h0,h1,l0,l1); pBh[2]=h0; pBh[3]=h1; pBl[2]=l0; pBl[3]=l1;
        }
        if (lkt < 287 && !boundary) {   // same-level prefetch: accumulate now
            sq[0]=fmaf(a0g.x,a0g.x,sq[0]); sq[1]=fmaf(a0g.y,a0g.y,sq[1]);
            sq[2]=fmaf(a0g.z,a0g.z,sq[2]); sq[3]=fmaf(a0g.w,a0g.w,sq[3]);
            sq[4]=fmaf(a1g.x,a1g.x,sq[4]); sq[5]=fmaf(a1g.y,a1g.y,sq[5]);
            sq[6]=fmaf(a1g.z,a1g.z,sq[6]); sq[7]=fmaf(a1g.w,a1g.w,sq[7]);
            sq[8]=fmaf(b0g.x,b0g.x,sq[8]);  sq[9]=fmaf(b0g.y,b0g.y,sq[9]);
            sq[10]=fmaf(b0g.z,b0g.z,sq[10]); sq[11]=fmaf(b0g.w,b0g.w,sq[11]);
            sq[12]=fmaf(b1g.x,b1g.x,sq[12]); sq[13]=fmaf(b1g.y,b1g.y,sq[13]);
            sq[14]=fmaf(b1g.z,b1g.z,sq[14]); sq[15]=fmaf(b1g.w,b1g.w,sq[15]);
        }

        if (boundary) {   // level epilogue: reduce norms through dead buf, then RMW
            int l = lkt >> 5;
            float* partA = (float*)&smq[buf][0][0][0];   // [16][128]
            float* partB = partA + 2048;
            __syncthreads();                              // all warps done with buf
#pragma unroll
            for (int j = 0; j < 8; j++) {
                partA[kr * 128 + mc + j] = sq[j];
                partB[kr * 128 + mc + j] = sq[8 + j];
            }
            __syncthreads();
            {
                int op = tid >> 7, col = tid & 127;
                const float* p = (op ? partB : partA) + col;
                float ss = 0.f;
#pragma unroll
                for (int k2 = 0; k2 < 16; k2++) ss += p[k2 * 128];
                s_inv[op][col] = 1.0f / fmaxf(sqrtf(ss), 1e-12f);
            }
#pragma unroll
            for (int j = 0; j < 16; j++) sq[j] = 0.f;
            __syncthreads();
#pragma unroll
            for (int f = 0; f < 4; f++) {
                int r0 = wm + f * 16 + (lane >> 2), r1 = r0 + 8;
                float q0 = s_inv[0][r0], q1 = s_inv[0][r1];
#pragma unroll
                for (int g = 0; g < 4; g++) {
                    int cb = wn + g * 8 + (lane & 3) * 2;
                    float s0 = s_inv[1][cb], s1 = s_inv[1][cb + 1];
                    float v00 = fmaxf(c[f][g][0] * q0 * s0, 0.f);
                    float v01 = fmaxf(c[f][g][1] * q0 * s1, 0.f);
                    float v10 = fmaxf(c[f][g][2] * q1 * s0, 0.f);
                    float v11 = fmaxf(c[f][g][3] * q1 * s1, 0.f);
                    float2* p0 = (float2*)(outp + (size_t)r0 * HW + cb);
                    float2* p1 = (float2*)(outp + (size_t)r1 * HW + cb);
                    if (l == 0) {
                        *p0 = make_float2(v00, v01);
                        *p1 = make_float2(v10, v11);
                    } else {
                        float2 o0 = *p0, o1 = *p1;
                        o0.x += v00; o0.y += v01; o1.x += v10; o1.y += v11;
                        *p0 = o0; *p1 = o1;
                    }
                    c[f][g][0]=0.f; c[f][g][1]=0.f; c[f][g][2]=0.f; c[f][g][3]=0.f;
                }
            }
            if (lkt < 287) {   // deferred accumulate: prefetched tile is next level
                sq[0]=fmaf(a0g.x,a0g.x,sq[0]); sq[1]=fmaf(a0g.y,a0g.y,sq[1]);
                sq[2]=fmaf(a0g.z,a0g.z,sq[2]); sq[3]=fmaf(a0g.w,a0g.w,sq[3]);
                sq[4]=fmaf(a1g.x,a1g.x,sq[4]); sq[5]=fmaf(a1g.y,a1g.y,sq[5]);
                sq[6]=fmaf(a1g.z,a1g.z,sq[6]); sq[7]=fmaf(a1g.w,a1g.w,sq[7]);
                sq[8]=fmaf(b0g.x,b0g.x,sq[8]);  sq[9]=fmaf(b0g.y,b0g.y,sq[9]);
                sq[10]=fmaf(b0g.z,b0g.z,sq[10]); sq[11]=fmaf(b0g.w,b0g.w,sq[11]);
                sq[12]=fmaf(b1g.x,b1g.x,sq[12]); sq[13]=fmaf(b1g.y,b1g.y,sq[13]);
                sq[14]=fmaf(b1g.z,b1g.z,sq[14]); sq[15]=fmaf(b1g.w,b1g.w,sq[15]);
            }
        }

        if (lkt < 287) {
            __syncthreads();
            buf ^= 1;
        }
    }
}

// ---------------- row softmax (scale = TEMP/L folds the mean) ----------------
__global__ void k_softmax() {
    float* r = g_corr + (size_t)blockIdx.x * HW;      // blockIdx.x = b*1024 + q
    int tid = threadIdx.x, wid = tid >> 5, lane = tid & 31;
    const float sc = 20.0f / 9.0f;
    float4 v = ((const float4*)r)[tid];
    v.x *= sc; v.y *= sc; v.z *= sc; v.w *= sc;
    float mx = fmaxf(fmaxf(v.x, v.y), fmaxf(v.z, v.w));
#pragma unroll
    for (int o = 16; o; o >>= 1) mx = fmaxf(mx, __shfl_xor_sync(0xffffffffu, mx, o));
    __shared__ float sh[8];
    if (lane == 0) sh[wid] = mx;
    __syncthreads();
    float m = sh[0];
#pragma unroll
    for (int k = 1; k < 8; k++) m = fmaxf(m, sh[k]);
    v.x = __expf(v.x - m); v.y = __expf(v.y - m);
    v.z = __expf(v.z - m); v.w = __expf(v.w - m);
    float s = v.x + v.y + v.z + v.w;
#pragma unroll
    for (int o = 16; o; o >>= 1) s += __shfl_xor_sync(0xffffffffu, s, o);
    __syncthreads();
    if (lane == 0) sh[wid] = s;
    __syncthreads();
    float tot = 0.f;
#pragma unroll
    for (int k = 0; k < 8; k++) tot += sh[k];
    float inv = 1.0f / tot;
    v.x *= inv; v.y *= inv; v.z *= inv; v.w *= inv;
    ((float4*)r)[tid] = v;
}

// ---------------- k_att: bf16-split MMA, K-split by 2 (half = z&1) ----------------
__global__ void __launch_bounds__(256, 2) k_att(const float* __restrict__ fs_in) {
    __shared__ __align__(16) uint4 smA[2][2][2][128];   // [buf][hl][kb][row]
    __shared__ __align__(16) uint4 smB[2][2][2][128];
    int b = blockIdx.z >> 1, half = blockIdx.z & 1;
    int m0 = blockIdx.y * 128, n0 = blockIdx.x * 128;
    int tid = threadIdx.x, lane = tid & 31, wid = tid >> 5;
    int wm = (wid >> 2) * 64, wn = (wid & 3) * 32;
    int lrow = tid >> 1, lkb = tid & 1;

    const float* Ag = fs_in + (size_t)b * CC * HW + (size_t)m0 * HW + half * 512;
    const float* Bg = g_corr + (size_t)b * HW * HW + (size_t)n0 * HW + half * 512;

    int rsel = ((lane >> 3) & 1) * 8 + (lane & 7);
    int kbsel = lane >> 4;
    unsigned baseA = (unsigned)__cvta_generic_to_shared(&smA[0][0][0][0]);
    unsigned baseB = (unsigned)__cvta_generic_to_shared(&smB[0][0][0][0]);
    unsigned offA = (unsigned)(kbsel * 2048 + (wm + rsel) * 16);     // + f*256
    unsigned offB = (unsigned)(kbsel * 2048 + (wn + rsel) * 16);     // + gg*256

    float c[4][4][4];
#pragma unroll
    for (int f = 0; f < 4; f++)
#pragma unroll
        for (int g = 0; g < 4; g++) { c[f][g][0]=0.f; c[f][g][1]=0.f; c[f][g][2]=0.f; c[f][g][3]=0.f; }

    {   // prologue: k-tile 0
        float4 a0g = *(const float4*)(Ag + (size_t)lrow * HW + lkb * 8);
        float4 a1g = *(const float4*)(Ag + (size_t)lrow * HW + lkb * 8 + 4);
        float4 b0g = *(const float4*)(Bg + (size_t)lrow * HW + lkb * 8);
        float4 b1g = *(const float4*)(Bg + (size_t)lrow * HW + lkb * 8 + 4);
        unsigned h0,h1,l0,l1,h2,h3,l2,l3;
        cvt_hl(a0g,h0,h1,l0,l1); cvt_hl(a1g,h2,h3,l2,l3);
        smA[0][0][lkb][lrow] = make_uint4(h0,h1,h2,h3);
        smA[0][1][lkb][lrow] = make_uint4(l0,l1,l2,l3);
        cvt_hl(b0g,h0,h1,l0,l1); cvt_hl(b1g,h2,h3,l2,l3);
        smB[0][0][lkb][lrow] = make_uint4(h0,h1,h2,h3);
        smB[0][1][lkb][lrow] = make_uint4(l0,l1,l2,l3);
    }
    __syncthreads();

    int buf = 0;
    for (int kt = 0; kt < 32; kt++) {
        float4 a0g, a1g, b0g, b1g;
        if (kt < 31) {
            int k0 = (kt + 1) * 16 + lkb * 8;
            a0g = *(const float4*)(Ag + (size_t)lrow * HW + k0);
            a1g = *(const float4*)(Ag + (size_t)lrow * HW + k0 + 4);
            b0g = *(const float4*)(Bg + (size_t)lrow * HW + k0);
            b1g = *(const float4*)(Bg + (size_t)lrow * HW + k0 + 4);
        }
        unsigned bA = baseA + (unsigned)buf * 8192u;
        unsigned bB = baseB + (unsigned)buf * 8192u;
        unsigned a[16], bh[8], bl[8], t[4];
#pragma unroll
        for (int f = 0; f < 4; f++) ldsm4(a + 4 * f, bA + offA + f * 256);
#pragma unroll
        for (int gg = 0; gg < 2; gg++) {
            ldsm4(t, bB + offB + gg * 256);
            bh[gg*4+0]=t[0]; bh[gg*4+1]=t[2]; bh[gg*4+2]=t[1]; bh[gg*4+3]=t[3];
        }
#pragma unroll
        for (int gg = 0; gg < 2; gg++) {
            ldsm4(t, bB + 4096u + offB + gg * 256);
            bl[gg*4+0]=t[0]; bl[gg*4+1]=t[2]; bl[gg*4+2]=t[1]; bl[gg*4+3]=t[3];
        }
#pragma unroll
        for (int f = 0; f < 4; f++)
#pragma unroll
            for (int g = 0; g < 4; g++) {
                mma_bf16(c[f][g], a + 4 * f, bh + 2 * g);
                mma_bf16(c[f][g], a + 4 * f, bl + 2 * g);
            }
#pragma unroll
        for (int f = 0; f < 4; f++) ldsm4(a + 4 * f, bA + 4096u + offA + f * 256);
#pragma unroll
        for (int f = 0; f < 4; f++)
#pragma unroll
            for (int g = 0; g < 4; g++)
                mma_bf16(c[f][g], a + 4 * f, bh + 2 * g);

        if (kt < 31) {
            int nb = buf ^ 1;
            unsigned h0,h1,l0,l1,h2,h3,l2,l3;
            cvt_hl(a0g,h0,h1,l0,l1); cvt_hl(a1g,h2,h3,l2,l3);
            smA[nb][0][lkb][lrow] = make_uint4(h0,h1,h2,h3);
            smA[nb][1][lkb][lrow] = make_uint4(l0,l1,l2,l3);
            cvt_hl(b0g,h0,h1,l0,l1); cvt_hl(b1g,h2,h3,l2,l3);
            smB[nb][0][lkb][lrow] = make_uint4(h0,h1,h2,h3);
            smB[nb][1][lkb][lrow] = make_uint4(l0,l1,l2,l3);
            __syncthreads();
            buf = nb;
        }
    }

    float* outp = (half ? g_attpb : g_attpa) + (size_t)b * CC * HW + (size_t)m0 * HW + n0;
#pragma unroll
    for (int f = 0; f < 4; f++) {
        int r0 = wm + f * 16 + (lane >> 2), r1 = r0 + 8;
#pragma unroll
        for (int g = 0; g < 4; g++) {
            int cb = wn + g * 8 + (lane & 3) * 2;
            *(float2*)(outp + (size_t)r0 * HW + cb) = make_float2(c[f][g][0], c[f][g][1]);
            *(float2*)(outp + (size_t)r1 * HW + cb) = make_float2(c[f][g][2], c[f][g][3]);
        }
    }
}

// att_out = pa + pb
__global__ void k_attcomb(float* __restrict__ attout) {
    int i4 = blockIdx.x * 256 + threadIdx.x;          // < 524288
    float4 a = ((const float4*)g_attpa)[i4];
    float4 bb = ((const float4*)g_attpb)[i4];
    ((float4*)attout)[i4] = make_float4(a.x + bb.x, a.y + bb.y, a.z + bb.z, a.w + bb.w);
}

// ---------------- inverse channel norms of f_q and att_fq ----------------
__global__ void k_norm2(const float* __restrict__ f_q, const float* __restrict__ att) {
    int b   = blockIdx.y;
    int pix = blockIdx.x * 256 + threadIdx.x;
    const float* src = (blockIdx.z == 0 ? f_q : att) + (size_t)b * CC * HW + pix;
    float ss = 0.f;
#pragma unroll 8
    for (int c = 0; c < CC; c++) { float v = src[(size_t)c * HW]; ss = fmaf(v, v, ss); }
    float inv = 1.0f / fmaxf(sqrtf(ss), 1e-12f);
    (blockIdx.z == 0 ? g_nq2 : g_na2)[b * HW + pix] = inv;
}

// ---------------- fq = l2n(f_q) + 0.5*l2n(att_fq) ----------------
__global__ void k_fqout(const float* __restrict__ f_q, const float* __restrict__ att,
                        float* __restrict__ fqo) {
    int i4 = blockIdx.x * 256 + threadIdx.x;          // < 524288
    int base = i4 * 4;
    int b = base >> 19;
    int pix = base & 1023;
    float4 q = ((const float4*)f_q)[i4];
    float4 a = ((const float4*)att)[i4];
    int ni = (b * HW + pix) >> 2;
    float4 nq = ((const float4*)g_nq2)[ni];
    float4 na = ((const float4*)g_na2)[ni];
    float4 o;
    o.x = q.x * nq.x + a.x * na.x * 0.5f;
    o.y = q.y * nq.y + a.y * na.y * 0.5f;
    o.z = q.z * nq.z + a.z * na.z * 0.5f;
    o.w = q.w * nq.w + a.w * na.w * 0.5f;
    ((float4*)fqo)[i4] = o;
}

// ---------------- conv1: bf16-split tensor implicit GEMM, K-split by 2 ----------------
__global__ void __launch_bounds__(256, 2) k_conv1(const float* __restrict__ f_q,
                                                  const float* __restrict__ f_s) {
    __shared__ __align__(16) unsigned smW[2][2][16][36];  // [buf][hi/lo][k][oc72h]
    __shared__ __align__(16) unsigned smI[2][2][16][68];  // [buf][hi/lo][k][pix136h]
    int b = blockIdx.z >> 1, half = blockIdx.z & 1;
    int oc0 = blockIdx.y * 64, pix0 = blockIdx.x * 128;
    int tid = threadIdx.x, lane = tid & 31, wid = tid >> 5;
    int wm = (wid >> 2) * 32, wn = (wid & 3) * 32;
    int kr = tid >> 4, mc = (tid & 15) * 8;

    int kA = (lane & 7) + ((lane >> 4) << 3);
    int cA = ((lane >> 3) & 1) << 3;
    int kB = (lane & 7) + (((lane >> 3) & 1) << 3);
    int cB = (lane >> 4) << 3;
    unsigned baseW = (unsigned)__cvta_generic_to_shared(&smW[0][0][0][0]);
    unsigned baseI = (unsigned)__cvta_generic_to_shared(&smI[0][0][0][0]);
    unsigned offA = (unsigned)(kA * 144 + (cA + wm) * 2);
    unsigned offB = (unsigned)(kB * 272 + (cB + wn) * 2);

    const float* fqp = f_q + (size_t)b * CC * HW;
    const float* fsp = f_s + (size_t)b * CC * HW;

    int pp0 = pix0 + mc;
    int py = pp0 >> 5, px0v = pp0 & 31;
    int wtt = (tid & 127);
    int wrow = wtt >> 3, wcol8 = (wtt & 7) * 8;
    bool whalf = (tid < 128);
    int kbase = half * 288;                           // global k-tile base

    float c[2][4][4];
#pragma unroll
    for (int f = 0; f < 2; f++)
#pragma unroll
        for (int g = 0; g < 4; g++) { c[f][g][0]=0.f; c[f][g][1]=0.f; c[f][g][2]=0.f; c[f][g][3]=0.f; }

    {   // prologue: global k-tile kbase
        int tap = kbase >> 6, ict = kbase & 63;
        int dy = 2 * (tap / 3) - 2, dx = 2 * (tap % 3) - 2;
        uint4 wv;
        const __nv_bfloat16* wsrc = whalf ? g_wt1h : g_wt1l;
        wv = *(const uint4*)(wsrc + (size_t)(tap * 1024 + ict * 16 + wrow) * 256 + oc0 + wcol8);
        float v[8];
        int ic = ict * 16 + kr;
        const float* src = (ic < 512 ? fqp + (size_t)ic * HW
                                     : fsp + (size_t)(ic - 512) * HW);
        int iy = py + dy;
        bool yok = ((unsigned)iy < 32u);
        const float* rowp = src + iy * 32;
#pragma unroll
        for (int j = 0; j < 8; j++) {
            int ix = px0v + j + dx;
            v[j] = (yok && ((unsigned)ix < 32u)) ? rowp[ix] : 0.f;
        }
        *(uint4*)&smW[0][whalf ? 0 : 1][wrow][wcol8 >> 1] = wv;
        unsigned h0,h1,l0,l1;
        unsigned* pIh = &smI[0][0][kr][mc >> 1];
        unsigned* pIl = &smI[0][1][kr][mc >> 1];
        float4 fa = make_float4(v[0], v[1], v[2], v[3]);
        float4 fb = make_float4(v[4], v[5], v[6], v[7]);
        cvt_hl(fa,h0,h1,l0,l1); pIh[0]=h0; pIh[1]=h1; pIl[0]=l0; pIl[1]=l1;
        cvt_hl(fb,h0,h1,l0,l1); pIh[2]=h0; pIh[3]=h1; pIl[2]=l0; pIl[3]=l1;
    }
    __syncthreads();

    int buf = 0;
    for (int kt = 0; kt < 288; kt++) {
        uint4 wv; float v[8];
        if (kt < 287) {
            int kn = kbase + kt + 1;
            int tap = kn >> 6, ict = kn & 63;
            int dy = 2 * (tap / 3) - 2, dx = 2 * (tap % 3) - 2;
            const __nv_bfloat16* wsrc = whalf ? g_wt1h : g_wt1l;
            wv = *(const uint4*)(wsrc + (size_t)(tap * 1024 + ict * 16 + wrow) * 256 + oc0 + wcol8);
            int ic = ict * 16 + kr;
            const float* src = (ic < 512 ? fqp + (size_t)ic * HW
                                         : fsp + (size_t)(ic - 512) * HW);
            int iy = py + dy;
            bool yok = ((unsigned)iy < 32u);
            const float* rowp = src + iy * 32;
#pragma unroll
            for (int j = 0; j < 8; j++) {
                int ix = px0v + j + dx;
                v[j] = (yok && ((unsigned)ix < 32u)) ? rowp[ix] : 0.f;
            }
        }
        unsigned bW = baseW + (unsigned)buf * 4608u;
        unsigned bI = baseI + (unsigned)buf * 8704u;
        unsigned a[8], al[8], bh[8], bl[8];
#pragma unroll
        for (int f = 0; f < 2; f++) ldsm4t(a  + 4 * f, bW + offA + f * 32);
#pragma unroll
        for (int f = 0; f < 2; f++) ldsm4t(al + 4 * f, bW + 2304u + offA + f * 32);
#pragma unroll
        for (int g2 = 0; g2 < 2; g2++) ldsm4t(bh + 4 * g2, bI + offB + g2 * 32);
#pragma unroll
        for (int g2 = 0; g2 < 2; g2++) ldsm4t(bl + 4 * g2, bI + 4352u + offB + g2 * 32);
#pragma unroll
        for (int f = 0; f < 2; f++)
#pragma unroll
            for (int g = 0; g < 4; g++) {
                mma_bf16(c[f][g], a  + 4 * f, bh + 2 * g);
                mma_bf16(c[f][g], a  + 4 * f, bl + 2 * g);
                mma_bf16(c[f][g], al + 4 * f, bh + 2 * g);
            }
        if (kt < 287) {
            int nb = buf ^ 1;
            *(uint4*)&smW[nb][whalf ? 0 : 1][wrow][wcol8 >> 1] = wv;
            unsigned h0,h1,l0,l1;
            unsigned* pIh = &smI[nb][0][kr][mc >> 1];
            unsigned* pIl = &smI[nb][1][kr][mc >> 1];
            float4 fa = make_float4(v[0], v[1], v[2], v[3]);
            float4 fb = make_float4(v[4], v[5], v[6], v[7]);
            cvt_hl(fa,h0,h1,l0,l1); pIh[0]=h0; pIh[1]=h1; pIl[0]=l0; pIl[1]=l1;
            cvt_hl(fb,h0,h1,l0,l1); pIh[2]=h0; pIh[3]=h1; pIl[2]=l0; pIl[3]=l1;
            __syncthreads();
            buf = nb;
        }
    }

    float* outp = (half ? g_c1pb : g_c1pa) + (size_t)b * 262144;
#pragma unroll
    for (int f = 0; f < 2; f++) {
        int r0 = wm + f * 16 + (lane >> 2), r1 = r0 + 8;
#pragma unroll
        for (int g = 0; g < 4; g++) {
            int cb = wn + g * 8 + (lane & 3) * 2;
            *(float2*)(outp + (size_t)(oc0 + r0) * HW + pix0 + cb) =
                make_float2(c[f][g][0], c[f][g][1]);
            *(float2*)(outp + (size_t)(oc0 + r1) * HW + pix0 + cb) =
                make_float2(c[f][g][2], c[f][g][3]);
        }
    }
}

// c1 = relu(pa + pb + bias)
__global__ void k_c1comb(const float* __restrict__ b1) {
    int i4 = blockIdx.x * 256 + threadIdx.x;          // < 262144
    float4 a = ((const float4*)g_c1pa)[i4];
    float4 bb = ((const float4*)g_c1pb)[i4];
    int oc = (i4 & 65535) >> 8;                       // per-b block: 65536 f4, 256 f4 per oc
    float bias = b1[oc];
    float4 o;
    o.x = fmaxf(a.x + bb.x + bias, 0.f);
    o.y = fmaxf(a.y + bb.y + bias, 0.f);
    o.z = fmaxf(a.z + bb.z + bias, 0.f);
    o.w = fmaxf(a.w + bb.w + bias, 0.f);
    ((float4*)g_c1)[i4] = o;
}

// ---------------- conv2: bf16-split tensor implicit GEMM, K-split by 2 ----------------
__global__ void __launch_bounds__(256, 2) k_conv2() {
    __shared__ __align__(16) unsigned smW[2][2][16][36];
    __shared__ __align__(16) unsigned smI[2][2][16][68];
    int b = blockIdx.z >> 1, half = blockIdx.z & 1;
    int oc0 = blockIdx.y * 64, pix0 = blockIdx.x * 128;
    int tid = threadIdx.x, lane = tid & 31, wid = tid >> 5;
    int wm = (wid >> 2) * 32, wn = (wid & 3) * 32;
    int kr = tid >> 4, mc = (tid & 15) * 8;

    int kA = (lane & 7) + ((lane >> 4) << 3);
    int cA = ((lane >> 3) & 1) << 3;
    int kB = (lane & 7) + (((lane >> 3) & 1) << 3);
    int cB = (lane >> 4) << 3;
    unsigned baseW = (unsigned)__cvta_generic_to_shared(&smW[0][0][0][0]);
    unsigned baseI = (unsigned)__cvta_generic_to_shared(&smI[0][0][0][0]);
    unsigned offA = (unsigned)(kA * 144 + (cA + wm) * 2);
    unsigned offB = (unsigned)(kB * 272 + (cB + wn) * 2);

    const float* c1p = g_c1 + (size_t)b * 262144;

    int offp[8];
#pragma unroll
    for (int j = 0; j < 8; j++) {
        int p = pix0 + mc + j; if (p > 899) p = 899;
        offp[j] = (p / 30) * 32 + (p % 30);
    }
    int wtt = (tid & 127);
    int wrow = wtt >> 3, wcol8 = (wtt & 7) * 8;
    bool whalf = (tid < 128);
    int kbase = half * 72;                            // 144 k-tiles total

    float c[2][4][4];
#pragma unroll
    for (int f = 0; f < 2; f++)
#pragma unroll
        for (int g = 0; g < 4; g++) { c[f][g][0]=0.f; c[f][g][1]=0.f; c[f][g][2]=0.f; c[f][g][3]=0.f; }

    {   // prologue: k-tile kbase
        int tap = kbase >> 4, ict = kbase & 15;
        int doff = (tap / 3) * 32 + (tap % 3);
        uint4 wv;
        const __nv_bfloat16* wsrc = whalf ? g_wt2h : g_wt2l;
        wv = *(const uint4*)(wsrc + (size_t)(tap * 256 + ict * 16 + wrow) * 256 + oc0 + wcol8);
        float v[8];
        const float* src = c1p + (size_t)(ict * 16 + kr) * HW;
#pragma unroll
        for (int j = 0; j < 8; j++) v[j] = src[offp[j] + doff];
        *(uint4*)&smW[0][whalf ? 0 : 1][wrow][wcol8 >> 1] = wv;
        unsigned h0,h1,l0,l1;
        unsigned* pIh = &smI[0][0][kr][mc >> 1];
        unsigned* pIl = &smI[0][1][kr][mc >> 1];
        float4 fa = make_float4(v[0], v[1], v[2], v[3]);
        float4 fb = make_float4(v[4], v[5], v[6], v[7]);
        cvt_hl(fa,h0,h1,l0,l1); pIh[0]=h0; pIh[1]=h1; pIl[0]=l0; pIl[1]=l1;
        cvt_hl(fb,h0,h1,l0,l1); pIh[2]=h0; pIh[3]=h1; pIl[2]=l0; pIl[3]=l1;
    }
    __syncthreads();

    int buf = 0;
    for (int kt = 0; kt < 72; kt++) {
        uint4 wv; float v[8];
        if (kt < 71) {
            int kn = kbase + kt + 1;
            int tap = kn >> 4, ict = kn & 15;
            int doff = (tap / 3) * 32 + (tap % 3);
            const __nv_bfloat16* wsrc = whalf ? g_wt2h : g_wt2l;
            wv = *(const uint4*)(wsrc + (size_t)(tap * 256 + ict * 16 + wrow) * 256 + oc0 + wcol8);
            const float* src = c1p + (size_t)(ict * 16 + kr) * HW;
#pragma unroll
            for (int j = 0; j < 8; j++) v[j] = src[offp[j] + doff];
        }
        unsigned bW = baseW + (unsigned)buf * 4608u;
        unsigned bI = baseI + (unsigned)buf * 8704u;
        unsigned a[8], al[8], bh[8], bl[8];
#pragma unroll
        for (int f = 0; f < 2; f++) ldsm4t(a  + 4 * f, bW + offA + f * 32);
#pragma unroll
        for (int f = 0; f < 2; f++) ldsm4t(al + 4 * f, bW + 2304u + offA + f * 32);
#pragma unroll
        for (int g2 = 0; g2 < 2; g2++) ldsm4t(bh + 4 * g2, bI + offB + g2 * 32);
#pragma unroll
        for (int g2 = 0; g2 < 2; g2++) ldsm4t(bl + 4 * g2, bI + 4352u + offB + g2 * 32);
#pragma unroll
        for (int f = 0; f < 2; f++)
#pragma unroll
            for (int g = 0; g < 4; g++) {
                mma_bf16(c[f][g], a  + 4 * f, bh + 2 * g);
                mma_bf16(c[f][g], a  + 4 * f, bl + 2 * g);
                mma_bf16(c[f][g], al + 4 * f, bh + 2 * g);
            }
        if (kt < 71) {
            int nb = buf ^ 1;
            *(uint4*)&smW[nb][whalf ? 0 : 1][wrow][wcol8 >> 1] = wv;
            unsigned h0,h1,l0,l1;
            unsigned* pIh = &smI[nb][0][kr][mc >> 1];
            unsigned* pIl = &smI[nb][1][kr][mc >> 1];
            float4 fa = make_float4(v[0], v[1], v[2], v[3]);
            float4 fb = make_float4(v[4], v[5], v[6], v[7]);
            cvt_hl(fa,h0,h1,l0,l1); pIh[0]=h0; pIh[1]=h1; pIl[0]=l0; pIl[1]=l1;
            cvt_hl(fb,h0,h1,l0,l1); pIh[2]=h0; pIh[3]=h1; pIl[2]=l0; pIl[3]=l1;
            __syncthreads();
            buf = nb;
        }
    }

    float* outp = (half ? g_c2pb : g_c2pa) + (size_t)b * 230400;
#pragma unroll
    for (int f = 0; f < 2; f++) {
        int r0 = wm + f * 16 + (lane >> 2), r1 = r0 + 8;
#pragma unroll
        for (int g = 0; g < 4; g++) {
            int cb = wn + g * 8 + (lane & 3) * 2;
            int p0 = pix0 + cb;                // even; p0<900 => p0+1<=899
            if (p0 < 900) {
                *(float2*)(outp + (size_t)(oc0 + r0) * 900 + p0) =
                    make_float2(c[f][g][0], c[f][g][1]);
                *(float2*)(outp + (size_t)(oc0 + r1) * 900 + p0) =
                    make_float2(c[f][g][2], c[f][g][3]);
            }
        }
    }
}

// ---------------- maxpool 3x3 s3 (combines conv2 partials + bias) ----------------
__global__ void k_pool(const float* __restrict__ b2) {
    int oc = blockIdx.x, b = blockIdx.y;
    int t = threadIdx.x;
    if (t >= 100) return;
    int y = t / 10, x = t % 10;
    size_t base = ((size_t)b * 256 + oc) * 900;
    const float* pa = g_c2pa + base;
    const float* pb = g_c2pb + base;
    float m = -3.4e38f;
#pragma unroll
    for (int dy = 0; dy < 3; dy++)
#pragma unroll
        for (int dx = 0; dx < 3; dx++) {
            int idx = (3 * y + dy) * 30 + 3 * x + dx;
            m = fmaxf(m, pa[idx] + pb[idx]);
        }
    g_pool[((size_t)b * 256 + oc) * 100 + t] = m + b2[oc];
}

// ---------------- conv3 (3x3 VALID, 10x10 -> 8x8) + mean -> weight[b] ----------------
__global__ void k_conv3(const float* __restrict__ w3, const float* __restrict__ b3,
                        float* __restrict__ wout) {
    int b = blockIdx.x;
    int tid = threadIdx.x;
    int o = tid >> 2, part = tid & 3;
    int oy = o >> 3, ox = o & 7;
    float s = 0.f;
    for (int ic = part * 64; ic < part * 64 + 64; ic++) {
        const float* pp = g_pool + ((size_t)b * 256 + ic) * 100 + oy * 10 + ox;
        const float* wp = w3 + ic * 9;
#pragma unroll
        for (int ky = 0; ky < 3; ky++)
#pragma unroll
            for (int kx = 0; kx < 3; kx++)
                s = fmaf(pp[ky * 10 + kx], wp[ky * 3 + kx], s);
    }
    s += __shfl_down_sync(0xffffffffu, s, 1);
    s += __shfl_down_sync(0xffffffffu, s, 2);
    __shared__ float sh[64];
    if (part == 0) sh[o] = s;
    __syncthreads();
    if (tid < 32) {
        float v = sh[tid] + sh[tid + 32];
#pragma unroll
        for (int off = 16; off; off >>= 1) v += __shfl_xor_sync(0xffffffffu, v, off);
        if (tid == 0) wout[b] = v * (1.0f / 64.0f) + b3[0];
    }
}

// ---------------- launch ----------------
extern "C" void kernel_launch(void* const* d_in, const int* in_sizes, int n_in,
                              void* d_out, int out_size) {
    const float* fq_feats = (const float*)d_in[0];
    const float* fs_feats = (const float*)d_in[1];
    const float* f_q = (const float*)d_in[2];
    const float* f_s = (const float*)d_in[3];
    const float* w1 = (const float*)d_in[4];
    const float* b1 = (const float*)d_in[5];
    const float* w2 = (const float*)d_in[6];
    const float* b2 = (const float*)d_in[7];
    const float* w3 = (const float*)d_in[8];
    const float* b3 = (const float*)d_in[9];

    float* out     = (float*)d_out;
    float* fq_out  = out;                       // [4,512,32,32]
    float* att_out = out + 2097152;             // [4,512,32,32]
    float* w_out   = out + 4194304;             // [1,4]

    k_twt1<<<9216, 256>>>(w1);
    k_twt2<<<2304, 256>>>(w2);
    k_corr<<<dim3(8, 8, 4), 256>>>(fq_feats, fs_feats);
    k_softmax<<<4096, 256>>>();
    k_att<<<dim3(8, 4, 8), 256>>>(f_s);
    k_attcomb<<<2048, 256>>>(att_out);
    k_norm2<<<dim3(4, 4, 2), 256>>>(f_q, att_out);
    k_fqout<<<2048, 256>>>(f_q, att_out, fq_out);
    k_conv1<<<dim3(8, 4, 8), 256>>>(f_q, f_s);
    k_c1comb<<<1024, 256>>>(b1);
    k_conv2<<<dim3(8, 4, 8), 256>>>();
    k_pool<<<dim3(256, 4), 128>>>(b2);
    k_conv3<<<4, 256>>>(w3, b3, w_out);
}